// round 1
// baseline (speedup 1.0000x reference)
#include <cuda_runtime.h>
#include <cuda_bf16.h>
#include <math.h>

// Problem dims (fixed by the dataset)
#define Bz 128
#define Lz 128
#define HEz 1024
#define HDz 1024
#define Ez 512
#define APz 512
#define Tz 64

// ---------------- device scratch (no allocations allowed) ----------------
__device__ __align__(128) float g_enc_proj[Bz * Lz * APz];      // 33.5 MB
__device__ __align__(128) float g_q[Bz * APz];
__device__ __align__(128) float g_lstm_in[Bz * (Ez + HEz)];     // [x_t, a_t]
__device__ __align__(128) float g_gates[Bz * 4 * HDz];
__device__ __align__(128) float g_h1[Bz * HDz];
__device__ __align__(128) float g_c1[Bz * HDz];
__device__ __align__(128) float g_h2[Bz * HDz];
__device__ __align__(128) float g_c2[Bz * HDz];
__device__ __align__(128) float g_hprev[Bz * HDz];

// ---------------- generic fp32 SGEMM: C = A(MxK) @ B(KxN) [+bias][+=C][tanh] ---
// BM=64, BN=64, BK=16, 256 threads, 4x4 microtile.
// flags: bit0 = accumulate into C, bit1 = tanh epilogue
#define FLAG_ACC  1
#define FLAG_TANH 2

__global__ __launch_bounds__(256) void sgemm64(
    const float* __restrict__ A, const float* __restrict__ B,
    float* __restrict__ C, int M, int N, int K,
    const float* __restrict__ bias, int flags)
{
    __shared__ float As[16][64];
    __shared__ float Bs[16][64];

    const int tid = threadIdx.x;
    const int tx = tid & 15;        // 0..15  (N direction)
    const int ty = tid >> 4;        // 0..15  (M direction)
    const int row0 = blockIdx.y * 64;
    const int col0 = blockIdx.x * 64;

    float acc[4][4] = {};

    // A tile load mapping: 64 rows x 4 float4 groups
    const int ar = tid >> 2;        // row within tile
    const int ag = tid & 3;         // float4 group within 16-wide K slab
    // B tile load mapping: 16 rows x 16 float4 groups
    const int br = tid >> 4;
    const int bg = tid & 15;

    for (int k0 = 0; k0 < K; k0 += 16) {
        float4 av = *(const float4*)(A + (size_t)(row0 + ar) * K + k0 + ag * 4);
        As[ag * 4 + 0][ar] = av.x;
        As[ag * 4 + 1][ar] = av.y;
        As[ag * 4 + 2][ar] = av.z;
        As[ag * 4 + 3][ar] = av.w;

        float4 bv = *(const float4*)(B + (size_t)(k0 + br) * N + col0 + bg * 4);
        *(float4*)&Bs[br][bg * 4] = bv;

        __syncthreads();

        #pragma unroll
        for (int kk = 0; kk < 16; kk++) {
            float a[4], b[4];
            #pragma unroll
            for (int i = 0; i < 4; i++) a[i] = As[kk][ty * 4 + i];
            #pragma unroll
            for (int j = 0; j < 4; j++) b[j] = Bs[kk][tx * 4 + j];
            #pragma unroll
            for (int i = 0; i < 4; i++)
                #pragma unroll
                for (int j = 0; j < 4; j++)
                    acc[i][j] += a[i] * b[j];
        }
        __syncthreads();
    }

    #pragma unroll
    for (int i = 0; i < 4; i++) {
        int r = row0 + ty * 4 + i;
        #pragma unroll
        for (int j = 0; j < 4; j++) {
            int c = col0 + tx * 4 + j;
            float v = acc[i][j];
            if (bias) v += bias[c];
            if (flags & FLAG_ACC) v += C[(size_t)r * N + c];
            if (flags & FLAG_TANH) v = tanhf(v);
            C[(size_t)r * N + c] = v;
        }
    }
}

// ---------------- init recurrent state ----------------
__global__ void init_state(const float* __restrict__ h1_0, const float* __restrict__ c1_0,
                           const float* __restrict__ h2_0, const float* __restrict__ c2_0)
{
    int idx = blockIdx.x * blockDim.x + threadIdx.x;
    if (idx < Bz * HDz) {
        g_h1[idx] = h1_0[idx];
        g_c1[idx] = c1_0[idx];
        g_h2[idx] = h2_0[idx];
        g_c2[idx] = c2_0[idx];
        g_hprev[idx] = 1.0f / (float)HEz;   // ones / HE, exact (2^-10)
    }
}

// ---------------- fused attention: e -> softmax -> a_t, plus lstm_in assembly ---
// one block per batch row b, 256 threads
__global__ __launch_bounds__(256) void attn_kernel(
    const float* __restrict__ enc_hiddens,
    const int* __restrict__ enc_masks,
    const float* __restrict__ corr_w,
    const float* __restrict__ corr_b,
    const float* __restrict__ captions,
    int t)
{
    __shared__ float qv[APz];
    __shared__ float cw[APz];
    __shared__ float e[Lz];

    const int b = blockIdx.x;
    const int tid = threadIdx.x;
    const int lane = tid & 31;
    const int warp = tid >> 5;

    for (int i = tid; i < APz; i += 256) {
        qv[i] = g_q[b * APz + i];
        cw[i] = corr_w[i];
    }
    __syncthreads();

    const float cb = corr_b[0];

    // e[l] = sum_ap tanh(enc_proj[b,l,ap] + q[b,ap]) * corr_w[ap] + corr_b
    for (int l = warp; l < Lz; l += 8) {
        const float* ep = g_enc_proj + ((size_t)(b * Lz + l)) * APz;
        float acc = 0.0f;
        for (int ap = lane; ap < APz; ap += 32)
            acc += tanhf(ep[ap] + qv[ap]) * cw[ap];
        #pragma unroll
        for (int off = 16; off; off >>= 1)
            acc += __shfl_xor_sync(0xffffffffu, acc, off);
        if (lane == 0) {
            float v = acc + cb;
            if (enc_masks[b * Lz + l]) v = -INFINITY;
            e[l] = v;
        }
    }
    __syncthreads();

    // softmax over L=128 (warp 0)
    if (warp == 0) {
        float m = -INFINITY;
        #pragma unroll
        for (int i = 0; i < 4; i++) m = fmaxf(m, e[lane + 32 * i]);
        #pragma unroll
        for (int off = 16; off; off >>= 1)
            m = fmaxf(m, __shfl_xor_sync(0xffffffffu, m, off));
        float ex[4], s = 0.0f;
        #pragma unroll
        for (int i = 0; i < 4; i++) { ex[i] = __expf(e[lane + 32 * i] - m); s += ex[i]; }
        #pragma unroll
        for (int off = 16; off; off >>= 1)
            s += __shfl_xor_sync(0xffffffffu, s, off);
        float inv = 1.0f / s;
        #pragma unroll
        for (int i = 0; i < 4; i++) e[lane + 32 * i] = ex[i] * inv;
    }
    __syncthreads();

    // a_t[b,h] = sum_l alpha[l] * enc_hiddens[b,l,h]   -> lstm_in[b, E + h]
    const float* eh = enc_hiddens + (size_t)b * Lz * HEz;
    for (int h = tid; h < HEz; h += 256) {
        float acc = 0.0f;
        #pragma unroll 8
        for (int l = 0; l < Lz; l++)
            acc += e[l] * eh[(size_t)l * HEz + h];
        g_lstm_in[b * (Ez + HEz) + Ez + h] = acc;
    }

    // x_t copy -> lstm_in[b, 0:E]
    for (int i = tid; i < Ez; i += 256)
        g_lstm_in[b * (Ez + HEz) + i] = captions[((size_t)t * Bz + b) * Ez + i];
}

// ---------------- LSTM pointwise cell update ----------------
__device__ __forceinline__ float sigmoidf_(float x) { return 1.0f / (1.0f + expf(-x)); }

__global__ __launch_bounds__(256) void lstm_point(
    const float* __restrict__ gates,
    const float* __restrict__ b_i, const float* __restrict__ b_h,
    float* __restrict__ h, float* __restrict__ c,
    float* __restrict__ hprev_out)
{
    int idx = blockIdx.x * blockDim.x + threadIdx.x;
    if (idx >= Bz * HDz) return;
    int b = idx >> 10;
    int j = idx & (HDz - 1);
    const float* g = gates + (size_t)b * 4 * HDz;

    float ig = sigmoidf_(g[j]            + b_i[j]            + b_h[j]);
    float fg = sigmoidf_(g[HDz + j]      + b_i[HDz + j]      + b_h[HDz + j]);
    float gg = tanhf   (g[2 * HDz + j]   + b_i[2 * HDz + j]  + b_h[2 * HDz + j]);
    float og = sigmoidf_(g[3 * HDz + j]  + b_i[3 * HDz + j]  + b_h[3 * HDz + j]);

    float cn = fg * c[idx] + ig * gg;
    float hn = og * tanhf(cn);
    c[idx] = cn;
    h[idx] = hn;
    if (hprev_out) hprev_out[idx] = hn;
}

// ---------------- host launcher ----------------
extern "C" void kernel_launch(void* const* d_in, const int* in_sizes, int n_in,
                              void* d_out, int out_size)
{
    const float* enc_hiddens = (const float*)d_in[0];
    const int*   enc_masks   = (const int*)  d_in[1];
    const float* h1_0 = (const float*)d_in[2];
    const float* c1_0 = (const float*)d_in[3];
    const float* h2_0 = (const float*)d_in[4];
    const float* c2_0 = (const float*)d_in[5];
    const float* captions = (const float*)d_in[6];
    const float* att_W = (const float*)d_in[7];
    const float* att_b = (const float*)d_in[8];
    const float* dhp_W = (const float*)d_in[9];
    const float* dhp_b = (const float*)d_in[10];
    const float* corr_w = (const float*)d_in[11];
    const float* corr_b = (const float*)d_in[12];
    const float* lt_W = (const float*)d_in[13];
    const float* lt_b = (const float*)d_in[14];
    const float* W_ih1 = (const float*)d_in[15];
    const float* W_hh1 = (const float*)d_in[16];
    const float* b_ih1 = (const float*)d_in[17];
    const float* b_hh1 = (const float*)d_in[18];
    const float* W_ih2 = (const float*)d_in[19];
    const float* W_hh2 = (const float*)d_in[20];
    const float* b_ih2 = (const float*)d_in[21];
    const float* b_hh2 = (const float*)d_in[22];

    float* out = (float*)d_out;

    // cached scratch pointers (address lookup only — no allocation)
    static float* p_enc_proj = nullptr;
    static float *p_q, *p_lstm_in, *p_gates, *p_h1, *p_c1, *p_h2, *p_c2, *p_hprev;
    if (!p_enc_proj) {
        cudaGetSymbolAddress((void**)&p_enc_proj, g_enc_proj);
        cudaGetSymbolAddress((void**)&p_q,        g_q);
        cudaGetSymbolAddress((void**)&p_lstm_in,  g_lstm_in);
        cudaGetSymbolAddress((void**)&p_gates,    g_gates);
        cudaGetSymbolAddress((void**)&p_h1,       g_h1);
        cudaGetSymbolAddress((void**)&p_c1,       g_c1);
        cudaGetSymbolAddress((void**)&p_h2,       g_h2);
        cudaGetSymbolAddress((void**)&p_c2,       g_c2);
        cudaGetSymbolAddress((void**)&p_hprev,    g_hprev);
    }

    // init recurrent state + h_prev0
    init_state<<<(Bz * HDz + 255) / 256, 256>>>(h1_0, c1_0, h2_0, c2_0);

    // enc_proj = enc_hiddens @ att_W + att_b   (16384 x 512, K=1024)
    sgemm64<<<dim3(APz / 64, (Bz * Lz) / 64), 256>>>(
        enc_hiddens, att_W, p_enc_proj, Bz * Lz, APz, HEz, att_b, 0);

    for (int t = 0; t < Tz; t++) {
        // q = h_prev @ dhp_W + dhp_b
        sgemm64<<<dim3(APz / 64, Bz / 64), 256>>>(
            p_hprev, dhp_W, p_q, Bz, APz, HDz, dhp_b, 0);

        // attention + lstm_in assembly
        attn_kernel<<<Bz, 256>>>(enc_hiddens, enc_masks, corr_w, corr_b, captions, t);

        // gates1 = lstm_in @ W_ih1 + h1 @ W_hh1
        sgemm64<<<dim3(4 * HDz / 64, Bz / 64), 256>>>(
            p_lstm_in, W_ih1, p_gates, Bz, 4 * HDz, Ez + HEz, nullptr, 0);
        sgemm64<<<dim3(4 * HDz / 64, Bz / 64), 256>>>(
            p_h1, W_hh1, p_gates, Bz, 4 * HDz, HDz, nullptr, FLAG_ACC);
        lstm_point<<<(Bz * HDz + 255) / 256, 256>>>(
            p_gates, b_ih1, b_hh1, p_h1, p_c1, nullptr);

        // gates2 = h1 @ W_ih2 + h2 @ W_hh2
        sgemm64<<<dim3(4 * HDz / 64, Bz / 64), 256>>>(
            p_h1, W_ih2, p_gates, Bz, 4 * HDz, HDz, nullptr, 0);
        sgemm64<<<dim3(4 * HDz / 64, Bz / 64), 256>>>(
            p_h2, W_hh2, p_gates, Bz, 4 * HDz, HDz, nullptr, FLAG_ACC);
        lstm_point<<<(Bz * HDz + 255) / 256, 256>>>(
            p_gates, b_ih2, b_hh2, p_h2, p_c2, p_hprev);

        // out[t] = tanh(h1 @ lt_W + lt_b)
        sgemm64<<<dim3(HDz / 64, Bz / 64), 256>>>(
            p_h1, lt_W, out + (size_t)t * Bz * HDz, Bz, HDz, HDz, lt_b, FLAG_TANH);
    }
    (void)in_sizes; (void)n_in; (void)out_size;
}

// round 2
// speedup vs baseline: 2.1666x; 2.1666x over previous
#include <cuda_runtime.h>
#include <math.h>

#define Bz 128
#define Lz 128
#define HEz 1024
#define HDz 1024
#define Ez 512
#define APz 512
#define Tz 64

// ---------------- device scratch ----------------
__device__ __align__(128) float g_enc_proj[Bz * Lz * APz];
__device__ __align__(128) float g_q[Bz * APz];
__device__ __align__(128) float g_e[Bz * Lz];
__device__ __align__(128) float g_lstm_in[Bz * (Ez + HEz)];
__device__ __align__(128) float g_gates1[Bz * 4 * HDz];
__device__ __align__(128) float g_gates2[Bz * 4 * HDz];
__device__ __align__(128) float g_outsc[Bz * HDz];
__device__ __align__(128) float g_h1[Bz * HDz];
__device__ __align__(128) float g_c1[Bz * HDz];
__device__ __align__(128) float g_h2[Bz * HDz];
__device__ __align__(128) float g_c2[Bz * HDz];
__device__ __align__(128) float g_hprev[Bz * HDz];

__device__ __forceinline__ float fast_tanh(float x) {
    float y;
    asm("tanh.approx.f32 %0, %1;" : "=f"(y) : "f"(x));
    return y;
}
__device__ __forceinline__ float sigmoidf_(float x) { return 1.0f / (1.0f + expf(-x)); }

// ---------------- plain SGEMM (one-time enc_proj only) ----------------
__global__ __launch_bounds__(256) void sgemm64(
    const float* __restrict__ A, const float* __restrict__ B,
    float* __restrict__ C, int M, int N, int K,
    const float* __restrict__ bias)
{
    __shared__ float As[16][64];
    __shared__ float Bs[16][64];
    const int tid = threadIdx.x;
    const int tx = tid & 15, ty = tid >> 4;
    const int row0 = blockIdx.y * 64, col0 = blockIdx.x * 64;
    float acc[4][4] = {};
    const int ar = tid >> 2, ag = tid & 3;
    const int br = tid >> 4, bg = tid & 15;

    for (int k0 = 0; k0 < K; k0 += 16) {
        float4 av = *(const float4*)(A + (size_t)(row0 + ar) * K + k0 + ag * 4);
        As[ag * 4 + 0][ar] = av.x; As[ag * 4 + 1][ar] = av.y;
        As[ag * 4 + 2][ar] = av.z; As[ag * 4 + 3][ar] = av.w;
        *(float4*)&Bs[br][bg * 4] = *(const float4*)(B + (size_t)(k0 + br) * N + col0 + bg * 4);
        __syncthreads();
        #pragma unroll
        for (int kk = 0; kk < 16; kk++) {
            float a[4], b[4];
            #pragma unroll
            for (int i = 0; i < 4; i++) a[i] = As[kk][ty * 4 + i];
            #pragma unroll
            for (int j = 0; j < 4; j++) b[j] = Bs[kk][tx * 4 + j];
            #pragma unroll
            for (int i = 0; i < 4; i++)
                #pragma unroll
                for (int j = 0; j < 4; j++) acc[i][j] += a[i] * b[j];
        }
        __syncthreads();
    }
    #pragma unroll
    for (int i = 0; i < 4; i++) {
        int r = row0 + ty * 4 + i;
        #pragma unroll
        for (int j = 0; j < 4; j++) {
            int c = col0 + tx * 4 + j;
            C[(size_t)r * N + c] = acc[i][j] + bias[c];
        }
    }
}

// ---------------- dual-operand split-K GEMM with atomic epilogue ----------------
// C += A1(MxK1)@B1(K1xN) + A2(MxK2)@B2(K2xN); C pre-initialized with bias.
// Virtual K axis [0, K1+K2); each z-slice handles `chunk` of it. K1, chunk % 16 == 0.
__global__ __launch_bounds__(256) void gemm_dual_splitk(
    const float* __restrict__ A1, const float* __restrict__ B1, int K1,
    const float* __restrict__ A2, const float* __restrict__ B2, int K2,
    float* __restrict__ C, int N, int chunk)
{
    __shared__ float As[16][64];
    __shared__ float Bs[16][64];
    const int tid = threadIdx.x;
    const int tx = tid & 15, ty = tid >> 4;
    const int row0 = blockIdx.y * 64, col0 = blockIdx.x * 64;
    const int vk_beg = blockIdx.z * chunk;
    const int vk_end = min(vk_beg + chunk, K1 + K2);

    float acc[4][4] = {};
    const int ar = tid >> 2, ag = tid & 3;
    const int br = tid >> 4, bg = tid & 15;

    for (int k0 = vk_beg; k0 < vk_end; k0 += 16) {
        const float* A; const float* B; int K, kk;
        if (k0 < K1) { A = A1; B = B1; K = K1; kk = k0; }
        else         { A = A2; B = B2; K = K2; kk = k0 - K1; }

        float4 av = *(const float4*)(A + (size_t)(row0 + ar) * K + kk + ag * 4);
        As[ag * 4 + 0][ar] = av.x; As[ag * 4 + 1][ar] = av.y;
        As[ag * 4 + 2][ar] = av.z; As[ag * 4 + 3][ar] = av.w;
        *(float4*)&Bs[br][bg * 4] = *(const float4*)(B + (size_t)(kk + br) * N + col0 + bg * 4);
        __syncthreads();
        #pragma unroll
        for (int k2 = 0; k2 < 16; k2++) {
            float a[4], b[4];
            #pragma unroll
            for (int i = 0; i < 4; i++) a[i] = As[k2][ty * 4 + i];
            #pragma unroll
            for (int j = 0; j < 4; j++) b[j] = Bs[k2][tx * 4 + j];
            #pragma unroll
            for (int i = 0; i < 4; i++)
                #pragma unroll
                for (int j = 0; j < 4; j++) acc[i][j] += a[i] * b[j];
        }
        __syncthreads();
    }
    #pragma unroll
    for (int i = 0; i < 4; i++) {
        int r = row0 + ty * 4 + i;
        #pragma unroll
        for (int j = 0; j < 4; j++)
            atomicAdd(&C[(size_t)r * N + col0 + tx * 4 + j], acc[i][j]);
    }
}

// ---------------- init: state + gates1 bias + q bias ----------------
__global__ void init_state(const float* __restrict__ h1_0, const float* __restrict__ c1_0,
                           const float* __restrict__ h2_0, const float* __restrict__ c2_0,
                           const float* __restrict__ b_ih1, const float* __restrict__ b_hh1,
                           const float* __restrict__ dhp_b)
{
    int idx = blockIdx.x * blockDim.x + threadIdx.x;
    if (idx >= Bz * HDz) return;
    g_h1[idx] = h1_0[idx]; g_c1[idx] = c1_0[idx];
    g_h2[idx] = h2_0[idx]; g_c2[idx] = c2_0[idx];
    g_hprev[idx] = 1.0f / (float)HEz;
    int b = idx >> 10, j = idx & (HDz - 1);
    #pragma unroll
    for (int gi = 0; gi < 4; gi++)
        g_gates1[(size_t)b * 4 * HDz + gi * HDz + j] = b_ih1[gi * HDz + j] + b_hh1[gi * HDz + j];
    if (idx < Bz * APz) g_q[idx] = dhp_b[idx & (APz - 1)];
}

// ---------------- attention part 1: logits e (+ x_t copy) ----------------
// grid (B, 4): block handles 32 l's; warp per l, 4 iterations
__global__ __launch_bounds__(256) void attn_e(
    const int* __restrict__ enc_masks,
    const float* __restrict__ corr_w, const float* __restrict__ corr_b,
    const float* __restrict__ captions, int t)
{
    __shared__ __align__(16) float qv[APz];
    __shared__ __align__(16) float cw[APz];
    const int b = blockIdx.x, yc = blockIdx.y;
    const int tid = threadIdx.x, lane = tid & 31, warp = tid >> 5;

    for (int i = tid; i < APz; i += 256) {
        qv[i] = g_q[b * APz + i];
        cw[i] = corr_w[i];
    }
    // x_t copy into lstm_in[:, 0:E]
    if (tid < 128) {
        int ci = yc * 128 + tid;
        g_lstm_in[b * (Ez + HEz) + ci] = captions[((size_t)t * Bz + b) * Ez + ci];
    }
    __syncthreads();

    const float cb = corr_b[0];
    const float4* qv4 = (const float4*)qv;
    const float4* cw4 = (const float4*)cw;

    for (int l = yc * 32 + warp; l < yc * 32 + 32; l += 8) {
        const float4* ep = (const float4*)(g_enc_proj + ((size_t)(b * Lz + l)) * APz);
        float acc = 0.0f;
        #pragma unroll
        for (int i = 0; i < 4; i++) {
            int g = lane + 32 * i;
            float4 v = ep[g];
            float4 q4 = qv4[g];
            float4 w4 = cw4[g];
            acc += fast_tanh(v.x + q4.x) * w4.x;
            acc += fast_tanh(v.y + q4.y) * w4.y;
            acc += fast_tanh(v.z + q4.z) * w4.z;
            acc += fast_tanh(v.w + q4.w) * w4.w;
        }
        #pragma unroll
        for (int off = 16; off; off >>= 1)
            acc += __shfl_xor_sync(0xffffffffu, acc, off);
        if (lane == 0) {
            float v = acc + cb;
            if (enc_masks[b * Lz + l]) v = -INFINITY;
            g_e[b * Lz + l] = v;
        }
    }
}

// ---------------- attention part 2: softmax + weighted sum ----------------
// grid (B, HEz/256): softmax recomputed per block (cheap), then 256 h-columns
__global__ __launch_bounds__(256) void attn_at(const float* __restrict__ enc_hiddens)
{
    __shared__ float al[Lz];
    const int b = blockIdx.x, hc = blockIdx.y;
    const int tid = threadIdx.x;

    if (tid < Lz) al[tid] = g_e[b * Lz + tid];
    __syncthreads();
    if (tid < 32) {
        float m = -INFINITY;
        #pragma unroll
        for (int i = 0; i < 4; i++) m = fmaxf(m, al[tid + 32 * i]);
        #pragma unroll
        for (int off = 16; off; off >>= 1)
            m = fmaxf(m, __shfl_xor_sync(0xffffffffu, m, off));
        float ex[4], s = 0.0f;
        #pragma unroll
        for (int i = 0; i < 4; i++) { ex[i] = __expf(al[tid + 32 * i] - m); s += ex[i]; }
        #pragma unroll
        for (int off = 16; off; off >>= 1)
            s += __shfl_xor_sync(0xffffffffu, s, off);
        float inv = 1.0f / s;
        #pragma unroll
        for (int i = 0; i < 4; i++) al[tid + 32 * i] = ex[i] * inv;
    }
    __syncthreads();

    const int h = hc * 256 + tid;
    const float* eh = enc_hiddens + (size_t)b * Lz * HEz + h;
    float acc = 0.0f;
    #pragma unroll 8
    for (int l = 0; l < Lz; l++)
        acc += al[l] * eh[(size_t)l * HEz];
    g_lstm_in[b * (Ez + HEz) + Ez + h] = acc;
}

// ---------------- LSTM pointwise, layer 1 (+ init gates2 & outsc) ----------------
__global__ __launch_bounds__(256) void lstm_point1(
    const float* __restrict__ b_ih2, const float* __restrict__ b_hh2,
    const float* __restrict__ lt_b)
{
    int idx = blockIdx.x * blockDim.x + threadIdx.x;
    if (idx >= Bz * HDz) return;
    int b = idx >> 10, j = idx & (HDz - 1);
    const float* g = g_gates1 + (size_t)b * 4 * HDz;

    float ig = sigmoidf_(g[j]);
    float fg = sigmoidf_(g[HDz + j]);
    float gg = tanhf(g[2 * HDz + j]);
    float og = sigmoidf_(g[3 * HDz + j]);
    float cn = fg * g_c1[idx] + ig * gg;
    float hn = og * tanhf(cn);
    g_c1[idx] = cn;
    g_h1[idx] = hn;

    // init next buffers
    #pragma unroll
    for (int gi = 0; gi < 4; gi++)
        g_gates2[(size_t)b * 4 * HDz + gi * HDz + j] = b_ih2[gi * HDz + j] + b_hh2[gi * HDz + j];
    g_outsc[idx] = lt_b[j];
}

// ---------------- LSTM pointwise, layer 2 (+ hprev, init gates1 & q) ------------
__global__ __launch_bounds__(256) void lstm_point2(
    const float* __restrict__ b_ih1, const float* __restrict__ b_hh1,
    const float* __restrict__ dhp_b)
{
    int idx = blockIdx.x * blockDim.x + threadIdx.x;
    if (idx >= Bz * HDz) return;
    int b = idx >> 10, j = idx & (HDz - 1);
    const float* g = g_gates2 + (size_t)b * 4 * HDz;

    float ig = sigmoidf_(g[j]);
    float fg = sigmoidf_(g[HDz + j]);
    float gg = tanhf(g[2 * HDz + j]);
    float og = sigmoidf_(g[3 * HDz + j]);
    float cn = fg * g_c2[idx] + ig * gg;
    float hn = og * tanhf(cn);
    g_c2[idx] = cn;
    g_h2[idx] = hn;
    g_hprev[idx] = hn;

    #pragma unroll
    for (int gi = 0; gi < 4; gi++)
        g_gates1[(size_t)b * 4 * HDz + gi * HDz + j] = b_ih1[gi * HDz + j] + b_hh1[gi * HDz + j];
    if (idx < Bz * APz) g_q[idx] = dhp_b[idx & (APz - 1)];
}

// ---------------- output tanh ----------------
__global__ void tanh_out(float* __restrict__ out)
{
    int idx = blockIdx.x * blockDim.x + threadIdx.x;
    if (idx < Bz * HDz) out[idx] = tanhf(g_outsc[idx]);
}

// ---------------- host launcher ----------------
extern "C" void kernel_launch(void* const* d_in, const int* in_sizes, int n_in,
                              void* d_out, int out_size)
{
    const float* enc_hiddens = (const float*)d_in[0];
    const int*   enc_masks   = (const int*)  d_in[1];
    const float* h1_0 = (const float*)d_in[2];
    const float* c1_0 = (const float*)d_in[3];
    const float* h2_0 = (const float*)d_in[4];
    const float* c2_0 = (const float*)d_in[5];
    const float* captions = (const float*)d_in[6];
    const float* att_W = (const float*)d_in[7];
    const float* att_b = (const float*)d_in[8];
    const float* dhp_W = (const float*)d_in[9];
    const float* dhp_b = (const float*)d_in[10];
    const float* corr_w = (const float*)d_in[11];
    const float* corr_b = (const float*)d_in[12];
    const float* lt_W = (const float*)d_in[13];
    const float* lt_b = (const float*)d_in[14];
    const float* W_ih1 = (const float*)d_in[15];
    const float* W_hh1 = (const float*)d_in[16];
    const float* b_ih1 = (const float*)d_in[17];
    const float* b_hh1 = (const float*)d_in[18];
    const float* W_ih2 = (const float*)d_in[19];
    const float* W_hh2 = (const float*)d_in[20];
    const float* b_ih2 = (const float*)d_in[21];
    const float* b_hh2 = (const float*)d_in[22];
    float* out = (float*)d_out;

    static float* p_enc_proj = nullptr;
    static float *p_q, *p_lstm_in, *p_g1, *p_g2, *p_outsc, *p_h1, *p_h2;
    if (!p_enc_proj) {
        cudaGetSymbolAddress((void**)&p_enc_proj, g_enc_proj);
        cudaGetSymbolAddress((void**)&p_q,        g_q);
        cudaGetSymbolAddress((void**)&p_lstm_in,  g_lstm_in);
        cudaGetSymbolAddress((void**)&p_g1,       g_gates1);
        cudaGetSymbolAddress((void**)&p_g2,       g_gates2);
        cudaGetSymbolAddress((void**)&p_outsc,    g_outsc);
        cudaGetSymbolAddress((void**)&p_h1,       g_h1);
        cudaGetSymbolAddress((void**)&p_h2,       g_h2);
    }

    init_state<<<(Bz * HDz + 255) / 256, 256>>>(h1_0, c1_0, h2_0, c2_0, b_ih1, b_hh1, dhp_b);

    // enc_proj = enc_hiddens @ att_W + att_b   (16384 x 512, K=1024)
    sgemm64<<<dim3(APz / 64, (Bz * Lz) / 64), 256>>>(
        enc_hiddens, att_W, p_enc_proj, Bz * Lz, APz, HEz, att_b);

    float* p_hprev; cudaGetSymbolAddress((void**)&p_hprev, g_hprev);

    for (int t = 0; t < Tz; t++) {
        // q += hprev @ dhp_W  (bias pre-initialized)
        gemm_dual_splitk<<<dim3(APz / 64, Bz / 64, 8), 256>>>(
            p_hprev, dhp_W, HDz, p_hprev, dhp_W, 0, p_q, APz, 128);

        attn_e<<<dim3(Bz, 4), 256>>>(enc_masks, corr_w, corr_b, captions, t);
        attn_at<<<dim3(Bz, HEz / 256), 256>>>(enc_hiddens);

        // gates1 += lstm_in @ W_ih1 + h1 @ W_hh1   (VK=2560, 5 slices)
        gemm_dual_splitk<<<dim3(4 * HDz / 64, Bz / 64, 5), 256>>>(
            p_lstm_in, W_ih1, Ez + HEz, p_h1, W_hh1, HDz, p_g1, 4 * HDz, 512);
        lstm_point1<<<(Bz * HDz + 255) / 256, 256>>>(b_ih2, b_hh2, lt_b);

        // outsc += h1 @ lt_W  (VK=1024, 4 slices)
        gemm_dual_splitk<<<dim3(HDz / 64, Bz / 64, 4), 256>>>(
            p_h1, lt_W, HDz, p_h1, lt_W, 0, p_outsc, HDz, 256);

        // gates2 += h1 @ W_ih2 + h2 @ W_hh2   (VK=2048, 4 slices)
        gemm_dual_splitk<<<dim3(4 * HDz / 64, Bz / 64, 4), 256>>>(
            p_h1, W_ih2, HDz, p_h2, W_hh2, HDz, p_g2, 4 * HDz, 512);
        lstm_point2<<<(Bz * HDz + 255) / 256, 256>>>(b_ih1, b_hh1, dhp_b);

        tanh_out<<<(Bz * HDz + 255) / 256, 256>>>(out + (size_t)t * Bz * HDz);
    }
    (void)in_sizes; (void)n_in; (void)out_size;
}

// round 4
// speedup vs baseline: 3.6944x; 1.7051x over previous
#include <cuda_runtime.h>
#include <math.h>
#include <cstdint>

#define Bz 128
#define Lz 128
#define HEz 1024
#define HDz 1024
#define Ez 512
#define APz 512
#define Tz 64
#define K1z 2560   // [x_t | a_t | h1_prev]
#define K2z 2048   // [h1 | h2]

// ---------------- device scratch ----------------
__device__ __align__(128) float g_enc_proj[Bz * Lz * APz];
__device__ __align__(128) float g_q[Bz * APz];
__device__ __align__(128) float g_e[Bz * Lz];
__device__ __align__(128) float g_abuf1[Bz * K1z];
__device__ __align__(128) float g_abuf2[Bz * K2z];
__device__ __align__(128) float g_gates1[Bz * 4 * HDz];
__device__ __align__(128) float g_gates2[Bz * 4 * HDz];
__device__ __align__(128) float g_outsc[Bz * HDz];
__device__ __align__(128) float g_c1[Bz * HDz];
__device__ __align__(128) float g_c2[Bz * HDz];
__device__ __align__(128) float g_hprev[Bz * HDz];
// pre-transposed K-major weights [N, K]
__device__ __align__(128) float g_W1t[4 * HDz * K1z];
__device__ __align__(128) float g_W2t[4 * HDz * K2z];
__device__ __align__(128) float g_ltWt[HDz * HDz];
__device__ __align__(128) float g_dhpWt[APz * HDz];
__device__ __align__(128) float g_attWt[APz * HEz];
__device__ __align__(128) float g_gb1[4 * HDz];
__device__ __align__(128) float g_gb2[4 * HDz];

__device__ __forceinline__ float fast_tanh(float x) {
    float y; asm("tanh.approx.f32 %0, %1;" : "=f"(y) : "f"(x)); return y;
}
__device__ __forceinline__ float sigmoidf_(float x) { return 1.0f / (1.0f + expf(-x)); }
__device__ __forceinline__ uint32_t f2tf32(float x) {
    uint32_t u; asm("cvt.rna.tf32.f32 %0, %1;" : "=r"(u) : "f"(x)); return u;
}

// ---------------- HMMA tf32 GEMM ----------------
// C[m0:+128, n0:+128] (+)= A[m0:, kbeg:kend](lda) @ Bt[n0:, kbeg:kend]^T
// Bt is K-major [N, ldb]. grid: (N/128, M/128, Z). chunk*Z == K exactly.
// gridDim.z == 1 -> direct store (C = acc + bias).
// gridDim.z  > 1 -> atomicAdd into zero-initialized C; z==0 adds bias.
#define BM 128
#define BN 128
#define BK 32

__global__ __launch_bounds__(256) void gemm_mma(
    const float* __restrict__ A, int lda,
    const float* __restrict__ Bt, int ldb,
    float* __restrict__ C, int ldc,
    int chunk, const float* __restrict__ bias)
{
    __shared__ __align__(16) uint32_t As[BM][BK + 4];
    __shared__ __align__(16) uint32_t Bs[BN][BK + 4];

    const int tid = threadIdx.x;
    const int wid = tid >> 5, lane = tid & 31;
    const int wm = wid & 1;        // 2 warps in M
    const int wn = wid >> 1;       // 4 warps in N
    const int lrow = lane >> 2, lcol = lane & 3;
    const int n0 = blockIdx.x * BN;
    const int m0 = blockIdx.y * BM;
    const int kbeg = blockIdx.z * chunk;
    const int kend = kbeg + chunk;

    float c[4][4][4];
    #pragma unroll
    for (int i = 0; i < 4; i++)
        #pragma unroll
        for (int j = 0; j < 4; j++)
            #pragma unroll
            for (int r = 0; r < 4; r++) c[i][j][r] = 0.0f;

    // global->shared mapping: row = tid>>1 (128 rows), half = tid&1 (16 floats)
    const int grow = tid >> 1, ghalf = tid & 1;
    const float* Ap = A + (size_t)(m0 + grow) * lda + ghalf * 16;
    const float* Bp = Bt + (size_t)(n0 + grow) * ldb + ghalf * 16;

    for (int k0 = kbeg; k0 < kend; k0 += BK) {
        #pragma unroll
        for (int j = 0; j < 4; j++) {
            float4 av = *(const float4*)(Ap + k0 + j * 4);
            uint32_t* d = &As[grow][ghalf * 16 + j * 4];
            d[0] = f2tf32(av.x); d[1] = f2tf32(av.y); d[2] = f2tf32(av.z); d[3] = f2tf32(av.w);
            float4 bv = *(const float4*)(Bp + k0 + j * 4);
            uint32_t* e = &Bs[grow][ghalf * 16 + j * 4];
            e[0] = f2tf32(bv.x); e[1] = f2tf32(bv.y); e[2] = f2tf32(bv.z); e[3] = f2tf32(bv.w);
        }
        __syncthreads();

        #pragma unroll
        for (int ks = 0; ks < 4; ks++) {
            uint32_t a[4][4], b[4][2];
            const int kc = ks * 8 + lcol;
            #pragma unroll
            for (int mi = 0; mi < 4; mi++) {
                const int r = wm * 64 + mi * 16 + lrow;
                a[mi][0] = As[r][kc];
                a[mi][1] = As[r + 8][kc];
                a[mi][2] = As[r][kc + 4];
                a[mi][3] = As[r + 8][kc + 4];
            }
            #pragma unroll
            for (int nj = 0; nj < 4; nj++) {
                const int n = wn * 32 + nj * 8 + lrow;
                b[nj][0] = Bs[n][kc];
                b[nj][1] = Bs[n][kc + 4];
            }
            #pragma unroll
            for (int mi = 0; mi < 4; mi++)
                #pragma unroll
                for (int nj = 0; nj < 4; nj++)
                    asm volatile(
                        "mma.sync.aligned.m16n8k8.row.col.f32.tf32.tf32.f32 "
                        "{%0,%1,%2,%3}, {%4,%5,%6,%7}, {%8,%9}, {%0,%1,%2,%3};"
                        : "+f"(c[mi][nj][0]), "+f"(c[mi][nj][1]),
                          "+f"(c[mi][nj][2]), "+f"(c[mi][nj][3])
                        : "r"(a[mi][0]), "r"(a[mi][1]), "r"(a[mi][2]), "r"(a[mi][3]),
                          "r"(b[nj][0]), "r"(b[nj][1]));
        }
        __syncthreads();
    }

    // epilogue: c0 at (row, col), c1 (row, col+1), c2 (row+8, col), c3 (row+8, col+1)
    const bool single = (gridDim.z == 1);
    const bool addb = (blockIdx.z == 0);
    #pragma unroll
    for (int mi = 0; mi < 4; mi++) {
        const int row = m0 + wm * 64 + mi * 16 + lrow;
        #pragma unroll
        for (int nj = 0; nj < 4; nj++) {
            const int col = n0 + wn * 32 + nj * 8 + 2 * lcol;
            float b0 = addb ? bias[col] : 0.0f;
            float b1 = addb ? bias[col + 1] : 0.0f;
            if (single) {
                *(float2*)&C[(size_t)row * ldc + col] =
                    make_float2(c[mi][nj][0] + b0, c[mi][nj][1] + b1);
                *(float2*)&C[(size_t)(row + 8) * ldc + col] =
                    make_float2(c[mi][nj][2] + b0, c[mi][nj][3] + b1);
            } else {
                atomicAdd(&C[(size_t)row * ldc + col],       c[mi][nj][0] + b0);
                atomicAdd(&C[(size_t)row * ldc + col + 1],   c[mi][nj][1] + b1);
                atomicAdd(&C[(size_t)(row + 8) * ldc + col],     c[mi][nj][2] + b0);
                atomicAdd(&C[(size_t)(row + 8) * ldc + col + 1], c[mi][nj][3] + b1);
            }
        }
    }
}

// ---------------- transpose: dst[n*ldd + koff + k] = src[k*N + n] ----------------
__global__ void transpose_into(const float* __restrict__ src, int K, int N,
                               float* __restrict__ dst, int ldd, int koff)
{
    __shared__ float tile[32][33];
    const int kb = blockIdx.x * 32, nb = blockIdx.y * 32;
    const int tx = threadIdx.x, ty = threadIdx.y;
    #pragma unroll
    for (int i = ty; i < 32; i += 8)
        tile[i][tx] = src[(size_t)(kb + i) * N + nb + tx];
    __syncthreads();
    #pragma unroll
    for (int i = ty; i < 32; i += 8)
        dst[(size_t)(nb + i) * ldd + koff + kb + tx] = tile[tx][i];
}

__global__ void gbias_kernel(const float* __restrict__ b_ih1, const float* __restrict__ b_hh1,
                             const float* __restrict__ b_ih2, const float* __restrict__ b_hh2)
{
    int i = blockIdx.x * blockDim.x + threadIdx.x;
    if (i < 4 * HDz) { g_gb1[i] = b_ih1[i] + b_hh1[i]; g_gb2[i] = b_ih2[i] + b_hh2[i]; }
}

// ---------------- init state (+ zero gates1, q) ----------------
__global__ void init_state(const float* __restrict__ h1_0, const float* __restrict__ c1_0,
                           const float* __restrict__ h2_0, const float* __restrict__ c2_0)
{
    int idx = blockIdx.x * blockDim.x + threadIdx.x;
    if (idx >= Bz * HDz) return;
    int b = idx >> 10, j = idx & (HDz - 1);
    g_c1[idx] = c1_0[idx];
    g_c2[idx] = c2_0[idx];
    g_abuf1[(size_t)b * K1z + 1536 + j] = h1_0[idx];
    g_abuf2[(size_t)b * K2z + 1024 + j] = h2_0[idx];
    g_hprev[idx] = 1.0f / (float)HEz;
    #pragma unroll
    for (int gi = 0; gi < 4; gi++)
        g_gates1[(size_t)b * 4 * HDz + gi * HDz + j] = 0.0f;
    if (idx < Bz * APz) g_q[idx] = 0.0f;
}

// ---------------- attention: logits (+ x_t copy) ----------------
__global__ __launch_bounds__(256) void attn_e(
    const int* __restrict__ enc_masks,
    const float* __restrict__ corr_w, const float* __restrict__ corr_b,
    const float* __restrict__ captions, int t)
{
    __shared__ __align__(16) float qv[APz];
    __shared__ __align__(16) float cw[APz];
    const int b = blockIdx.x, yc = blockIdx.y;
    const int tid = threadIdx.x, lane = tid & 31, warp = tid >> 5;

    for (int i = tid; i < APz; i += 256) { qv[i] = g_q[b * APz + i]; cw[i] = corr_w[i]; }
    if (tid < 128) {
        int ci = yc * 128 + tid;
        g_abuf1[(size_t)b * K1z + ci] = captions[((size_t)t * Bz + b) * Ez + ci];
    }
    __syncthreads();

    const float cb = corr_b[0];
    const float4* qv4 = (const float4*)qv;
    const float4* cw4 = (const float4*)cw;

    for (int l = yc * 32 + warp; l < yc * 32 + 32; l += 8) {
        const float4* ep = (const float4*)(g_enc_proj + ((size_t)(b * Lz + l)) * APz);
        float acc = 0.0f;
        #pragma unroll
        for (int i = 0; i < 4; i++) {
            int g = lane + 32 * i;
            float4 v = ep[g], q4 = qv4[g], w4 = cw4[g];
            acc += fast_tanh(v.x + q4.x) * w4.x;
            acc += fast_tanh(v.y + q4.y) * w4.y;
            acc += fast_tanh(v.z + q4.z) * w4.z;
            acc += fast_tanh(v.w + q4.w) * w4.w;
        }
        #pragma unroll
        for (int off = 16; off; off >>= 1) acc += __shfl_xor_sync(0xffffffffu, acc, off);
        if (lane == 0) {
            float v = acc + cb;
            if (enc_masks[b * Lz + l]) v = -INFINITY;
            g_e[b * Lz + l] = v;
        }
    }
}

// ---------------- attention: softmax + weighted sum ----------------
__global__ __launch_bounds__(256) void attn_at(const float* __restrict__ enc_hiddens)
{
    __shared__ float al[Lz];
    const int b = blockIdx.x, hc = blockIdx.y;
    const int tid = threadIdx.x;

    if (tid < Lz) al[tid] = g_e[b * Lz + tid];
    __syncthreads();
    if (tid < 32) {
        float m = -INFINITY;
        #pragma unroll
        for (int i = 0; i < 4; i++) m = fmaxf(m, al[tid + 32 * i]);
        #pragma unroll
        for (int off = 16; off; off >>= 1) m = fmaxf(m, __shfl_xor_sync(0xffffffffu, m, off));
        float ex[4], s = 0.0f;
        #pragma unroll
        for (int i = 0; i < 4; i++) { ex[i] = __expf(al[tid + 32 * i] - m); s += ex[i]; }
        #pragma unroll
        for (int off = 16; off; off >>= 1) s += __shfl_xor_sync(0xffffffffu, s, off);
        float inv = 1.0f / s;
        #pragma unroll
        for (int i = 0; i < 4; i++) al[tid + 32 * i] = ex[i] * inv;
    }
    __syncthreads();

    const int h = hc * 256 + tid;
    const float* eh = enc_hiddens + (size_t)b * Lz * HEz + h;
    float acc = 0.0f;
    #pragma unroll 8
    for (int l = 0; l < Lz; l++) acc += al[l] * eh[(size_t)l * HEz];
    g_abuf1[(size_t)b * K1z + Ez + h] = acc;
}

// ---------------- LSTM pointwise, layer 1 (+ zero gates2/outsc) ----------------
__global__ __launch_bounds__(256) void lstm_point1()
{
    int idx = blockIdx.x * blockDim.x + threadIdx.x;
    if (idx >= Bz * HDz) return;
    int b = idx >> 10, j = idx & (HDz - 1);
    const float* g = g_gates1 + (size_t)b * 4 * HDz;
    float ig = sigmoidf_(g[j]);
    float fg = sigmoidf_(g[HDz + j]);
    float gg = tanhf(g[2 * HDz + j]);
    float og = sigmoidf_(g[3 * HDz + j]);
    float cn = fg * g_c1[idx] + ig * gg;
    float hn = og * tanhf(cn);
    g_c1[idx] = cn;
    g_abuf2[(size_t)b * K2z + j] = hn;
    g_abuf1[(size_t)b * K1z + 1536 + j] = hn;
    #pragma unroll
    for (int gi = 0; gi < 4; gi++)
        g_gates2[(size_t)b * 4 * HDz + gi * HDz + j] = 0.0f;
    g_outsc[idx] = 0.0f;
}

// ---------------- LSTM pointwise, layer 2 (+ tanh out + zero gates1/q) ----------
__global__ __launch_bounds__(256) void lstm_point2(float* __restrict__ out)
{
    int idx = blockIdx.x * blockDim.x + threadIdx.x;
    if (idx >= Bz * HDz) return;
    int b = idx >> 10, j = idx & (HDz - 1);
    const float* g = g_gates2 + (size_t)b * 4 * HDz;
    float ig = sigmoidf_(g[j]);
    float fg = sigmoidf_(g[HDz + j]);
    float gg = tanhf(g[2 * HDz + j]);
    float og = sigmoidf_(g[3 * HDz + j]);
    float cn = fg * g_c2[idx] + ig * gg;
    float hn = og * tanhf(cn);
    g_c2[idx] = cn;
    g_abuf2[(size_t)b * K2z + 1024 + j] = hn;
    g_hprev[idx] = hn;
    out[idx] = tanhf(g_outsc[idx]);
    #pragma unroll
    for (int gi = 0; gi < 4; gi++)
        g_gates1[(size_t)b * 4 * HDz + gi * HDz + j] = 0.0f;
    if (idx < Bz * APz) g_q[idx] = 0.0f;
}

// ---------------- host launcher ----------------
extern "C" void kernel_launch(void* const* d_in, const int* in_sizes, int n_in,
                              void* d_out, int out_size)
{
    const float* enc_hiddens = (const float*)d_in[0];
    const int*   enc_masks   = (const int*)  d_in[1];
    const float* h1_0 = (const float*)d_in[2];
    const float* c1_0 = (const float*)d_in[3];
    const float* h2_0 = (const float*)d_in[4];
    const float* c2_0 = (const float*)d_in[5];
    const float* captions = (const float*)d_in[6];
    const float* att_W = (const float*)d_in[7];
    const float* att_b = (const float*)d_in[8];
    const float* dhp_W = (const float*)d_in[9];
    const float* dhp_b = (const float*)d_in[10];
    const float* corr_w = (const float*)d_in[11];
    const float* corr_b = (const float*)d_in[12];
    const float* lt_W = (const float*)d_in[13];
    const float* lt_b = (const float*)d_in[14];
    const float* W_ih1 = (const float*)d_in[15];
    const float* W_hh1 = (const float*)d_in[16];
    const float* b_ih1 = (const float*)d_in[17];
    const float* b_hh1 = (const float*)d_in[18];
    const float* W_ih2 = (const float*)d_in[19];
    const float* W_hh2 = (const float*)d_in[20];
    const float* b_ih2 = (const float*)d_in[21];
    const float* b_hh2 = (const float*)d_in[22];
    float* out = (float*)d_out;

    static bool inited = false;
    static float *p_enc_proj, *p_a1, *p_a2, *p_g1, *p_g2, *p_q, *p_outsc, *p_hprev;
    static float *p_W1t, *p_W2t, *p_ltWt, *p_dhpWt, *p_attWt, *p_gb1, *p_gb2;
    if (!inited) {
        cudaGetSymbolAddress((void**)&p_enc_proj, g_enc_proj);
        cudaGetSymbolAddress((void**)&p_a1,    g_abuf1);
        cudaGetSymbolAddress((void**)&p_a2,    g_abuf2);
        cudaGetSymbolAddress((void**)&p_g1,    g_gates1);
        cudaGetSymbolAddress((void**)&p_g2,    g_gates2);
        cudaGetSymbolAddress((void**)&p_q,     g_q);
        cudaGetSymbolAddress((void**)&p_outsc, g_outsc);
        cudaGetSymbolAddress((void**)&p_hprev, g_hprev);
        cudaGetSymbolAddress((void**)&p_W1t,   g_W1t);
        cudaGetSymbolAddress((void**)&p_W2t,   g_W2t);
        cudaGetSymbolAddress((void**)&p_ltWt,  g_ltWt);
        cudaGetSymbolAddress((void**)&p_dhpWt, g_dhpWt);
        cudaGetSymbolAddress((void**)&p_attWt, g_attWt);
        cudaGetSymbolAddress((void**)&p_gb1,   g_gb1);
        cudaGetSymbolAddress((void**)&p_gb2,   g_gb2);
        inited = true;
    }
    dim3 tb(32, 8);

    init_state<<<(Bz * HDz + 255) / 256, 256>>>(h1_0, c1_0, h2_0, c2_0);

    // one-time weight transposes (K-major [N, K])
    transpose_into<<<dim3(HEz / 32, APz / 32), tb>>>(att_W, HEz, APz, p_attWt, HEz, 0);
    transpose_into<<<dim3(HDz / 32, APz / 32), tb>>>(dhp_W, HDz, APz, p_dhpWt, HDz, 0);
    transpose_into<<<dim3(HDz / 32, HDz / 32), tb>>>(lt_W, HDz, HDz, p_ltWt, HDz, 0);
    transpose_into<<<dim3(1536 / 32, 4 * HDz / 32), tb>>>(W_ih1, 1536, 4 * HDz, p_W1t, K1z, 0);
    transpose_into<<<dim3(HDz / 32, 4 * HDz / 32), tb>>>(W_hh1, HDz, 4 * HDz, p_W1t, K1z, 1536);
    transpose_into<<<dim3(HDz / 32, 4 * HDz / 32), tb>>>(W_ih2, HDz, 4 * HDz, p_W2t, K2z, 0);
    transpose_into<<<dim3(HDz / 32, 4 * HDz / 32), tb>>>(W_hh2, HDz, 4 * HDz, p_W2t, K2z, 1024);
    gbias_kernel<<<(4 * HDz + 255) / 256, 256>>>(b_ih1, b_hh1, b_ih2, b_hh2);

    // enc_proj = enc_hiddens @ att_W + att_b  (direct store, z=1)
    gemm_mma<<<dim3(APz / BN, Bz * Lz / BM, 1), 256>>>(
        enc_hiddens, HEz, p_attWt, HEz, p_enc_proj, APz, HEz, att_b);

    for (int t = 0; t < Tz; t++) {
        // q += hprev @ dhp_W (+dhp_b at z==0)   K=1024, z=8
        gemm_mma<<<dim3(APz / BN, 1, 8), 256>>>(
            p_hprev, HDz, p_dhpWt, HDz, p_q, APz, 128, dhp_b);

        attn_e<<<dim3(Bz, 4), 256>>>(enc_masks, corr_w, corr_b, captions, t);
        attn_at<<<dim3(Bz, HEz / 256), 256>>>(enc_hiddens);

        // gates1 += [x|a|h1] @ W1t^T (+gb1)   K=2560, z=4
        gemm_mma<<<dim3(4 * HDz / BN, 1, 4), 256>>>(
            p_a1, K1z, p_W1t, K1z, p_g1, 4 * HDz, 640, p_gb1);
        lstm_point1<<<(Bz * HDz + 255) / 256, 256>>>();

        // outsc += h1 @ lt_W (+lt_b)   K=1024, z=8
        gemm_mma<<<dim3(HDz / BN, 1, 8), 256>>>(
            p_a2, K2z, p_ltWt, HDz, p_outsc, HDz, 128, lt_b);

        // gates2 += [h1|h2] @ W2t^T (+gb2)   K=2048, z=4
        gemm_mma<<<dim3(4 * HDz / BN, 1, 4), 256>>>(
            p_a2, K2z, p_W2t, K2z, p_g2, 4 * HDz, 512, p_gb2);

        lstm_point2<<<(Bz * HDz + 255) / 256, 256>>>(out + (size_t)t * Bz * HDz);
    }
    (void)in_sizes; (void)n_in; (void)out_size;
}

// round 5
// speedup vs baseline: 4.3920x; 1.1888x over previous
#include <cuda_runtime.h>
#include <math.h>
#include <cstdint>

#define Bz 128
#define Lz 128
#define HEz 1024
#define HDz 1024
#define Ez 512
#define APz 512
#define Tz 64
#define K1z 2560        // [x_t | a_t | h1_prev]
#define K2z 2048        // [h1 | h2]
#define N2z 5120        // gates2 (4096) + out-proj (1024)

// ---------------- device scratch ----------------
__device__ __align__(128) float g_enc_proj[Bz * Lz * APz];
__device__ __align__(128) float g_ehtf[Bz * Lz * HEz];      // tf32-rounded enc_hiddens
__device__ __align__(128) float g_q[Bz * APz];
__device__ __align__(128) float g_e[Bz * Lz];
__device__ __align__(128) float g_abuf1[Bz * K1z];
__device__ __align__(128) float g_abuf2[Bz * K2z];
__device__ __align__(128) float g_gates1[Bz * 4 * HDz];
__device__ __align__(128) float g_g2c[Bz * N2z];            // gates2 | outsc
__device__ __align__(128) float g_c1[Bz * HDz];
__device__ __align__(128) float g_c2[Bz * HDz];
__device__ __align__(128) float g_hprev[Bz * HDz];
// pre-transposed, tf32-rounded K-major weights [N, K]
__device__ __align__(128) float g_W1t[4 * HDz * K1z];
__device__ __align__(128) float g_W2c[N2z * K2z];
__device__ __align__(128) float g_dhpWt[APz * HDz];
__device__ __align__(128) float g_attWt[APz * HEz];
__device__ __align__(128) float g_gb1[4 * HDz];
__device__ __align__(128) float g_gb2c[N2z];

__device__ __forceinline__ float fast_tanh(float x) {
    float y; asm("tanh.approx.f32 %0, %1;" : "=f"(y) : "f"(x)); return y;
}
__device__ __forceinline__ float sigmoidf_(float x) { return 1.0f / (1.0f + expf(-x)); }
__device__ __forceinline__ float f2tf32f(float x) {
    uint32_t u; asm("cvt.rna.tf32.f32 %0, %1;" : "=r"(u) : "f"(x));
    return __uint_as_float(u);
}
__device__ __forceinline__ uint32_t smem_u32(const void* p) {
    uint32_t a;
    asm("{ .reg .u64 t; cvta.to.shared.u64 t, %1; cvt.u32.u64 %0, t; }" : "=r"(a) : "l"(p));
    return a;
}
#define CP16(dst, src) \
    asm volatile("cp.async.cg.shared.global [%0], [%1], 16;" :: "r"(dst), "l"(src))

// ---------------- pipelined HMMA tf32 GEMM ----------------
// C[m0:+128, n0:+128] (+)= A[m0:, kslice](lda) @ Bt[n0:, kslice]^T
// A and Bt must already be tf32-rounded. grid (N/128, M/128, Z), chunk*Z == K.
// Z==1: direct store C = acc + bias.  Z>1: atomicAdd into zeroed C, z==0 adds bias.
#define BM 128
#define BN 128
#define BK 32
#define SWRD 36
#define STGW (2 * 128 * SWRD)   // words per stage (A tile + B tile)

__global__ __launch_bounds__(256, 2) void gemm_mma(
    const float* __restrict__ A, int lda,
    const float* __restrict__ Bt, int ldb,
    float* __restrict__ C, int ldc,
    int chunk, const float* __restrict__ bias)
{
    extern __shared__ float sm[];
    const int tid = threadIdx.x;
    const int wid = tid >> 5, lane = tid & 31;
    const int wm = wid & 1, wn = wid >> 1;
    const int lrow = lane >> 2, lcol = lane & 3;
    const int n0 = blockIdx.x * BN;
    const int m0 = blockIdx.y * BM;
    const int kbeg = blockIdx.z * chunk;
    const int NC = chunk / BK;

    float c[4][4][4];
    #pragma unroll
    for (int i = 0; i < 4; i++)
        #pragma unroll
        for (int j = 0; j < 4; j++)
            #pragma unroll
            for (int r = 0; r < 4; r++) c[i][j][r] = 0.0f;

    const int grow = tid >> 1, ghalf = tid & 1;
    const float* Ap = A + (size_t)(m0 + grow) * lda + ghalf * 16 + kbeg;
    const float* Bp = Bt + (size_t)(n0 + grow) * ldb + ghalf * 16 + kbeg;
    const uint32_t sbase = smem_u32(sm);
    const uint32_t doffA = (grow * SWRD + ghalf * 16) * 4;

    // prologue: stage 0 <- chunk 0
    {
        uint32_t au = sbase + doffA;
        uint32_t bu = au + 128 * SWRD * 4;
        #pragma unroll
        for (int j = 0; j < 4; j++) {
            CP16(au + j * 16, Ap + j * 4);
            CP16(bu + j * 16, Bp + j * 4);
        }
        asm volatile("cp.async.commit_group;" ::: "memory");
    }

    for (int cc = 0; cc < NC; cc++) {
        const int s = cc & 1;
        if (cc + 1 < NC) {
            const int s2 = s ^ 1;
            uint32_t au = sbase + s2 * STGW * 4 + doffA;
            uint32_t bu = au + 128 * SWRD * 4;
            const int k0 = (cc + 1) * BK;
            #pragma unroll
            for (int j = 0; j < 4; j++) {
                CP16(au + j * 16, Ap + k0 + j * 4);
                CP16(bu + j * 16, Bp + k0 + j * 4);
            }
            asm volatile("cp.async.commit_group;" ::: "memory");
            asm volatile("cp.async.wait_group 1;" ::: "memory");
        } else {
            asm volatile("cp.async.wait_group 0;" ::: "memory");
        }
        __syncthreads();

        const uint32_t* as32 = (const uint32_t*)(sm + (size_t)s * STGW);
        const uint32_t* bs32 = as32 + 128 * SWRD;

        #pragma unroll
        for (int ks = 0; ks < 4; ks++) {
            uint32_t a[4][4], b[4][2];
            const int kc = ks * 8 + lcol;
            #pragma unroll
            for (int mi = 0; mi < 4; mi++) {
                const int r = wm * 64 + mi * 16 + lrow;
                a[mi][0] = as32[r * SWRD + kc];
                a[mi][1] = as32[(r + 8) * SWRD + kc];
                a[mi][2] = as32[r * SWRD + kc + 4];
                a[mi][3] = as32[(r + 8) * SWRD + kc + 4];
            }
            #pragma unroll
            for (int nj = 0; nj < 4; nj++) {
                const int n = wn * 32 + nj * 8 + lrow;
                b[nj][0] = bs32[n * SWRD + kc];
                b[nj][1] = bs32[n * SWRD + kc + 4];
            }
            #pragma unroll
            for (int mi = 0; mi < 4; mi++)
                #pragma unroll
                for (int nj = 0; nj < 4; nj++)
                    asm volatile(
                        "mma.sync.aligned.m16n8k8.row.col.f32.tf32.tf32.f32 "
                        "{%0,%1,%2,%3}, {%4,%5,%6,%7}, {%8,%9}, {%0,%1,%2,%3};"
                        : "+f"(c[mi][nj][0]), "+f"(c[mi][nj][1]),
                          "+f"(c[mi][nj][2]), "+f"(c[mi][nj][3])
                        : "r"(a[mi][0]), "r"(a[mi][1]), "r"(a[mi][2]), "r"(a[mi][3]),
                          "r"(b[nj][0]), "r"(b[nj][1]));
        }
        __syncthreads();
    }

    const bool single = (gridDim.z == 1);
    const bool addb = (blockIdx.z == 0);
    #pragma unroll
    for (int mi = 0; mi < 4; mi++) {
        const int row = m0 + wm * 64 + mi * 16 + lrow;
        #pragma unroll
        for (int nj = 0; nj < 4; nj++) {
            const int col = n0 + wn * 32 + nj * 8 + 2 * lcol;
            float b0 = addb ? bias[col] : 0.0f;
            float b1 = addb ? bias[col + 1] : 0.0f;
            if (single) {
                *(float2*)&C[(size_t)row * ldc + col] =
                    make_float2(c[mi][nj][0] + b0, c[mi][nj][1] + b1);
                *(float2*)&C[(size_t)(row + 8) * ldc + col] =
                    make_float2(c[mi][nj][2] + b0, c[mi][nj][3] + b1);
            } else {
                atomicAdd(&C[(size_t)row * ldc + col],           c[mi][nj][0] + b0);
                atomicAdd(&C[(size_t)row * ldc + col + 1],       c[mi][nj][1] + b1);
                atomicAdd(&C[(size_t)(row + 8) * ldc + col],     c[mi][nj][2] + b0);
                atomicAdd(&C[(size_t)(row + 8) * ldc + col + 1], c[mi][nj][3] + b1);
            }
        }
    }
}

// ---------------- transpose with tf32 rounding: dst[n*ldd+koff+k] = tf32(src[k*N+n])
__global__ void transpose_into(const float* __restrict__ src, int K, int N,
                               float* __restrict__ dst, int ldd, int koff)
{
    __shared__ float tile[32][33];
    const int kb = blockIdx.x * 32, nb = blockIdx.y * 32;
    const int tx = threadIdx.x, ty = threadIdx.y;
    #pragma unroll
    for (int i = ty; i < 32; i += 8)
        tile[i][tx] = src[(size_t)(kb + i) * N + nb + tx];
    __syncthreads();
    #pragma unroll
    for (int i = ty; i < 32; i += 8)
        dst[(size_t)(nb + i) * ldd + koff + kb + tx] = f2tf32f(tile[tx][i]);
}

// zero a rectangular region dst[r0..r0+rows) x [c0..c0+cols) with pitch ldd
__global__ void zero_region(float* __restrict__ dst, int ldd, int r0, int c0, int cols)
{
    dst[(size_t)(r0 + blockIdx.x) * ldd + c0 + threadIdx.x * 4 + 0] = 0.0f;
    dst[(size_t)(r0 + blockIdx.x) * ldd + c0 + threadIdx.x * 4 + 1] = 0.0f;
    dst[(size_t)(r0 + blockIdx.x) * ldd + c0 + threadIdx.x * 4 + 2] = 0.0f;
    dst[(size_t)(r0 + blockIdx.x) * ldd + c0 + threadIdx.x * 4 + 3] = 0.0f;
}

// tf32-round enc_hiddens into scratch (one-time)
__global__ void cvt_eh(const float* __restrict__ src)
{
    size_t i = (size_t)blockIdx.x * blockDim.x + threadIdx.x;
    float4 v = *(const float4*)(src + i * 4);
    v.x = f2tf32f(v.x); v.y = f2tf32f(v.y); v.z = f2tf32f(v.z); v.w = f2tf32f(v.w);
    *(float4*)(g_ehtf + i * 4) = v;
}

__global__ void gbias_kernel(const float* __restrict__ b_ih1, const float* __restrict__ b_hh1,
                             const float* __restrict__ b_ih2, const float* __restrict__ b_hh2,
                             const float* __restrict__ lt_b)
{
    int i = blockIdx.x * blockDim.x + threadIdx.x;
    if (i < 4 * HDz) {
        g_gb1[i] = b_ih1[i] + b_hh1[i];
        g_gb2c[i] = b_ih2[i] + b_hh2[i];
    }
    if (i < HDz) g_gb2c[4 * HDz + i] = lt_b[i];
}

// ---------------- init state (+ zero gates1, q) ----------------
__global__ void init_state(const float* __restrict__ h1_0, const float* __restrict__ c1_0,
                           const float* __restrict__ h2_0, const float* __restrict__ c2_0)
{
    int idx = blockIdx.x * blockDim.x + threadIdx.x;
    if (idx >= Bz * HDz) return;
    int b = idx >> 10, j = idx & (HDz - 1);
    g_c1[idx] = c1_0[idx];
    g_c2[idx] = c2_0[idx];
    g_abuf1[(size_t)b * K1z + 1536 + j] = f2tf32f(h1_0[idx]);
    g_abuf2[(size_t)b * K2z + 1024 + j] = f2tf32f(h2_0[idx]);
    g_hprev[idx] = f2tf32f(1.0f / (float)HEz);
    #pragma unroll
    for (int gi = 0; gi < 4; gi++)
        g_gates1[(size_t)b * 4 * HDz + gi * HDz + j] = 0.0f;
    if (idx < Bz * APz) g_q[idx] = 0.0f;
}

// ---------------- attention: logits (+ x_t copy) ----------------
__global__ __launch_bounds__(256) void attn_e(
    const int* __restrict__ enc_masks,
    const float* __restrict__ corr_w, const float* __restrict__ corr_b,
    const float* __restrict__ captions, int t)
{
    __shared__ __align__(16) float qv[APz];
    __shared__ __align__(16) float cw[APz];
    const int b = blockIdx.x, yc = blockIdx.y;
    const int tid = threadIdx.x, lane = tid & 31, warp = tid >> 5;

    for (int i = tid; i < APz; i += 256) { qv[i] = g_q[b * APz + i]; cw[i] = corr_w[i]; }
    if (tid < 128) {
        int ci = yc * 128 + tid;
        g_abuf1[(size_t)b * K1z + ci] = f2tf32f(captions[((size_t)t * Bz + b) * Ez + ci]);
    }
    __syncthreads();

    const float cb = corr_b[0];
    const float4* qv4 = (const float4*)qv;
    const float4* cw4 = (const float4*)cw;

    for (int l = yc * 32 + warp; l < yc * 32 + 32; l += 8) {
        const float4* ep = (const float4*)(g_enc_proj + ((size_t)(b * Lz + l)) * APz);
        float acc = 0.0f;
        #pragma unroll
        for (int i = 0; i < 4; i++) {
            int g = lane + 32 * i;
            float4 v = ep[g], q4 = qv4[g], w4 = cw4[g];
            acc += fast_tanh(v.x + q4.x) * w4.x;
            acc += fast_tanh(v.y + q4.y) * w4.y;
            acc += fast_tanh(v.z + q4.z) * w4.z;
            acc += fast_tanh(v.w + q4.w) * w4.w;
        }
        #pragma unroll
        for (int off = 16; off; off >>= 1) acc += __shfl_xor_sync(0xffffffffu, acc, off);
        if (lane == 0) {
            float v = acc + cb;
            if (enc_masks[b * Lz + l]) v = -INFINITY;
            g_e[b * Lz + l] = v;
        }
    }
}

// ---------------- attention: softmax + weighted sum ----------------
__global__ __launch_bounds__(256) void attn_at(const float* __restrict__ enc_hiddens)
{
    __shared__ float al[Lz];
    const int b = blockIdx.x, hc = blockIdx.y;
    const int tid = threadIdx.x;

    if (tid < Lz) al[tid] = g_e[b * Lz + tid];
    __syncthreads();
    if (tid < 32) {
        float m = -INFINITY;
        #pragma unroll
        for (int i = 0; i < 4; i++) m = fmaxf(m, al[tid + 32 * i]);
        #pragma unroll
        for (int off = 16; off; off >>= 1) m = fmaxf(m, __shfl_xor_sync(0xffffffffu, m, off));
        float ex[4], s = 0.0f;
        #pragma unroll
        for (int i = 0; i < 4; i++) { ex[i] = __expf(al[tid + 32 * i] - m); s += ex[i]; }
        #pragma unroll
        for (int off = 16; off; off >>= 1) s += __shfl_xor_sync(0xffffffffu, s, off);
        float inv = 1.0f / s;
        #pragma unroll
        for (int i = 0; i < 4; i++) al[tid + 32 * i] = ex[i] * inv;
    }
    __syncthreads();

    const int h = hc * 256 + tid;
    const float* eh = enc_hiddens + (size_t)b * Lz * HEz + h;
    float acc = 0.0f;
    #pragma unroll 8
    for (int l = 0; l < Lz; l++) acc += al[l] * eh[(size_t)l * HEz];
    g_abuf1[(size_t)b * K1z + Ez + h] = f2tf32f(acc);
}

// ---------------- LSTM pointwise, layer 1 (+ zero g2c) ----------------
__global__ __launch_bounds__(256) void lstm_point1()
{
    int idx = blockIdx.x * blockDim.x + threadIdx.x;
    if (idx >= Bz * HDz) return;
    int b = idx >> 10, j = idx & (HDz - 1);
    const float* g = g_gates1 + (size_t)b * 4 * HDz;
    float ig = sigmoidf_(g[j]);
    float fg = sigmoidf_(g[HDz + j]);
    float gg = tanhf(g[2 * HDz + j]);
    float og = sigmoidf_(g[3 * HDz + j]);
    float cn = fg * g_c1[idx] + ig * gg;
    float hn = og * tanhf(cn);
    g_c1[idx] = cn;
    float hn_t = f2tf32f(hn);
    g_abuf2[(size_t)b * K2z + j] = hn_t;
    g_abuf1[(size_t)b * K1z + 1536 + j] = hn_t;
    #pragma unroll
    for (int gi = 0; gi < 5; gi++)
        g_g2c[(size_t)b * N2z + gi * HDz + j] = 0.0f;
}

// ---------------- LSTM pointwise, layer 2 (+ tanh out + zero gates1/q) ----------
__global__ __launch_bounds__(256) void lstm_point2(float* __restrict__ out)
{
    int idx = blockIdx.x * blockDim.x + threadIdx.x;
    if (idx >= Bz * HDz) return;
    int b = idx >> 10, j = idx & (HDz - 1);
    const float* g = g_g2c + (size_t)b * N2z;
    float ig = sigmoidf_(g[j]);
    float fg = sigmoidf_(g[HDz + j]);
    float gg = tanhf(g[2 * HDz + j]);
    float og = sigmoidf_(g[3 * HDz + j]);
    float cn = fg * g_c2[idx] + ig * gg;
    float hn = og * tanhf(cn);
    g_c2[idx] = cn;
    float hn_t = f2tf32f(hn);
    g_abuf2[(size_t)b * K2z + 1024 + j] = hn_t;
    g_hprev[idx] = hn_t;
    out[idx] = tanhf(g[4 * HDz + j]);
    #pragma unroll
    for (int gi = 0; gi < 4; gi++)
        g_gates1[(size_t)b * 4 * HDz + gi * HDz + j] = 0.0f;
    if (idx < Bz * APz) g_q[idx] = 0.0f;
}

// ---------------- host launcher ----------------
extern "C" void kernel_launch(void* const* d_in, const int* in_sizes, int n_in,
                              void* d_out, int out_size)
{
    const float* enc_hiddens = (const float*)d_in[0];
    const int*   enc_masks   = (const int*)  d_in[1];
    const float* h1_0 = (const float*)d_in[2];
    const float* c1_0 = (const float*)d_in[3];
    const float* h2_0 = (const float*)d_in[4];
    const float* c2_0 = (const float*)d_in[5];
    const float* captions = (const float*)d_in[6];
    const float* att_W = (const float*)d_in[7];
    const float* att_b = (const float*)d_in[8];
    const float* dhp_W = (const float*)d_in[9];
    const float* dhp_b = (const float*)d_in[10];
    const float* corr_w = (const float*)d_in[11];
    const float* corr_b = (const float*)d_in[12];
    const float* lt_W = (const float*)d_in[13];
    const float* lt_b = (const float*)d_in[14];
    const float* W_ih1 = (const float*)d_in[15];
    const float* W_hh1 = (const float*)d_in[16];
    const float* b_ih1 = (const float*)d_in[17];
    const float* b_hh1 = (const float*)d_in[18];
    const float* W_ih2 = (const float*)d_in[19];
    const float* W_hh2 = (const float*)d_in[20];
    const float* b_ih2 = (const float*)d_in[21];
    const float* b_hh2 = (const float*)d_in[22];
    float* out = (float*)d_out;

    static bool inited = false;
    static float *p_enc_proj, *p_ehtf, *p_a1, *p_a2, *p_g1, *p_g2c, *p_q, *p_hprev;
    static float *p_W1t, *p_W2c, *p_dhpWt, *p_attWt, *p_gb1, *p_gb2c;
    if (!inited) {
        cudaGetSymbolAddress((void**)&p_enc_proj, g_enc_proj);
        cudaGetSymbolAddress((void**)&p_ehtf,  g_ehtf);
        cudaGetSymbolAddress((void**)&p_a1,    g_abuf1);
        cudaGetSymbolAddress((void**)&p_a2,    g_abuf2);
        cudaGetSymbolAddress((void**)&p_g1,    g_gates1);
        cudaGetSymbolAddress((void**)&p_g2c,   g_g2c);
        cudaGetSymbolAddress((void**)&p_q,     g_q);
        cudaGetSymbolAddress((void**)&p_hprev, g_hprev);
        cudaGetSymbolAddress((void**)&p_W1t,   g_W1t);
        cudaGetSymbolAddress((void**)&p_W2c,   g_W2c);
        cudaGetSymbolAddress((void**)&p_dhpWt, g_dhpWt);
        cudaGetSymbolAddress((void**)&p_attWt, g_attWt);
        cudaGetSymbolAddress((void**)&p_gb1,   g_gb1);
        cudaGetSymbolAddress((void**)&p_gb2c,  g_gb2c);
        cudaFuncSetAttribute(gemm_mma, cudaFuncAttributeMaxDynamicSharedMemorySize,
                             2 * STGW * 4);
        inited = true;
    }
    const int GSM = 2 * STGW * 4;   // 73728 B
    dim3 tb(32, 8);

    init_state<<<(Bz * HDz + 255) / 256, 256>>>(h1_0, c1_0, h2_0, c2_0);

    // one-time: tf32-rounded weights (K-major [N,K]) + enc_hiddens copy
    transpose_into<<<dim3(HEz / 32, APz / 32), tb>>>(att_W, HEz, APz, p_attWt, HEz, 0);
    transpose_into<<<dim3(HDz / 32, APz / 32), tb>>>(dhp_W, HDz, APz, p_dhpWt, HDz, 0);
    transpose_into<<<dim3(1536 / 32, 4 * HDz / 32), tb>>>(W_ih1, 1536, 4 * HDz, p_W1t, K1z, 0);
    transpose_into<<<dim3(HDz / 32, 4 * HDz / 32), tb>>>(W_hh1, HDz, 4 * HDz, p_W1t, K1z, 1536);
    transpose_into<<<dim3(HDz / 32, 4 * HDz / 32), tb>>>(W_ih2, HDz, 4 * HDz, p_W2c, K2z, 0);
    transpose_into<<<dim3(HDz / 32, 4 * HDz / 32), tb>>>(W_hh2, HDz, 4 * HDz, p_W2c, K2z, 1024);
    transpose_into<<<dim3(HDz / 32, HDz / 32), tb>>>(lt_W, HDz, HDz,
                                                     p_W2c + (size_t)4 * HDz * K2z, K2z, 0);
    zero_region<<<HDz, 256>>>(p_W2c, K2z, 4 * HDz, 1024, 1024);
    cvt_eh<<<(Bz * Lz * HEz / 4 + 255) / 256, 256>>>(enc_hiddens);
    gbias_kernel<<<(4 * HDz + 255) / 256, 256>>>(b_ih1, b_hh1, b_ih2, b_hh2, lt_b);

    // enc_proj = enc_hiddens @ att_W + att_b  (direct store)
    gemm_mma<<<dim3(APz / BN, Bz * Lz / BM, 1), 256, GSM>>>(
        p_ehtf, HEz, p_attWt, HEz, p_enc_proj, APz, HEz, att_b);

    for (int t = 0; t < Tz; t++) {
        // q += hprev @ dhp_W (+dhp_b)   K=1024, z=8
        gemm_mma<<<dim3(APz / BN, 1, 8), 256, GSM>>>(
            p_hprev, HDz, p_dhpWt, HDz, p_q, APz, 128, dhp_b);

        attn_e<<<dim3(Bz, 4), 256>>>(enc_masks, corr_w, corr_b, captions, t);
        attn_at<<<dim3(Bz, HEz / 256), 256>>>(enc_hiddens);

        // gates1 += [x|a|h1] @ W1t^T (+gb1)   K=2560, z=8
        gemm_mma<<<dim3(4 * HDz / BN, 1, 8), 256, GSM>>>(
            p_a1, K1z, p_W1t, K1z, p_g1, 4 * HDz, 320, p_gb1);
        lstm_point1<<<(Bz * HDz + 255) / 256, 256>>>();

        // [gates2 | outsc] += [h1|h2] @ W2c^T (+gb2c)   K=2048, z=8
        gemm_mma<<<dim3(N2z / BN, 1, 8), 256, GSM>>>(
            p_a2, K2z, p_W2c, K2z, p_g2c, N2z, 256, p_gb2c);

        lstm_point2<<<(Bz * HDz + 255) / 256, 256>>>(out + (size_t)t * Bz * HDz);
    }
    (void)in_sizes; (void)n_in; (void)out_size;
}

// round 6
// speedup vs baseline: 4.8223x; 1.0980x over previous
#include <cuda_runtime.h>
#include <math.h>
#include <cstdint>

#define Bz 128
#define Lz 128
#define HEz 1024
#define HDz 1024
#define Ez 512
#define APz 512
#define Tz 64
#define K1z 2560        // [x_t | a_t | h1_prev]
#define K2z 2048        // [h1 | h2]
#define N2z 5120        // gates2 (4096) + out-proj (1024)

// ---------------- device scratch ----------------
__device__ __align__(128) float g_enc_proj[Bz * Lz * APz];
__device__ __align__(128) float g_ehtf[Bz * Lz * HEz];      // tf32-rounded enc_hiddens
__device__ __align__(128) float g_q[Bz * APz];
__device__ __align__(128) float g_e[Bz * Lz];
__device__ __align__(128) float g_abuf1[Bz * K1z];
__device__ __align__(128) float g_abuf2[Bz * K2z];
__device__ __align__(128) float g_gates1[Bz * 4 * HDz];
__device__ __align__(128) float g_g2c[Bz * N2z];            // gates2 | outsc
__device__ __align__(128) float g_c1[Bz * HDz];
__device__ __align__(128) float g_c2[Bz * HDz];
__device__ __align__(128) float g_hprev[Bz * HDz];
// pre-transposed, tf32-rounded K-major weights [N, K]
__device__ __align__(128) float g_W1t[4 * HDz * K1z];
__device__ __align__(128) float g_W2c[N2z * K2z];
__device__ __align__(128) float g_dhpWt[APz * HDz];
__device__ __align__(128) float g_attWt[APz * HEz];
__device__ __align__(128) float g_gb1[4 * HDz];
__device__ __align__(128) float g_gb2c[N2z];

__device__ __forceinline__ float fast_tanh(float x) {
    float y; asm("tanh.approx.f32 %0, %1;" : "=f"(y) : "f"(x)); return y;
}
__device__ __forceinline__ float sigmoidf_(float x) { return 1.0f / (1.0f + expf(-x)); }
__device__ __forceinline__ float f2tf32f(float x) {
    uint32_t u; asm("cvt.rna.tf32.f32 %0, %1;" : "=r"(u) : "f"(x));
    return __uint_as_float(u);
}
__device__ __forceinline__ uint32_t smem_u32(const void* p) {
    uint32_t a;
    asm("{ .reg .u64 t; cvta.to.shared.u64 t, %1; cvt.u32.u64 %0, t; }" : "=r"(a) : "l"(p));
    return a;
}
#define CP16(dst, src) \
    asm volatile("cp.async.cg.shared.global [%0], [%1], 16;" :: "r"(dst), "l"(src))
#define CP16P(dst, src, pol) \
    asm volatile("cp.async.cg.shared.global.L2::cache_hint [%0], [%1], 16, %2;" \
                 :: "r"(dst), "l"(src), "l"(pol))

// ---------------- 3-stage pipelined HMMA tf32 GEMM ----------------
// C[m0:+64, n0:+128] (+)= A[m0:, kslice](lda) @ Bt[n0:, kslice]^T
// A, Bt must be tf32-rounded. grid (N/128, M/64, Z), chunk*Z == K, chunk%32==0.
// Z==1: direct store C = acc + bias.  Z>1: atomicAdd into zeroed C; z==0 adds bias.
#define BMt 64
#define BN 128
#define BK 32
#define SWRD 36
#define STGW ((BMt + BN) * SWRD)    // words per stage

__global__ __launch_bounds__(256, 2) void gemm_mma(
    const float* __restrict__ A, int lda,
    const float* __restrict__ Bt, int ldb,
    float* __restrict__ C, int ldc,
    int chunk, const float* __restrict__ bias)
{
    extern __shared__ float sm[];
    const int tid = threadIdx.x;
    const int wid = tid >> 5, lane = tid & 31;
    const int wm = wid & 1, wn = wid >> 1;
    const int lrow = lane >> 2, lcol = lane & 3;
    const int n0 = blockIdx.x * BN;
    const int m0 = blockIdx.y * BMt;
    const int kbeg = blockIdx.z * chunk;
    const int NC = chunk / BK;

    uint64_t pol;
    asm("createpolicy.fractional.L2::evict_first.b64 %0, 1.0;" : "=l"(pol));

    float c[2][4][4];
    #pragma unroll
    for (int i = 0; i < 2; i++)
        #pragma unroll
        for (int j = 0; j < 4; j++)
            #pragma unroll
            for (int r = 0; r < 4; r++) c[i][j][r] = 0.0f;

    const uint32_t sbase = smem_u32(sm);
    const float* Abase = A + (size_t)m0 * lda + kbeg;
    const float* Bbase = Bt + (size_t)n0 * ldb + kbeg;

    // per-thread load slots (A: 2 chunks of 16B, B: 4 chunks of 16B)
    const int ar0 = (tid + 0)   >> 3, ao0 = (tid + 0)   & 7;
    const int ar1 = (tid + 256) >> 3, ao1 = (tid + 256) & 7;

#define LOAD_STAGE(ck, st) do {                                                   \
        uint32_t sb = sbase + (uint32_t)(st) * STGW * 4;                          \
        const float* Ag = Abase + (ck) * BK;                                      \
        const float* Bg = Bbase + (ck) * BK;                                      \
        CP16(sb + (ar0 * SWRD + ao0 * 4) * 4, Ag + (size_t)ar0 * lda + ao0 * 4);  \
        CP16(sb + (ar1 * SWRD + ao1 * 4) * 4, Ag + (size_t)ar1 * lda + ao1 * 4);  \
        _Pragma("unroll")                                                         \
        for (int j = 0; j < 4; j++) {                                             \
            int i = tid + j * 256;                                                \
            int row = i >> 3, off = i & 7;                                        \
            CP16P(sb + ((BMt + row) * SWRD + off * 4) * 4,                        \
                  Bg + (size_t)row * ldb + off * 4, pol);                         \
        }                                                                         \
    } while (0)

    // prologue: chunks 0,1 -> stages 0,1
    LOAD_STAGE(0, 0);
    asm volatile("cp.async.commit_group;" ::: "memory");
    LOAD_STAGE(1, 1);
    asm volatile("cp.async.commit_group;" ::: "memory");

    int s = 0;
    for (int cc = 0; cc < NC; cc++) {
        asm volatile("cp.async.wait_group 1;" ::: "memory");
        __syncthreads();
        if (cc + 2 < NC) {
            int st = s + 2 >= 3 ? s - 1 : s + 2;
            LOAD_STAGE(cc + 2, st);
        }
        asm volatile("cp.async.commit_group;" ::: "memory");

        const uint32_t* as32 = (const uint32_t*)(sm + (size_t)s * STGW);
        const uint32_t* bs32 = as32 + BMt * SWRD;

        #pragma unroll
        for (int ks = 0; ks < 4; ks++) {
            uint32_t a[2][4], b[4][2];
            const int kc = ks * 8 + lcol;
            #pragma unroll
            for (int mi = 0; mi < 2; mi++) {
                const int r = wm * 32 + mi * 16 + lrow;
                a[mi][0] = as32[r * SWRD + kc];
                a[mi][1] = as32[(r + 8) * SWRD + kc];
                a[mi][2] = as32[r * SWRD + kc + 4];
                a[mi][3] = as32[(r + 8) * SWRD + kc + 4];
            }
            #pragma unroll
            for (int nj = 0; nj < 4; nj++) {
                const int n = wn * 32 + nj * 8 + lrow;
                b[nj][0] = bs32[n * SWRD + kc];
                b[nj][1] = bs32[n * SWRD + kc + 4];
            }
            #pragma unroll
            for (int mi = 0; mi < 2; mi++)
                #pragma unroll
                for (int nj = 0; nj < 4; nj++)
                    asm volatile(
                        "mma.sync.aligned.m16n8k8.row.col.f32.tf32.tf32.f32 "
                        "{%0,%1,%2,%3}, {%4,%5,%6,%7}, {%8,%9}, {%0,%1,%2,%3};"
                        : "+f"(c[mi][nj][0]), "+f"(c[mi][nj][1]),
                          "+f"(c[mi][nj][2]), "+f"(c[mi][nj][3])
                        : "r"(a[mi][0]), "r"(a[mi][1]), "r"(a[mi][2]), "r"(a[mi][3]),
                          "r"(b[nj][0]), "r"(b[nj][1]));
        }
        s = (s + 1 == 3) ? 0 : s + 1;
    }
#undef LOAD_STAGE

    const bool single = (gridDim.z == 1);
    const bool addb = (blockIdx.z == 0);
    #pragma unroll
    for (int mi = 0; mi < 2; mi++) {
        const int row = m0 + wm * 32 + mi * 16 + lrow;
        #pragma unroll
        for (int nj = 0; nj < 4; nj++) {
            const int col = n0 + wn * 32 + nj * 8 + 2 * lcol;
            float b0 = addb ? bias[col] : 0.0f;
            float b1 = addb ? bias[col + 1] : 0.0f;
            if (single) {
                *(float2*)&C[(size_t)row * ldc + col] =
                    make_float2(c[mi][nj][0] + b0, c[mi][nj][1] + b1);
                *(float2*)&C[(size_t)(row + 8) * ldc + col] =
                    make_float2(c[mi][nj][2] + b0, c[mi][nj][3] + b1);
            } else {
                atomicAdd(&C[(size_t)row * ldc + col],           c[mi][nj][0] + b0);
                atomicAdd(&C[(size_t)row * ldc + col + 1],       c[mi][nj][1] + b1);
                atomicAdd(&C[(size_t)(row + 8) * ldc + col],     c[mi][nj][2] + b0);
                atomicAdd(&C[(size_t)(row + 8) * ldc + col + 1], c[mi][nj][3] + b1);
            }
        }
    }
}

// ---------------- transpose with tf32 rounding ----------------
__global__ void transpose_into(const float* __restrict__ src, int K, int N,
                               float* __restrict__ dst, int ldd, int koff)
{
    __shared__ float tile[32][33];
    const int kb = blockIdx.x * 32, nb = blockIdx.y * 32;
    const int tx = threadIdx.x, ty = threadIdx.y;
    #pragma unroll
    for (int i = ty; i < 32; i += 8)
        tile[i][tx] = src[(size_t)(kb + i) * N + nb + tx];
    __syncthreads();
    #pragma unroll
    for (int i = ty; i < 32; i += 8)
        dst[(size_t)(nb + i) * ldd + koff + kb + tx] = f2tf32f(tile[tx][i]);
}

__global__ void zero_region(float* __restrict__ dst, int ldd, int r0, int c0, int cols)
{
    dst[(size_t)(r0 + blockIdx.x) * ldd + c0 + threadIdx.x * 4 + 0] = 0.0f;
    dst[(size_t)(r0 + blockIdx.x) * ldd + c0 + threadIdx.x * 4 + 1] = 0.0f;
    dst[(size_t)(r0 + blockIdx.x) * ldd + c0 + threadIdx.x * 4 + 2] = 0.0f;
    dst[(size_t)(r0 + blockIdx.x) * ldd + c0 + threadIdx.x * 4 + 3] = 0.0f;
}

__global__ void cvt_eh(const float* __restrict__ src)
{
    size_t i = (size_t)blockIdx.x * blockDim.x + threadIdx.x;
    float4 v = *(const float4*)(src + i * 4);
    v.x = f2tf32f(v.x); v.y = f2tf32f(v.y); v.z = f2tf32f(v.z); v.w = f2tf32f(v.w);
    *(float4*)(g_ehtf + i * 4) = v;
}

__global__ void gbias_kernel(const float* __restrict__ b_ih1, const float* __restrict__ b_hh1,
                             const float* __restrict__ b_ih2, const float* __restrict__ b_hh2,
                             const float* __restrict__ lt_b)
{
    int i = blockIdx.x * blockDim.x + threadIdx.x;
    if (i < 4 * HDz) {
        g_gb1[i] = b_ih1[i] + b_hh1[i];
        g_gb2c[i] = b_ih2[i] + b_hh2[i];
    }
    if (i < HDz) g_gb2c[4 * HDz + i] = lt_b[i];
}

// ---------------- init state ----------------
__global__ void init_state(const float* __restrict__ h1_0, const float* __restrict__ c1_0,
                           const float* __restrict__ h2_0, const float* __restrict__ c2_0)
{
    int idx = blockIdx.x * blockDim.x + threadIdx.x;
    if (idx >= Bz * HDz) return;
    int b = idx >> 10, j = idx & (HDz - 1);
    g_c1[idx] = c1_0[idx];
    g_c2[idx] = c2_0[idx];
    g_abuf1[(size_t)b * K1z + 1536 + j] = f2tf32f(h1_0[idx]);
    g_abuf2[(size_t)b * K2z + 1024 + j] = f2tf32f(h2_0[idx]);
    g_hprev[idx] = f2tf32f(1.0f / (float)HEz);
    #pragma unroll
    for (int gi = 0; gi < 4; gi++)
        g_gates1[(size_t)b * 4 * HDz + gi * HDz + j] = 0.0f;
    if (idx < Bz * APz) g_q[idx] = 0.0f;
}

// ---------------- attention: logits (+ x_t copy) ----------------
__global__ __launch_bounds__(256) void attn_e(
    const int* __restrict__ enc_masks,
    const float* __restrict__ corr_w, const float* __restrict__ corr_b,
    const float* __restrict__ captions, int t)
{
    __shared__ __align__(16) float qv[APz];
    __shared__ __align__(16) float cw[APz];
    const int b = blockIdx.x, yc = blockIdx.y;
    const int tid = threadIdx.x, lane = tid & 31, warp = tid >> 5;

    for (int i = tid; i < APz; i += 256) { qv[i] = g_q[b * APz + i]; cw[i] = corr_w[i]; }
    if (tid < 128) {
        int ci = yc * 128 + tid;
        g_abuf1[(size_t)b * K1z + ci] = f2tf32f(captions[((size_t)t * Bz + b) * Ez + ci]);
    }
    __syncthreads();

    const float cb = corr_b[0];
    const float4* qv4 = (const float4*)qv;
    const float4* cw4 = (const float4*)cw;

    for (int l = yc * 32 + warp; l < yc * 32 + 32; l += 8) {
        const float4* ep = (const float4*)(g_enc_proj + ((size_t)(b * Lz + l)) * APz);
        float acc = 0.0f;
        #pragma unroll
        for (int i = 0; i < 4; i++) {
            int g = lane + 32 * i;
            float4 v = ep[g], q4 = qv4[g], w4 = cw4[g];
            acc += fast_tanh(v.x + q4.x) * w4.x;
            acc += fast_tanh(v.y + q4.y) * w4.y;
            acc += fast_tanh(v.z + q4.z) * w4.z;
            acc += fast_tanh(v.w + q4.w) * w4.w;
        }
        #pragma unroll
        for (int off = 16; off; off >>= 1) acc += __shfl_xor_sync(0xffffffffu, acc, off);
        if (lane == 0) {
            float v = acc + cb;
            if (enc_masks[b * Lz + l]) v = -INFINITY;
            g_e[b * Lz + l] = v;
        }
    }
}

// ---------------- attention: softmax + weighted sum ----------------
__global__ __launch_bounds__(256) void attn_at(const float* __restrict__ enc_hiddens)
{
    __shared__ float al[Lz];
    const int b = blockIdx.x, hc = blockIdx.y;
    const int tid = threadIdx.x;

    if (tid < Lz) al[tid] = g_e[b * Lz + tid];
    __syncthreads();
    if (tid < 32) {
        float m = -INFINITY;
        #pragma unroll
        for (int i = 0; i < 4; i++) m = fmaxf(m, al[tid + 32 * i]);
        #pragma unroll
        for (int off = 16; off; off >>= 1) m = fmaxf(m, __shfl_xor_sync(0xffffffffu, m, off));
        float ex[4], s = 0.0f;
        #pragma unroll
        for (int i = 0; i < 4; i++) { ex[i] = __expf(al[tid + 32 * i] - m); s += ex[i]; }
        #pragma unroll
        for (int off = 16; off; off >>= 1) s += __shfl_xor_sync(0xffffffffu, s, off);
        float inv = 1.0f / s;
        #pragma unroll
        for (int i = 0; i < 4; i++) al[tid + 32 * i] = ex[i] * inv;
    }
    __syncthreads();

    const int h = hc * 256 + tid;
    const float* eh = enc_hiddens + (size_t)b * Lz * HEz + h;
    float acc = 0.0f;
    #pragma unroll 8
    for (int l = 0; l < Lz; l++) acc += al[l] * eh[(size_t)l * HEz];
    g_abuf1[(size_t)b * K1z + Ez + h] = f2tf32f(acc);
}

// ---------------- LSTM pointwise, layer 1 (+ zero g2c) ----------------
__global__ __launch_bounds__(256) void lstm_point1()
{
    int idx = blockIdx.x * blockDim.x + threadIdx.x;
    if (idx >= Bz * HDz) return;
    int b = idx >> 10, j = idx & (HDz - 1);
    const float* g = g_gates1 + (size_t)b * 4 * HDz;
    float ig = sigmoidf_(g[j]);
    float fg = sigmoidf_(g[HDz + j]);
    float gg = tanhf(g[2 * HDz + j]);
    float og = sigmoidf_(g[3 * HDz + j]);
    float cn = fg * g_c1[idx] + ig * gg;
    float hn = og * tanhf(cn);
    g_c1[idx] = cn;
    float hn_t = f2tf32f(hn);
    g_abuf2[(size_t)b * K2z + j] = hn_t;
    g_abuf1[(size_t)b * K1z + 1536 + j] = hn_t;
    #pragma unroll
    for (int gi = 0; gi < 5; gi++)
        g_g2c[(size_t)b * N2z + gi * HDz + j] = 0.0f;
}

// ---------------- LSTM pointwise, layer 2 (+ tanh out + zero gates1/q) ----------
__global__ __launch_bounds__(256) void lstm_point2(float* __restrict__ out)
{
    int idx = blockIdx.x * blockDim.x + threadIdx.x;
    if (idx >= Bz * HDz) return;
    int b = idx >> 10, j = idx & (HDz - 1);
    const float* g = g_g2c + (size_t)b * N2z;
    float ig = sigmoidf_(g[j]);
    float fg = sigmoidf_(g[HDz + j]);
    float gg = tanhf(g[2 * HDz + j]);
    float og = sigmoidf_(g[3 * HDz + j]);
    float cn = fg * g_c2[idx] + ig * gg;
    float hn = og * tanhf(cn);
    g_c2[idx] = cn;
    float hn_t = f2tf32f(hn);
    g_abuf2[(size_t)b * K2z + 1024 + j] = hn_t;
    g_hprev[idx] = hn_t;
    out[idx] = tanhf(g[4 * HDz + j]);
    #pragma unroll
    for (int gi = 0; gi < 4; gi++)
        g_gates1[(size_t)b * 4 * HDz + gi * HDz + j] = 0.0f;
    if (idx < Bz * APz) g_q[idx] = 0.0f;
}

// ---------------- host launcher ----------------
extern "C" void kernel_launch(void* const* d_in, const int* in_sizes, int n_in,
                              void* d_out, int out_size)
{
    const float* enc_hiddens = (const float*)d_in[0];
    const int*   enc_masks   = (const int*)  d_in[1];
    const float* h1_0 = (const float*)d_in[2];
    const float* c1_0 = (const float*)d_in[3];
    const float* h2_0 = (const float*)d_in[4];
    const float* c2_0 = (const float*)d_in[5];
    const float* captions = (const float*)d_in[6];
    const float* att_W = (const float*)d_in[7];
    const float* att_b = (const float*)d_in[8];
    const float* dhp_W = (const float*)d_in[9];
    const float* dhp_b = (const float*)d_in[10];
    const float* corr_w = (const float*)d_in[11];
    const float* corr_b = (const float*)d_in[12];
    const float* lt_W = (const float*)d_in[13];
    const float* lt_b = (const float*)d_in[14];
    const float* W_ih1 = (const float*)d_in[15];
    const float* W_hh1 = (const float*)d_in[16];
    const float* b_ih1 = (const float*)d_in[17];
    const float* b_hh1 = (const float*)d_in[18];
    const float* W_ih2 = (const float*)d_in[19];
    const float* W_hh2 = (const float*)d_in[20];
    const float* b_ih2 = (const float*)d_in[21];
    const float* b_hh2 = (const float*)d_in[22];
    float* out = (float*)d_out;

    static bool inited = false;
    static float *p_enc_proj, *p_ehtf, *p_a1, *p_a2, *p_g1, *p_g2c, *p_q, *p_hprev;
    static float *p_W1t, *p_W2c, *p_dhpWt, *p_attWt, *p_gb1, *p_gb2c;
    if (!inited) {
        cudaGetSymbolAddress((void**)&p_enc_proj, g_enc_proj);
        cudaGetSymbolAddress((void**)&p_ehtf,  g_ehtf);
        cudaGetSymbolAddress((void**)&p_a1,    g_abuf1);
        cudaGetSymbolAddress((void**)&p_a2,    g_abuf2);
        cudaGetSymbolAddress((void**)&p_g1,    g_gates1);
        cudaGetSymbolAddress((void**)&p_g2c,   g_g2c);
        cudaGetSymbolAddress((void**)&p_q,     g_q);
        cudaGetSymbolAddress((void**)&p_hprev, g_hprev);
        cudaGetSymbolAddress((void**)&p_W1t,   g_W1t);
        cudaGetSymbolAddress((void**)&p_W2c,   g_W2c);
        cudaGetSymbolAddress((void**)&p_dhpWt, g_dhpWt);
        cudaGetSymbolAddress((void**)&p_attWt, g_attWt);
        cudaGetSymbolAddress((void**)&p_gb1,   g_gb1);
        cudaGetSymbolAddress((void**)&p_gb2c,  g_gb2c);
        cudaFuncSetAttribute(gemm_mma, cudaFuncAttributeMaxDynamicSharedMemorySize,
                             3 * STGW * 4);
        inited = true;
    }
    const int GSM = 3 * STGW * 4;   // 82944 B
    dim3 tb(32, 8);

    init_state<<<(Bz * HDz + 255) / 256, 256>>>(h1_0, c1_0, h2_0, c2_0);

    // one-time: tf32-rounded weights (K-major [N,K]) + enc_hiddens copy
    transpose_into<<<dim3(HEz / 32, APz / 32), tb>>>(att_W, HEz, APz, p_attWt, HEz, 0);
    transpose_into<<<dim3(HDz / 32, APz / 32), tb>>>(dhp_W, HDz, APz, p_dhpWt, HDz, 0);
    transpose_into<<<dim3(1536 / 32, 4 * HDz / 32), tb>>>(W_ih1, 1536, 4 * HDz, p_W1t, K1z, 0);
    transpose_into<<<dim3(HDz / 32, 4 * HDz / 32), tb>>>(W_hh1, HDz, 4 * HDz, p_W1t, K1z, 1536);
    transpose_into<<<dim3(HDz / 32, 4 * HDz / 32), tb>>>(W_ih2, HDz, 4 * HDz, p_W2c, K2z, 0);
    transpose_into<<<dim3(HDz / 32, 4 * HDz / 32), tb>>>(W_hh2, HDz, 4 * HDz, p_W2c, K2z, 1024);
    transpose_into<<<dim3(HDz / 32, HDz / 32), tb>>>(lt_W, HDz, HDz,
                                                     p_W2c + (size_t)4 * HDz * K2z, K2z, 0);
    zero_region<<<HDz, 256>>>(p_W2c, K2z, 4 * HDz, 1024, 1024);
    cvt_eh<<<(Bz * Lz * HEz / 4 + 255) / 256, 256>>>(enc_hiddens);
    gbias_kernel<<<(4 * HDz + 255) / 256, 256>>>(b_ih1, b_hh1, b_ih2, b_hh2, lt_b);

    // enc_proj = enc_hiddens @ att_W + att_b  (direct store)
    gemm_mma<<<dim3(APz / BN, Bz * Lz / BMt, 1), 256, GSM>>>(
        p_ehtf, HEz, p_attWt, HEz, p_enc_proj, APz, HEz, att_b);

    for (int t = 0; t < Tz; t++) {
        // q += hprev @ dhp_W (+dhp_b)   K=1024, z=16 -> 128 blocks
        gemm_mma<<<dim3(APz / BN, Bz / BMt, 16), 256, GSM>>>(
            p_hprev, HDz, p_dhpWt, HDz, p_q, APz, 64, dhp_b);

        attn_e<<<dim3(Bz, 4), 256>>>(enc_masks, corr_w, corr_b, captions, t);
        attn_at<<<dim3(Bz, HEz / 256), 256>>>(enc_hiddens);

        // gates1 += [x|a|h1] @ W1t^T (+gb1)   K=2560, z=5 -> 320 blocks
        gemm_mma<<<dim3(4 * HDz / BN, Bz / BMt, 5), 256, GSM>>>(
            p_a1, K1z, p_W1t, K1z, p_g1, 4 * HDz, 512, p_gb1);
        lstm_point1<<<(Bz * HDz + 255) / 256, 256>>>();

        // [gates2 | outsc] += [h1|h2] @ W2c^T (+gb2c)   K=2048, z=4 -> 320 blocks
        gemm_mma<<<dim3(N2z / BN, Bz / BMt, 4), 256, GSM>>>(
            p_a2, K2z, p_W2c, K2z, p_g2c, N2z, 512, p_gb2c);

        lstm_point2<<<(Bz * HDz + 255) / 256, 256>>>(out + (size_t)t * Bz * HDz);
    }
    (void)in_sizes; (void)n_in; (void)out_size;
}

// round 7
// speedup vs baseline: 7.7577x; 1.6087x over previous
#include <cuda_runtime.h>
#include <cuda_fp16.h>
#include <math.h>
#include <cstdint>

#define Bz 128
#define Lz 128
#define HEz 1024
#define HDz 1024
#define Ez 512
#define APz 512
#define Tz 64
#define K1z 2560        // [x_t | a_t | h1_prev]
#define K2z 2048        // [h1 | h2]
#define N2z 5120        // gates2 (4096) + out-proj (1024)

// ---------------- device scratch ----------------
__device__ __align__(128) __half g_enc_proj[Bz * Lz * APz];   // fp16, 16 MB
__device__ __align__(128) __half g_ehtf[Bz * Lz * HEz];       // fp16 enc_hiddens, 32 MB
__device__ __align__(128) float  g_q[Bz * APz];
__device__ __align__(128) __half g_abuf1[Bz * K1z];
__device__ __align__(128) __half g_abuf2[Bz * K2z];
__device__ __align__(128) float  g_gates1[Bz * 4 * HDz];
__device__ __align__(128) float  g_g2c[Bz * N2z];             // gates2 | outsc
__device__ __align__(128) float  g_c1[Bz * HDz];
__device__ __align__(128) float  g_c2[Bz * HDz];
__device__ __align__(128) __half g_hprev[Bz * HDz];
// pre-transposed fp16 K-major weights [N, K]
__device__ __align__(128) __half g_W1t[4 * HDz * K1z];
__device__ __align__(128) __half g_W2c[N2z * K2z];
__device__ __align__(128) __half g_dhpWt[APz * HDz];
__device__ __align__(128) __half g_attWt[APz * HEz];
__device__ __align__(128) float  g_gb1[4 * HDz];
__device__ __align__(128) float  g_gb2c[N2z];

__device__ __forceinline__ float fast_tanh(float x) {
    float y; asm("tanh.approx.f32 %0, %1;" : "=f"(y) : "f"(x)); return y;
}
__device__ __forceinline__ float sigmoidf_(float x) { return 1.0f / (1.0f + expf(-x)); }
__device__ __forceinline__ uint32_t smem_u32(const void* p) {
    uint32_t a;
    asm("{ .reg .u64 t; cvta.to.shared.u64 t, %1; cvt.u32.u64 %0, t; }" : "=r"(a) : "l"(p));
    return a;
}
#define CP16(dst, src) \
    asm volatile("cp.async.cg.shared.global [%0], [%1], 16;" :: "r"(dst), "l"(src))

// ---------------- 3-stage pipelined HMMA fp16 GEMM (m16n8k16) ----------------
// C[m0:+64, n0:+128] (+)= A[m0:, kslice](lda) @ Bt[n0:, kslice]^T  (fp32 accum)
// A, Bt fp16; lda/ldb in halves. grid (N/128, M/64, Z), chunk*Z == K, chunk%64==0.
// Z==1: direct store (+bias); flags&1 -> fp16 output. Z>1: atomicAdd; z==0 adds bias.
#define BMt 64
#define BN 128
#define BKh 64                      // halves per K-chunk
#define SWH 72                      // row pitch in halves (144 B)
#define STGH ((BMt + BN) * SWH)     // halves per stage

__global__ __launch_bounds__(256, 2) void gemm_mma(
    const __half* __restrict__ A, int lda,
    const __half* __restrict__ Bt, int ldb,
    float* __restrict__ C, int ldc,
    int chunk, const float* __restrict__ bias, int flags)
{
    extern __shared__ __half smh[];
    const int tid = threadIdx.x;
    const int wid = tid >> 5, lane = tid & 31;
    const int wm = wid & 1, wn = wid >> 1;
    const int lrow = lane >> 2, lcol = lane & 3;
    const int n0 = blockIdx.x * BN;
    const int m0 = blockIdx.y * BMt;
    const int kbeg = blockIdx.z * chunk;
    const int NC = chunk / BKh;

    float c[2][4][4];
    #pragma unroll
    for (int i = 0; i < 2; i++)
        #pragma unroll
        for (int j = 0; j < 4; j++)
            #pragma unroll
            for (int r = 0; r < 4; r++) c[i][j][r] = 0.0f;

    const uint32_t sbase = smem_u32(smh);
    const __half* Abase = A + (size_t)m0 * lda + kbeg;
    const __half* Bbase = Bt + (size_t)n0 * ldb + kbeg;

    // A tile: 64 rows x 8 16B-chunks (2/thread). B tile: 128 rows x 8 (4/thread).
    const int ar0 = (tid + 0)   >> 3, ao0 = (tid + 0)   & 7;
    const int ar1 = (tid + 256) >> 3, ao1 = (tid + 256) & 7;

#define LOAD_STAGE(ck, st) do {                                                   \
        uint32_t sb = sbase + (uint32_t)(st) * STGH * 2;                          \
        const __half* Ag = Abase + (size_t)(ck) * BKh;                            \
        const __half* Bg = Bbase + (size_t)(ck) * BKh;                            \
        CP16(sb + ar0 * 144 + ao0 * 16, Ag + (size_t)ar0 * lda + ao0 * 8);        \
        CP16(sb + ar1 * 144 + ao1 * 16, Ag + (size_t)ar1 * lda + ao1 * 8);        \
        _Pragma("unroll")                                                         \
        for (int j = 0; j < 4; j++) {                                             \
            int i = tid + j * 256;                                                \
            int row = i >> 3, off = i & 7;                                        \
            CP16(sb + (BMt + row) * 144 + off * 16,                               \
                 Bg + (size_t)row * ldb + off * 8);                               \
        }                                                                         \
    } while (0)

    LOAD_STAGE(0, 0);
    asm volatile("cp.async.commit_group;" ::: "memory");
    if (NC > 1) {
        LOAD_STAGE(1, 1);
        asm volatile("cp.async.commit_group;" ::: "memory");
    }

    int s = 0;
    for (int cc = 0; cc < NC; cc++) {
        if (cc + 1 < NC) { asm volatile("cp.async.wait_group 1;" ::: "memory"); }
        else             { asm volatile("cp.async.wait_group 0;" ::: "memory"); }
        __syncthreads();
        if (cc + 2 < NC) {
            int st = s + 2 >= 3 ? s - 1 : s + 2;
            LOAD_STAGE(cc + 2, st);
            asm volatile("cp.async.commit_group;" ::: "memory");
        }

        const __half* as16 = smh + (size_t)s * STGH;
        const __half* bs16 = as16 + BMt * SWH;

        #pragma unroll
        for (int ks = 0; ks < 4; ks++) {
            uint32_t a[2][4], b[4][2];
            const int kc = ks * 16 + 2 * lcol;
            #pragma unroll
            for (int mi = 0; mi < 2; mi++) {
                const int r = wm * 32 + mi * 16 + lrow;
                a[mi][0] = *(const uint32_t*)(as16 + r * SWH + kc);
                a[mi][1] = *(const uint32_t*)(as16 + (r + 8) * SWH + kc);
                a[mi][2] = *(const uint32_t*)(as16 + r * SWH + kc + 8);
                a[mi][3] = *(const uint32_t*)(as16 + (r + 8) * SWH + kc + 8);
            }
            #pragma unroll
            for (int nj = 0; nj < 4; nj++) {
                const int n = wn * 32 + nj * 8 + lrow;
                b[nj][0] = *(const uint32_t*)(bs16 + n * SWH + kc);
                b[nj][1] = *(const uint32_t*)(bs16 + n * SWH + kc + 8);
            }
            #pragma unroll
            for (int mi = 0; mi < 2; mi++)
                #pragma unroll
                for (int nj = 0; nj < 4; nj++)
                    asm volatile(
                        "mma.sync.aligned.m16n8k16.row.col.f32.f16.f16.f32 "
                        "{%0,%1,%2,%3}, {%4,%5,%6,%7}, {%8,%9}, {%0,%1,%2,%3};"
                        : "+f"(c[mi][nj][0]), "+f"(c[mi][nj][1]),
                          "+f"(c[mi][nj][2]), "+f"(c[mi][nj][3])
                        : "r"(a[mi][0]), "r"(a[mi][1]), "r"(a[mi][2]), "r"(a[mi][3]),
                          "r"(b[nj][0]), "r"(b[nj][1]));
        }
        s = (s + 1 == 3) ? 0 : s + 1;
    }
#undef LOAD_STAGE

    const bool single = (gridDim.z == 1);
    const bool addb = (blockIdx.z == 0);
    const bool h16 = (flags & 1);
    #pragma unroll
    for (int mi = 0; mi < 2; mi++) {
        const int row = m0 + wm * 32 + mi * 16 + lrow;
        #pragma unroll
        for (int nj = 0; nj < 4; nj++) {
            const int col = n0 + wn * 32 + nj * 8 + 2 * lcol;
            float b0 = addb ? bias[col] : 0.0f;
            float b1 = addb ? bias[col + 1] : 0.0f;
            if (single) {
                if (h16) {
                    __half* Ch = (__half*)C;
                    *(__half2*)(Ch + (size_t)row * ldc + col) =
                        __floats2half2_rn(c[mi][nj][0] + b0, c[mi][nj][1] + b1);
                    *(__half2*)(Ch + (size_t)(row + 8) * ldc + col) =
                        __floats2half2_rn(c[mi][nj][2] + b0, c[mi][nj][3] + b1);
                } else {
                    *(float2*)&C[(size_t)row * ldc + col] =
                        make_float2(c[mi][nj][0] + b0, c[mi][nj][1] + b1);
                    *(float2*)&C[(size_t)(row + 8) * ldc + col] =
                        make_float2(c[mi][nj][2] + b0, c[mi][nj][3] + b1);
                }
            } else {
                atomicAdd(&C[(size_t)row * ldc + col],           c[mi][nj][0] + b0);
                atomicAdd(&C[(size_t)row * ldc + col + 1],       c[mi][nj][1] + b1);
                atomicAdd(&C[(size_t)(row + 8) * ldc + col],     c[mi][nj][2] + b0);
                atomicAdd(&C[(size_t)(row + 8) * ldc + col + 1], c[mi][nj][3] + b1);
            }
        }
    }
}

// ---------------- transpose fp32 -> fp16 K-major ----------------
__global__ void transpose_into(const float* __restrict__ src, int K, int N,
                               __half* __restrict__ dst, int ldd, int koff)
{
    __shared__ float tile[32][33];
    const int kb = blockIdx.x * 32, nb = blockIdx.y * 32;
    const int tx = threadIdx.x, ty = threadIdx.y;
    #pragma unroll
    for (int i = ty; i < 32; i += 8)
        tile[i][tx] = src[(size_t)(kb + i) * N + nb + tx];
    __syncthreads();
    #pragma unroll
    for (int i = ty; i < 32; i += 8)
        dst[(size_t)(nb + i) * ldd + koff + kb + tx] = __float2half_rn(tile[tx][i]);
}

__global__ void zero_region_h(__half* __restrict__ dst, int ldd, int r0, int c0)
{
    __half z = __float2half(0.0f);
    #pragma unroll
    for (int j = 0; j < 4; j++)
        dst[(size_t)(r0 + blockIdx.x) * ldd + c0 + threadIdx.x * 4 + j] = z;
}

__global__ void cvt_eh(const float* __restrict__ src)
{
    size_t i = (size_t)blockIdx.x * blockDim.x + threadIdx.x;
    float4 v = *(const float4*)(src + i * 4);
    __half2* d = (__half2*)g_ehtf;
    d[2 * i] = __floats2half2_rn(v.x, v.y);
    d[2 * i + 1] = __floats2half2_rn(v.z, v.w);
}

__global__ void gbias_kernel(const float* __restrict__ b_ih1, const float* __restrict__ b_hh1,
                             const float* __restrict__ b_ih2, const float* __restrict__ b_hh2,
                             const float* __restrict__ lt_b)
{
    int i = blockIdx.x * blockDim.x + threadIdx.x;
    if (i < 4 * HDz) {
        g_gb1[i] = b_ih1[i] + b_hh1[i];
        g_gb2c[i] = b_ih2[i] + b_hh2[i];
    }
    if (i < HDz) g_gb2c[4 * HDz + i] = lt_b[i];
}

// ---------------- init state ----------------
__global__ void init_state(const float* __restrict__ h1_0, const float* __restrict__ c1_0,
                           const float* __restrict__ h2_0, const float* __restrict__ c2_0)
{
    int idx = blockIdx.x * blockDim.x + threadIdx.x;
    if (idx >= Bz * HDz) return;
    int b = idx >> 10, j = idx & (HDz - 1);
    g_c1[idx] = c1_0[idx];
    g_c2[idx] = c2_0[idx];
    g_abuf1[(size_t)b * K1z + 1536 + j] = __float2half_rn(h1_0[idx]);
    g_abuf2[(size_t)b * K2z + 1024 + j] = __float2half_rn(h2_0[idx]);
    g_hprev[idx] = __float2half_rn(1.0f / (float)HEz);
    #pragma unroll
    for (int gi = 0; gi < 4; gi++)
        g_gates1[(size_t)b * 4 * HDz + gi * HDz + j] = 0.0f;
    if (idx < Bz * APz) g_q[idx] = 0.0f;
}

// ---------------- fused attention: logits + softmax + weighted sum + x_t copy ---
// one block per b, 512 threads
__global__ __launch_bounds__(512) void attn_fused(
    const int* __restrict__ enc_masks,
    const float* __restrict__ corr_w, const float* __restrict__ corr_b,
    const float* __restrict__ captions, int t)
{
    __shared__ __align__(16) float qv[APz];
    __shared__ __align__(16) float cw[APz];
    __shared__ float al[Lz];
    const int b = blockIdx.x;
    const int tid = threadIdx.x, lane = tid & 31, warp = tid >> 5;

    if (tid < APz) {
        qv[tid] = g_q[b * APz + tid];
        cw[tid] = corr_w[tid];
        // x_t copy -> abuf1[:, 0:512]
        g_abuf1[(size_t)b * K1z + tid] = __float2half_rn(captions[((size_t)t * Bz + b) * Ez + tid]);
    }
    __syncthreads();

    const float cb = corr_b[0];
    // e[l]: 16 warps x 8 l each; lane handles 16 aps (2 x uint4 = 16 halves)
    #pragma unroll
    for (int li = 0; li < 8; li++) {
        const int l = warp + li * 16;
        const uint4* ep = (const uint4*)(g_enc_proj + ((size_t)(b * Lz + l)) * APz);
        float acc = 0.0f;
        #pragma unroll
        for (int u = 0; u < 2; u++) {
            uint4 pk = ep[lane * 2 + u];
            const __half2* h2 = (const __half2*)&pk;
            const int ap0 = lane * 16 + u * 8;
            #pragma unroll
            for (int p = 0; p < 4; p++) {
                float2 v = __half22float2(h2[p]);
                acc += fast_tanh(v.x + qv[ap0 + 2 * p]) * cw[ap0 + 2 * p];
                acc += fast_tanh(v.y + qv[ap0 + 2 * p + 1]) * cw[ap0 + 2 * p + 1];
            }
        }
        #pragma unroll
        for (int off = 16; off; off >>= 1) acc += __shfl_xor_sync(0xffffffffu, acc, off);
        if (lane == 0) {
            float v = acc + cb;
            if (enc_masks[b * Lz + l]) v = -INFINITY;
            al[l] = v;
        }
    }
    __syncthreads();

    // softmax over L=128 (warp 0)
    if (tid < 32) {
        float m = -INFINITY;
        #pragma unroll
        for (int i = 0; i < 4; i++) m = fmaxf(m, al[tid + 32 * i]);
        #pragma unroll
        for (int off = 16; off; off >>= 1) m = fmaxf(m, __shfl_xor_sync(0xffffffffu, m, off));
        float ex[4], s = 0.0f;
        #pragma unroll
        for (int i = 0; i < 4; i++) { ex[i] = __expf(al[tid + 32 * i] - m); s += ex[i]; }
        #pragma unroll
        for (int off = 16; off; off >>= 1) s += __shfl_xor_sync(0xffffffffu, s, off);
        float inv = 1.0f / s;
        #pragma unroll
        for (int i = 0; i < 4; i++) al[tid + 32 * i] = ex[i] * inv;
    }
    __syncthreads();

    // a_t: thread handles half2 (h = 2*tid, 2*tid+1)
    const __half2* eh2 = (const __half2*)(g_ehtf + (size_t)b * Lz * HEz);
    float2 acc2 = make_float2(0.0f, 0.0f);
    #pragma unroll 8
    for (int l = 0; l < Lz; l++) {
        float2 v = __half22float2(eh2[(size_t)l * (HEz / 2) + tid]);
        float a = al[l];
        acc2.x += a * v.x;
        acc2.y += a * v.y;
    }
    *(__half2*)(g_abuf1 + (size_t)b * K1z + Ez + 2 * tid) = __floats2half2_rn(acc2.x, acc2.y);
}

// ---------------- LSTM pointwise, layer 1 (+ zero g2c) ----------------
__global__ __launch_bounds__(256) void lstm_point1()
{
    int idx = blockIdx.x * blockDim.x + threadIdx.x;
    if (idx >= Bz * HDz) return;
    int b = idx >> 10, j = idx & (HDz - 1);
    const float* g = g_gates1 + (size_t)b * 4 * HDz;
    float ig = sigmoidf_(g[j]);
    float fg = sigmoidf_(g[HDz + j]);
    float gg = tanhf(g[2 * HDz + j]);
    float og = sigmoidf_(g[3 * HDz + j]);
    float cn = fg * g_c1[idx] + ig * gg;
    float hn = og * tanhf(cn);
    g_c1[idx] = cn;
    __half hn_h = __float2half_rn(hn);
    g_abuf2[(size_t)b * K2z + j] = hn_h;
    g_abuf1[(size_t)b * K1z + 1536 + j] = hn_h;
    #pragma unroll
    for (int gi = 0; gi < 5; gi++)
        g_g2c[(size_t)b * N2z + gi * HDz + j] = 0.0f;
}

// ---------------- LSTM pointwise, layer 2 (+ tanh out + zero gates1/q) ----------
__global__ __launch_bounds__(256) void lstm_point2(float* __restrict__ out)
{
    int idx = blockIdx.x * blockDim.x + threadIdx.x;
    if (idx >= Bz * HDz) return;
    int b = idx >> 10, j = idx & (HDz - 1);
    const float* g = g_g2c + (size_t)b * N2z;
    float ig = sigmoidf_(g[j]);
    float fg = sigmoidf_(g[HDz + j]);
    float gg = tanhf(g[2 * HDz + j]);
    float og = sigmoidf_(g[3 * HDz + j]);
    float cn = fg * g_c2[idx] + ig * gg;
    float hn = og * tanhf(cn);
    g_c2[idx] = cn;
    __half hn_h = __float2half_rn(hn);
    g_abuf2[(size_t)b * K2z + 1024 + j] = hn_h;
    g_hprev[idx] = hn_h;
    out[idx] = tanhf(g[4 * HDz + j]);
    #pragma unroll
    for (int gi = 0; gi < 4; gi++)
        g_gates1[(size_t)b * 4 * HDz + gi * HDz + j] = 0.0f;
    if (idx < Bz * APz) g_q[idx] = 0.0f;
}

// ---------------- host launcher ----------------
extern "C" void kernel_launch(void* const* d_in, const int* in_sizes, int n_in,
                              void* d_out, int out_size)
{
    const float* enc_hiddens = (const float*)d_in[0];
    const int*   enc_masks   = (const int*)  d_in[1];
    const float* h1_0 = (const float*)d_in[2];
    const float* c1_0 = (const float*)d_in[3];
    const float* h2_0 = (const float*)d_in[4];
    const float* c2_0 = (const float*)d_in[5];
    const float* captions = (const float*)d_in[6];
    const float* att_W = (const float*)d_in[7];
    const float* att_b = (const float*)d_in[8];
    const float* dhp_W = (const float*)d_in[9];
    const float* dhp_b = (const float*)d_in[10];
    const float* corr_w = (const float*)d_in[11];
    const float* corr_b = (const float*)d_in[12];
    const float* lt_W = (const float*)d_in[13];
    const float* lt_b = (const float*)d_in[14];
    const float* W_ih1 = (const float*)d_in[15];
    const float* W_hh1 = (const float*)d_in[16];
    const float* b_ih1 = (const float*)d_in[17];
    const float* b_hh1 = (const float*)d_in[18];
    const float* W_ih2 = (const float*)d_in[19];
    const float* W_hh2 = (const float*)d_in[20];
    const float* b_ih2 = (const float*)d_in[21];
    const float* b_hh2 = (const float*)d_in[22];
    float* out = (float*)d_out;

    static bool inited = false;
    static __half *p_enc_proj, *p_ehtf, *p_a1, *p_a2, *p_hprev;
    static __half *p_W1t, *p_W2c, *p_dhpWt, *p_attWt;
    static float *p_g1, *p_g2c, *p_q, *p_gb1, *p_gb2c;
    if (!inited) {
        cudaGetSymbolAddress((void**)&p_enc_proj, g_enc_proj);
        cudaGetSymbolAddress((void**)&p_ehtf,  g_ehtf);
        cudaGetSymbolAddress((void**)&p_a1,    g_abuf1);
        cudaGetSymbolAddress((void**)&p_a2,    g_abuf2);
        cudaGetSymbolAddress((void**)&p_g1,    g_gates1);
        cudaGetSymbolAddress((void**)&p_g2c,   g_g2c);
        cudaGetSymbolAddress((void**)&p_q,     g_q);
        cudaGetSymbolAddress((void**)&p_hprev, g_hprev);
        cudaGetSymbolAddress((void**)&p_W1t,   g_W1t);
        cudaGetSymbolAddress((void**)&p_W2c,   g_W2c);
        cudaGetSymbolAddress((void**)&p_dhpWt, g_dhpWt);
        cudaGetSymbolAddress((void**)&p_attWt, g_attWt);
        cudaGetSymbolAddress((void**)&p_gb1,   g_gb1);
        cudaGetSymbolAddress((void**)&p_gb2c,  g_gb2c);
        cudaFuncSetAttribute(gemm_mma, cudaFuncAttributeMaxDynamicSharedMemorySize,
                             3 * STGH * 2);
        inited = true;
    }
    const int GSM = 3 * STGH * 2;   // 82944 B
    dim3 tb(32, 8);

    init_state<<<(Bz * HDz + 255) / 256, 256>>>(h1_0, c1_0, h2_0, c2_0);

    // one-time: fp16 K-major weights + fp16 enc_hiddens
    transpose_into<<<dim3(HEz / 32, APz / 32), tb>>>(att_W, HEz, APz, p_attWt, HEz, 0);
    transpose_into<<<dim3(HDz / 32, APz / 32), tb>>>(dhp_W, HDz, APz, p_dhpWt, HDz, 0);
    transpose_into<<<dim3(1536 / 32, 4 * HDz / 32), tb>>>(W_ih1, 1536, 4 * HDz, p_W1t, K1z, 0);
    transpose_into<<<dim3(HDz / 32, 4 * HDz / 32), tb>>>(W_hh1, HDz, 4 * HDz, p_W1t, K1z, 1536);
    transpose_into<<<dim3(HDz / 32, 4 * HDz / 32), tb>>>(W_ih2, HDz, 4 * HDz, p_W2c, K2z, 0);
    transpose_into<<<dim3(HDz / 32, 4 * HDz / 32), tb>>>(W_hh2, HDz, 4 * HDz, p_W2c, K2z, 1024);
    transpose_into<<<dim3(HDz / 32, HDz / 32), tb>>>(lt_W, HDz, HDz,
                                                     p_W2c + (size_t)4 * HDz * K2z, K2z, 0);
    zero_region_h<<<HDz, 256>>>(p_W2c, K2z, 4 * HDz, 1024);
    cvt_eh<<<(Bz * Lz * HEz / 4 + 255) / 256, 256>>>(enc_hiddens);
    gbias_kernel<<<(4 * HDz + 255) / 256, 256>>>(b_ih1, b_hh1, b_ih2, b_hh2, lt_b);

    // enc_proj(fp16) = enc_hiddens @ att_W + att_b
    gemm_mma<<<dim3(APz / BN, Bz * Lz / BMt, 1), 256, GSM>>>(
        p_ehtf, HEz, p_attWt, HEz, (float*)p_enc_proj, APz, HEz, att_b, 1);

    for (int t = 0; t < Tz; t++) {
        // q += hprev @ dhp_W (+dhp_b)   K=1024, z=16 -> 128 blocks (NC=1)
        gemm_mma<<<dim3(APz / BN, Bz / BMt, 16), 256, GSM>>>(
            p_hprev, HDz, p_dhpWt, HDz, p_q, APz, 64, dhp_b, 0);

        attn_fused<<<Bz, 512>>>(enc_masks, corr_w, corr_b, captions, t);

        // gates1 += [x|a|h1] @ W1t^T (+gb1)   K=2560, z=5 -> 320 blocks
        gemm_mma<<<dim3(4 * HDz / BN, Bz / BMt, 5), 256, GSM>>>(
            p_a1, K1z, p_W1t, K1z, p_g1, 4 * HDz, 512, p_gb1, 0);
        lstm_point1<<<(Bz * HDz + 255) / 256, 256>>>();

        // [gates2 | outsc] += [h1|h2] @ W2c^T (+gb2c)   K=2048, z=4 -> 320 blocks
        gemm_mma<<<dim3(N2z / BN, Bz / BMt, 4), 256, GSM>>>(
            p_a2, K2z, p_W2c, K2z, p_g2c, N2z, 512, p_gb2c, 0);

        lstm_point2<<<(Bz * HDz + 255) / 256, 256>>>(out + (size_t)t * Bz * HDz);
    }
    (void)in_sizes; (void)n_in; (void)out_size;
}

// round 8
// speedup vs baseline: 8.2108x; 1.0584x over previous
#include <cuda_runtime.h>
#include <cuda_fp16.h>
#include <math.h>
#include <cstdint>

#define Bz 128
#define Lz 128
#define HEz 1024
#define HDz 1024
#define Ez 512
#define APz 512
#define Tz 64
#define K1z 2560        // [x_t | a_t | h1_prev]
#define K2z 2048        // [h1 | h2]
#define N2z 5120        // gates2 (4096) + out-proj (1024)

// ---------------- device scratch ----------------
__device__ __align__(128) __half g_enc_proj[Bz * Lz * APz];
__device__ __align__(128) __half g_ehtf[Bz * Lz * HEz];
__device__ __align__(128) float  g_q[Bz * APz];
__device__ __align__(128) __half g_abuf1[Bz * K1z];
__device__ __align__(128) __half g_abuf2[Bz * K2z];
__device__ __align__(128) float  g_gates1[Bz * 4 * HDz];
__device__ __align__(128) float  g_g2c[Bz * N2z];
__device__ __align__(128) float  g_c1[Bz * HDz];
__device__ __align__(128) float  g_c2[Bz * HDz];
__device__ __align__(128) __half g_hprev[Bz * HDz];
__device__ __align__(128) __half g_W1t[4 * HDz * K1z];
__device__ __align__(128) __half g_W2c[N2z * K2z];
__device__ __align__(128) __half g_dhpWt[APz * HDz];
__device__ __align__(128) __half g_attWt[APz * HEz];
__device__ __align__(128) float  g_gb1[4 * HDz];
__device__ __align__(128) float  g_gb2c[N2z];

__device__ __forceinline__ float fast_tanh(float x) {
    float y; asm("tanh.approx.f32 %0, %1;" : "=f"(y) : "f"(x)); return y;
}
__device__ __forceinline__ float sigmoidf_(float x) { return 1.0f / (1.0f + expf(-x)); }
__device__ __forceinline__ uint32_t smem_u32(const void* p) {
    uint32_t a;
    asm("{ .reg .u64 t; cvta.to.shared.u64 t, %1; cvt.u32.u64 %0, t; }" : "=r"(a) : "l"(p));
    return a;
}
#define CP16(dst, src) \
    asm volatile("cp.async.cg.shared.global [%0], [%1], 16;" :: "r"(dst), "l"(src))
#define LDSM4(d0, d1, d2, d3, addr) \
    asm volatile("ldmatrix.sync.aligned.m8n8.x4.shared.b16 {%0,%1,%2,%3}, [%4];" \
                 : "=r"(d0), "=r"(d1), "=r"(d2), "=r"(d3) : "r"(addr))

// ---------------- 3-stage pipelined HMMA fp16 GEMM (m16n8k16 + ldmatrix) --------
// C[m0:+64, n0:+128] (+)= A[m0:, kslice](lda) @ Bt[n0:, kslice]^T  (fp32 accum)
// grid (N/128, M/64, Z), chunk*Z == K, chunk % 64 == 0.
// Z==1: direct store (+bias); flags&1 -> fp16 output. Z>1: atomicAdd; z==0 adds bias.
#define BMt 64
#define BN 128
#define BKh 64
#define SWH 72
#define STGH ((BMt + BN) * SWH)

__global__ __launch_bounds__(256, 2) void gemm_mma(
    const __half* __restrict__ A, int lda,
    const __half* __restrict__ Bt, int ldb,
    float* __restrict__ C, int ldc,
    int chunk, const float* __restrict__ bias, int flags)
{
    extern __shared__ __half smh[];
    const int tid = threadIdx.x;
    const int wid = tid >> 5, lane = tid & 31;
    const int wm = wid & 1, wn = wid >> 1;
    const int lrow = lane >> 2, lcol = lane & 3;
    const int n0 = blockIdx.x * BN;
    const int m0 = blockIdx.y * BMt;
    const int kbeg = blockIdx.z * chunk;
    const int NC = chunk / BKh;

    float c[2][4][4];
    #pragma unroll
    for (int i = 0; i < 2; i++)
        #pragma unroll
        for (int j = 0; j < 4; j++)
            #pragma unroll
            for (int r = 0; r < 4; r++) c[i][j][r] = 0.0f;

    const uint32_t sbase = smem_u32(smh);
    const __half* Abase = A + (size_t)m0 * lda + kbeg;
    const __half* Bbase = Bt + (size_t)n0 * ldb + kbeg;

    const int ar0 = (tid + 0)   >> 3, ao0 = (tid + 0)   & 7;
    const int ar1 = (tid + 256) >> 3, ao1 = (tid + 256) & 7;

    // ldmatrix per-lane base offsets (bytes within a stage)
    const uint32_t a_off =
        ((uint32_t)((wm * 32 + (lane & 15)) * SWH + ((lane >> 4) << 3))) * 2;
    const uint32_t b_off =
        ((uint32_t)((BMt + wn * 32 + (lane & 7) + (((lane >> 4) & 1) << 3)) * SWH
                    + (((lane >> 3) & 1) << 3))) * 2;

#define LOAD_STAGE(ck, st) do {                                                   \
        uint32_t sb = sbase + (uint32_t)(st) * STGH * 2;                          \
        const __half* Ag = Abase + (size_t)(ck) * BKh;                            \
        const __half* Bg = Bbase + (size_t)(ck) * BKh;                            \
        CP16(sb + ar0 * 144 + ao0 * 16, Ag + (size_t)ar0 * lda + ao0 * 8);        \
        CP16(sb + ar1 * 144 + ao1 * 16, Ag + (size_t)ar1 * lda + ao1 * 8);        \
        _Pragma("unroll")                                                         \
        for (int j = 0; j < 4; j++) {                                             \
            int i = tid + j * 256;                                                \
            int row = i >> 3, off = i & 7;                                        \
            CP16(sb + (BMt + row) * 144 + off * 16,                               \
                 Bg + (size_t)row * ldb + off * 8);                               \
        }                                                                         \
    } while (0)

    LOAD_STAGE(0, 0);
    asm volatile("cp.async.commit_group;" ::: "memory");
    if (NC > 1) {
        LOAD_STAGE(1, 1);
        asm volatile("cp.async.commit_group;" ::: "memory");
    }

    int s = 0;
    for (int cc = 0; cc < NC; cc++) {
        if (cc + 1 < NC) { asm volatile("cp.async.wait_group 1;" ::: "memory"); }
        else             { asm volatile("cp.async.wait_group 0;" ::: "memory"); }
        __syncthreads();
        if (cc + 2 < NC) {
            int st = s + 2 >= 3 ? s - 1 : s + 2;
            LOAD_STAGE(cc + 2, st);
            asm volatile("cp.async.commit_group;" ::: "memory");
        }

        const uint32_t stg = sbase + (uint32_t)s * STGH * 2;
        const uint32_t aad = stg + a_off;
        const uint32_t bad = stg + b_off;

        #pragma unroll
        for (int ks = 0; ks < 4; ks++) {
            uint32_t a[2][4], b[4][2];
            const uint32_t kso = ks * 32;   // 16 halves
            LDSM4(a[0][0], a[0][1], a[0][2], a[0][3], aad + kso);
            LDSM4(a[1][0], a[1][1], a[1][2], a[1][3], aad + 16 * SWH * 2 + kso);
            LDSM4(b[0][0], b[0][1], b[1][0], b[1][1], bad + kso);
            LDSM4(b[2][0], b[2][1], b[3][0], b[3][1], bad + 16 * SWH * 2 + kso);
            #pragma unroll
            for (int mi = 0; mi < 2; mi++)
                #pragma unroll
                for (int nj = 0; nj < 4; nj++)
                    asm volatile(
                        "mma.sync.aligned.m16n8k16.row.col.f32.f16.f16.f32 "
                        "{%0,%1,%2,%3}, {%4,%5,%6,%7}, {%8,%9}, {%0,%1,%2,%3};"
                        : "+f"(c[mi][nj][0]), "+f"(c[mi][nj][1]),
                          "+f"(c[mi][nj][2]), "+f"(c[mi][nj][3])
                        : "r"(a[mi][0]), "r"(a[mi][1]), "r"(a[mi][2]), "r"(a[mi][3]),
                          "r"(b[nj][0]), "r"(b[nj][1]));
        }
        s = (s + 1 == 3) ? 0 : s + 1;
    }
#undef LOAD_STAGE

    const bool single = (gridDim.z == 1);
    const bool addb = (blockIdx.z == 0);
    const bool h16 = (flags & 1);
    #pragma unroll
    for (int mi = 0; mi < 2; mi++) {
        const int row = m0 + wm * 32 + mi * 16 + lrow;
        #pragma unroll
        for (int nj = 0; nj < 4; nj++) {
            const int col = n0 + wn * 32 + nj * 8 + 2 * lcol;
            float b0 = addb ? bias[col] : 0.0f;
            float b1 = addb ? bias[col + 1] : 0.0f;
            if (single) {
                if (h16) {
                    __half* Ch = (__half*)C;
                    *(__half2*)(Ch + (size_t)row * ldc + col) =
                        __floats2half2_rn(c[mi][nj][0] + b0, c[mi][nj][1] + b1);
                    *(__half2*)(Ch + (size_t)(row + 8) * ldc + col) =
                        __floats2half2_rn(c[mi][nj][2] + b0, c[mi][nj][3] + b1);
                } else {
                    *(float2*)&C[(size_t)row * ldc + col] =
                        make_float2(c[mi][nj][0] + b0, c[mi][nj][1] + b1);
                    *(float2*)&C[(size_t)(row + 8) * ldc + col] =
                        make_float2(c[mi][nj][2] + b0, c[mi][nj][3] + b1);
                }
            } else {
                atomicAdd(&C[(size_t)row * ldc + col],           c[mi][nj][0] + b0);
                atomicAdd(&C[(size_t)row * ldc + col + 1],       c[mi][nj][1] + b1);
                atomicAdd(&C[(size_t)(row + 8) * ldc + col],     c[mi][nj][2] + b0);
                atomicAdd(&C[(size_t)(row + 8) * ldc + col + 1], c[mi][nj][3] + b1);
            }
        }
    }
}

// ---------------- transpose fp32 -> fp16 K-major ----------------
__global__ void transpose_into(const float* __restrict__ src, int K, int N,
                               __half* __restrict__ dst, int ldd, int koff)
{
    __shared__ float tile[32][33];
    const int kb = blockIdx.x * 32, nb = blockIdx.y * 32;
    const int tx = threadIdx.x, ty = threadIdx.y;
    #pragma unroll
    for (int i = ty; i < 32; i += 8)
        tile[i][tx] = src[(size_t)(kb + i) * N + nb + tx];
    __syncthreads();
    #pragma unroll
    for (int i = ty; i < 32; i += 8)
        dst[(size_t)(nb + i) * ldd + koff + kb + tx] = __float2half_rn(tile[tx][i]);
}

__global__ void zero_region_h(__half* __restrict__ dst, int ldd, int r0, int c0)
{
    __half z = __float2half(0.0f);
    #pragma unroll
    for (int j = 0; j < 4; j++)
        dst[(size_t)(r0 + blockIdx.x) * ldd + c0 + threadIdx.x * 4 + j] = z;
}

__global__ void cvt_eh(const float* __restrict__ src)
{
    size_t i = (size_t)blockIdx.x * blockDim.x + threadIdx.x;
    float4 v = *(const float4*)(src + i * 4);
    __half2* d = (__half2*)g_ehtf;
    d[2 * i] = __floats2half2_rn(v.x, v.y);
    d[2 * i + 1] = __floats2half2_rn(v.z, v.w);
}

__global__ void gbias_kernel(const float* __restrict__ b_ih1, const float* __restrict__ b_hh1,
                             const float* __restrict__ b_ih2, const float* __restrict__ b_hh2,
                             const float* __restrict__ lt_b)
{
    int i = blockIdx.x * blockDim.x + threadIdx.x;
    if (i < 4 * HDz) {
        g_gb1[i] = b_ih1[i] + b_hh1[i];
        g_gb2c[i] = b_ih2[i] + b_hh2[i];
    }
    if (i < HDz) g_gb2c[4 * HDz + i] = lt_b[i];
}

// ---------------- init state ----------------
__global__ void init_state(const float* __restrict__ h1_0, const float* __restrict__ c1_0,
                           const float* __restrict__ h2_0, const float* __restrict__ c2_0)
{
    int idx = blockIdx.x * blockDim.x + threadIdx.x;
    if (idx >= Bz * HDz) return;
    int b = idx >> 10, j = idx & (HDz - 1);
    g_c1[idx] = c1_0[idx];
    g_c2[idx] = c2_0[idx];
    g_abuf1[(size_t)b * K1z + 1536 + j] = __float2half_rn(h1_0[idx]);
    g_abuf2[(size_t)b * K2z + 1024 + j] = __float2half_rn(h2_0[idx]);
    g_hprev[idx] = __float2half_rn(1.0f / (float)HEz);
    #pragma unroll
    for (int gi = 0; gi < 4; gi++)
        g_gates1[(size_t)b * 4 * HDz + gi * HDz + j] = 0.0f;
    if (idx < Bz * APz) g_q[idx] = 0.0f;
}

// ---------------- fused attention ----------------
__global__ __launch_bounds__(512) void attn_fused(
    const int* __restrict__ enc_masks,
    const float* __restrict__ corr_w, const float* __restrict__ corr_b,
    const float* __restrict__ captions, int t)
{
    __shared__ __align__(16) float qv[APz];
    __shared__ __align__(16) float cw[APz];
    __shared__ float al[Lz];
    const int b = blockIdx.x;
    const int tid = threadIdx.x, lane = tid & 31, warp = tid >> 5;

    if (tid < APz) {
        qv[tid] = g_q[b * APz + tid];
        cw[tid] = corr_w[tid];
        g_abuf1[(size_t)b * K1z + tid] = __float2half_rn(captions[((size_t)t * Bz + b) * Ez + tid]);
    }
    __syncthreads();

    const float cb = corr_b[0];
    #pragma unroll
    for (int li = 0; li < 8; li++) {
        const int l = warp + li * 16;
        const uint4* ep = (const uint4*)(g_enc_proj + ((size_t)(b * Lz + l)) * APz);
        float acc = 0.0f;
        #pragma unroll
        for (int u = 0; u < 2; u++) {
            uint4 pk = ep[lane * 2 + u];
            const __half2* h2 = (const __half2*)&pk;
            const int ap0 = lane * 16 + u * 8;
            #pragma unroll
            for (int p = 0; p < 4; p++) {
                float2 v = __half22float2(h2[p]);
                acc += fast_tanh(v.x + qv[ap0 + 2 * p]) * cw[ap0 + 2 * p];
                acc += fast_tanh(v.y + qv[ap0 + 2 * p + 1]) * cw[ap0 + 2 * p + 1];
            }
        }
        #pragma unroll
        for (int off = 16; off; off >>= 1) acc += __shfl_xor_sync(0xffffffffu, acc, off);
        if (lane == 0) {
            float v = acc + cb;
            if (enc_masks[b * Lz + l]) v = -INFINITY;
            al[l] = v;
        }
    }
    __syncthreads();

    if (tid < 32) {
        float m = -INFINITY;
        #pragma unroll
        for (int i = 0; i < 4; i++) m = fmaxf(m, al[tid + 32 * i]);
        #pragma unroll
        for (int off = 16; off; off >>= 1) m = fmaxf(m, __shfl_xor_sync(0xffffffffu, m, off));
        float ex[4], s = 0.0f;
        #pragma unroll
        for (int i = 0; i < 4; i++) { ex[i] = __expf(al[tid + 32 * i] - m); s += ex[i]; }
        #pragma unroll
        for (int off = 16; off; off >>= 1) s += __shfl_xor_sync(0xffffffffu, s, off);
        float inv = 1.0f / s;
        #pragma unroll
        for (int i = 0; i < 4; i++) al[tid + 32 * i] = ex[i] * inv;
    }
    __syncthreads();

    const __half2* eh2 = (const __half2*)(g_ehtf + (size_t)b * Lz * HEz);
    float2 acc2 = make_float2(0.0f, 0.0f);
    #pragma unroll 8
    for (int l = 0; l < Lz; l++) {
        float2 v = __half22float2(eh2[(size_t)l * (HEz / 2) + tid]);
        float a = al[l];
        acc2.x += a * v.x;
        acc2.y += a * v.y;
    }
    *(__half2*)(g_abuf1 + (size_t)b * K1z + Ez + 2 * tid) = __floats2half2_rn(acc2.x, acc2.y);
}

// ---------------- LSTM pointwise ----------------
__global__ __launch_bounds__(256) void lstm_point1()
{
    int idx = blockIdx.x * blockDim.x + threadIdx.x;
    if (idx >= Bz * HDz) return;
    int b = idx >> 10, j = idx & (HDz - 1);
    const float* g = g_gates1 + (size_t)b * 4 * HDz;
    float ig = sigmoidf_(g[j]);
    float fg = sigmoidf_(g[HDz + j]);
    float gg = tanhf(g[2 * HDz + j]);
    float og = sigmoidf_(g[3 * HDz + j]);
    float cn = fg * g_c1[idx] + ig * gg;
    float hn = og * tanhf(cn);
    g_c1[idx] = cn;
    __half hn_h = __float2half_rn(hn);
    g_abuf2[(size_t)b * K2z + j] = hn_h;
    g_abuf1[(size_t)b * K1z + 1536 + j] = hn_h;
    #pragma unroll
    for (int gi = 0; gi < 5; gi++)
        g_g2c[(size_t)b * N2z + gi * HDz + j] = 0.0f;
}

__global__ __launch_bounds__(256) void lstm_point2(float* __restrict__ out)
{
    int idx = blockIdx.x * blockDim.x + threadIdx.x;
    if (idx >= Bz * HDz) return;
    int b = idx >> 10, j = idx & (HDz - 1);
    const float* g = g_g2c + (size_t)b * N2z;
    float ig = sigmoidf_(g[j]);
    float fg = sigmoidf_(g[HDz + j]);
    float gg = tanhf(g[2 * HDz + j]);
    float og = sigmoidf_(g[3 * HDz + j]);
    float cn = fg * g_c2[idx] + ig * gg;
    float hn = og * tanhf(cn);
    g_c2[idx] = cn;
    __half hn_h = __float2half_rn(hn);
    g_abuf2[(size_t)b * K2z + 1024 + j] = hn_h;
    g_hprev[idx] = hn_h;
    out[idx] = tanhf(g[4 * HDz + j]);
    #pragma unroll
    for (int gi = 0; gi < 4; gi++)
        g_gates1[(size_t)b * 4 * HDz + gi * HDz + j] = 0.0f;
    if (idx < Bz * APz) g_q[idx] = 0.0f;
}

// ---------------- host launcher ----------------
extern "C" void kernel_launch(void* const* d_in, const int* in_sizes, int n_in,
                              void* d_out, int out_size)
{
    const float* enc_hiddens = (const float*)d_in[0];
    const int*   enc_masks   = (const int*)  d_in[1];
    const float* h1_0 = (const float*)d_in[2];
    const float* c1_0 = (const float*)d_in[3];
    const float* h2_0 = (const float*)d_in[4];
    const float* c2_0 = (const float*)d_in[5];
    const float* captions = (const float*)d_in[6];
    const float* att_W = (const float*)d_in[7];
    const float* att_b = (const float*)d_in[8];
    const float* dhp_W = (const float*)d_in[9];
    const float* dhp_b = (const float*)d_in[10];
    const float* corr_w = (const float*)d_in[11];
    const float* corr_b = (const float*)d_in[12];
    const float* lt_W = (const float*)d_in[13];
    const float* lt_b = (const float*)d_in[14];
    const float* W_ih1 = (const float*)d_in[15];
    const float* W_hh1 = (const float*)d_in[16];
    const float* b_ih1 = (const float*)d_in[17];
    const float* b_hh1 = (const float*)d_in[18];
    const float* W_ih2 = (const float*)d_in[19];
    const float* W_hh2 = (const float*)d_in[20];
    const float* b_ih2 = (const float*)d_in[21];
    const float* b_hh2 = (const float*)d_in[22];
    float* out = (float*)d_out;

    static bool inited = false;
    static __half *p_enc_proj, *p_ehtf, *p_a1, *p_a2, *p_hprev;
    static __half *p_W1t, *p_W2c, *p_dhpWt, *p_attWt;
    static float *p_g1, *p_g2c, *p_q, *p_gb1, *p_gb2c;
    if (!inited) {
        cudaGetSymbolAddress((void**)&p_enc_proj, g_enc_proj);
        cudaGetSymbolAddress((void**)&p_ehtf,  g_ehtf);
        cudaGetSymbolAddress((void**)&p_a1,    g_abuf1);
        cudaGetSymbolAddress((void**)&p_a2,    g_abuf2);
        cudaGetSymbolAddress((void**)&p_g1,    g_gates1);
        cudaGetSymbolAddress((void**)&p_g2c,   g_g2c);
        cudaGetSymbolAddress((void**)&p_q,     g_q);
        cudaGetSymbolAddress((void**)&p_hprev, g_hprev);
        cudaGetSymbolAddress((void**)&p_W1t,   g_W1t);
        cudaGetSymbolAddress((void**)&p_W2c,   g_W2c);
        cudaGetSymbolAddress((void**)&p_dhpWt, g_dhpWt);
        cudaGetSymbolAddress((void**)&p_attWt, g_attWt);
        cudaGetSymbolAddress((void**)&p_gb1,   g_gb1);
        cudaGetSymbolAddress((void**)&p_gb2c,  g_gb2c);
        cudaFuncSetAttribute(gemm_mma, cudaFuncAttributeMaxDynamicSharedMemorySize,
                             3 * STGH * 2);
        inited = true;
    }
    const int GSM = 3 * STGH * 2;   // 82944 B
    dim3 tb(32, 8);

    init_state<<<(Bz * HDz + 255) / 256, 256>>>(h1_0, c1_0, h2_0, c2_0);

    transpose_into<<<dim3(HEz / 32, APz / 32), tb>>>(att_W, HEz, APz, p_attWt, HEz, 0);
    transpose_into<<<dim3(HDz / 32, APz / 32), tb>>>(dhp_W, HDz, APz, p_dhpWt, HDz, 0);
    transpose_into<<<dim3(1536 / 32, 4 * HDz / 32), tb>>>(W_ih1, 1536, 4 * HDz, p_W1t, K1z, 0);
    transpose_into<<<dim3(HDz / 32, 4 * HDz / 32), tb>>>(W_hh1, HDz, 4 * HDz, p_W1t, K1z, 1536);
    transpose_into<<<dim3(HDz / 32, 4 * HDz / 32), tb>>>(W_ih2, HDz, 4 * HDz, p_W2c, K2z, 0);
    transpose_into<<<dim3(HDz / 32, 4 * HDz / 32), tb>>>(W_hh2, HDz, 4 * HDz, p_W2c, K2z, 1024);
    transpose_into<<<dim3(HDz / 32, HDz / 32), tb>>>(lt_W, HDz, HDz,
                                                     p_W2c + (size_t)4 * HDz * K2z, K2z, 0);
    zero_region_h<<<HDz, 256>>>(p_W2c, K2z, 4 * HDz, 1024);
    cvt_eh<<<(Bz * Lz * HEz / 4 + 255) / 256, 256>>>(enc_hiddens);
    gbias_kernel<<<(4 * HDz + 255) / 256, 256>>>(b_ih1, b_hh1, b_ih2, b_hh2, lt_b);

    gemm_mma<<<dim3(APz / BN, Bz * Lz / BMt, 1), 256, GSM>>>(
        p_ehtf, HEz, p_attWt, HEz, (float*)p_enc_proj, APz, HEz, att_b, 1);

    for (int t = 0; t < Tz; t++) {
        gemm_mma<<<dim3(APz / BN, Bz / BMt, 16), 256, GSM>>>(
            p_hprev, HDz, p_dhpWt, HDz, p_q, APz, 64, dhp_b, 0);

        attn_fused<<<Bz, 512>>>(enc_masks, corr_w, corr_b, captions, t);

        gemm_mma<<<dim3(4 * HDz / BN, Bz / BMt, 5), 256, GSM>>>(
            p_a1, K1z, p_W1t, K1z, p_g1, 4 * HDz, 512, p_gb1, 0);
        lstm_point1<<<(Bz * HDz + 255) / 256, 256>>>();

        gemm_mma<<<dim3(N2z / BN, Bz / BMt, 4), 256, GSM>>>(
            p_a2, K2z, p_W2c, K2z, p_g2c, N2z, 512, p_gb2c, 0);

        lstm_point2<<<(Bz * HDz + 255) / 256, 256>>>(out + (size_t)t * Bz * HDz);
    }
    (void)in_sizes; (void)n_in; (void)out_size;
}

// round 10
// speedup vs baseline: 8.7871x; 1.0702x over previous
#include <cuda_runtime.h>
#include <cuda_fp16.h>
#include <math.h>
#include <cstdint>

#define Bz 128
#define Lz 128
#define HEz 1024
#define HDz 1024
#define Ez 512
#define APz 512
#define Tz 64
#define K1z 2560        // [x_t | a_t | h1_prev]
#define K2z 2048        // [h1 | h2]
#define N2z 5120        // gates2 (4096) + out-proj (1024)

// ---------------- device scratch ----------------
__device__ __align__(128) __half g_enc_proj[Bz * Lz * APz];
__device__ __align__(128) __half g_ehtf[Bz * Lz * HEz];
__device__ __align__(128) float  g_q[Bz * APz];
__device__ __align__(128) __half g_abuf1[Bz * K1z];
__device__ __align__(128) __half g_abuf2[Bz * K2z];
__device__ __align__(128) float  g_gates1[Bz * 4 * HDz];
__device__ __align__(128) float  g_g2c[Bz * N2z];
__device__ __align__(128) float  g_c1[Bz * HDz];
__device__ __align__(128) float  g_c2[Bz * HDz];
__device__ __align__(128) __half g_hprev[Bz * HDz];
__device__ __align__(128) __half g_W1t[4 * HDz * K1z];
__device__ __align__(128) __half g_W2c[N2z * K2z];
__device__ __align__(128) __half g_dhpWt[APz * HDz];
__device__ __align__(128) __half g_attWt[APz * HEz];
__device__ __align__(128) float  g_gb1[4 * HDz];
__device__ __align__(128) float  g_gb2c[N2z];

__device__ __forceinline__ float fast_tanh(float x) {
    float y; asm("tanh.approx.f32 %0, %1;" : "=f"(y) : "f"(x)); return y;
}
__device__ __forceinline__ float sigmoidf_(float x) { return 1.0f / (1.0f + expf(-x)); }
__device__ __forceinline__ uint32_t smem_u32(const void* p) {
    uint32_t a;
    asm("{ .reg .u64 t; cvta.to.shared.u64 t, %1; cvt.u32.u64 %0, t; }" : "=r"(a) : "l"(p));
    return a;
}
#define CP16(dst, src) \
    asm volatile("cp.async.cg.shared.global [%0], [%1], 16;" :: "r"(dst), "l"(src))
#define LDSM4(d0, d1, d2, d3, addr) \
    asm volatile("ldmatrix.sync.aligned.m8n8.x4.shared.b16 {%0,%1,%2,%3}, [%4];" \
                 : "=r"(d0), "=r"(d1), "=r"(d2), "=r"(d3) : "r"(addr))
// PDL: wait for upstream grid's memory; signal dependents may launch
#define GRID_WAIT()       asm volatile("griddepcontrol.wait;" ::: "memory")
#define GRID_LAUNCH_DEP() asm volatile("griddepcontrol.launch_dependents;" ::: "memory")

// ---------------- 3-stage pipelined HMMA fp16 GEMM (m16n8k16 + ldmatrix + PDL) --
// C[m0:+64, n0:+128] (+)= A[m0:, kslice](lda) @ Bt[n0:, kslice]^T  (fp32 accum)
// B (weights) stages 0..1 prefetched BEFORE griddepcontrol.wait; A after.
#define BMt 64
#define BN 128
#define BKh 64
#define SWH 72
#define STGH ((BMt + BN) * SWH)

__global__ __launch_bounds__(256, 2) void gemm_mma(
    const __half* __restrict__ A, int lda,
    const __half* __restrict__ Bt, int ldb,
    float* __restrict__ C, int ldc,
    int chunk, const float* __restrict__ bias, int flags)
{
    extern __shared__ __half smh[];
    const int tid = threadIdx.x;
    const int wid = tid >> 5, lane = tid & 31;
    const int wm = wid & 1, wn = wid >> 1;
    const int lrow = lane >> 2, lcol = lane & 3;
    const int n0 = blockIdx.x * BN;
    const int m0 = blockIdx.y * BMt;
    const int kbeg = blockIdx.z * chunk;
    const int NC = chunk / BKh;

    float c[2][4][4];
    #pragma unroll
    for (int i = 0; i < 2; i++)
        #pragma unroll
        for (int j = 0; j < 4; j++)
            #pragma unroll
            for (int r = 0; r < 4; r++) c[i][j][r] = 0.0f;

    const uint32_t sbase = smem_u32(smh);
    const __half* Abase = A + (size_t)m0 * lda + kbeg;
    const __half* Bbase = Bt + (size_t)n0 * ldb + kbeg;

    const int ar0 = (tid + 0)   >> 3, ao0 = (tid + 0)   & 7;
    const int ar1 = (tid + 256) >> 3, ao1 = (tid + 256) & 7;

    const uint32_t a_off =
        ((uint32_t)((wm * 32 + (lane & 15)) * SWH + ((lane >> 4) << 3))) * 2;
    const uint32_t b_off =
        ((uint32_t)((BMt + wn * 32 + (lane & 7) + (((lane >> 4) & 1) << 3)) * SWH
                    + (((lane >> 3) & 1) << 3))) * 2;

#define LOAD_A_STAGE(ck, st) do {                                                 \
        uint32_t sb = sbase + (uint32_t)(st) * STGH * 2;                          \
        const __half* Ag = Abase + (size_t)(ck) * BKh;                            \
        CP16(sb + ar0 * 144 + ao0 * 16, Ag + (size_t)ar0 * lda + ao0 * 8);        \
        CP16(sb + ar1 * 144 + ao1 * 16, Ag + (size_t)ar1 * lda + ao1 * 8);        \
    } while (0)
#define LOAD_B_STAGE(ck, st) do {                                                 \
        uint32_t sb = sbase + (uint32_t)(st) * STGH * 2;                          \
        const __half* Bg = Bbase + (size_t)(ck) * BKh;                            \
        _Pragma("unroll")                                                         \
        for (int j = 0; j < 4; j++) {                                             \
            int i = tid + j * 256;                                                \
            int row = i >> 3, off = i & 7;                                        \
            CP16(sb + (BMt + row) * 144 + off * 16,                               \
                 Bg + (size_t)row * ldb + off * 8);                               \
        }                                                                         \
    } while (0)

    // weight prefetch (independent of predecessor) BEFORE the PDL wait
    LOAD_B_STAGE(0, 0);
    if (NC > 1) LOAD_B_STAGE(1, 1);
    GRID_WAIT();
    LOAD_A_STAGE(0, 0);
    asm volatile("cp.async.commit_group;" ::: "memory");
    if (NC > 1) {
        LOAD_A_STAGE(1, 1);
        asm volatile("cp.async.commit_group;" ::: "memory");
    }

    int s = 0;
    for (int cc = 0; cc < NC; cc++) {
        if (cc + 1 < NC) { asm volatile("cp.async.wait_group 1;" ::: "memory"); }
        else             { asm volatile("cp.async.wait_group 0;" ::: "memory"); }
        __syncthreads();
        if (cc + 2 < NC) {
            int st = s + 2 >= 3 ? s - 1 : s + 2;
            LOAD_B_STAGE(cc + 2, st);
            LOAD_A_STAGE(cc + 2, st);
            asm volatile("cp.async.commit_group;" ::: "memory");
        }

        const uint32_t stg = sbase + (uint32_t)s * STGH * 2;
        const uint32_t aad = stg + a_off;
        const uint32_t bad = stg + b_off;

        #pragma unroll
        for (int ks = 0; ks < 4; ks++) {
            uint32_t a[2][4], b[4][2];
            const uint32_t kso = ks * 32;
            LDSM4(a[0][0], a[0][1], a[0][2], a[0][3], aad + kso);
            LDSM4(a[1][0], a[1][1], a[1][2], a[1][3], aad + 16 * SWH * 2 + kso);
            LDSM4(b[0][0], b[0][1], b[1][0], b[1][1], bad + kso);
            LDSM4(b[2][0], b[2][1], b[3][0], b[3][1], bad + 16 * SWH * 2 + kso);
            #pragma unroll
            for (int mi = 0; mi < 2; mi++)
                #pragma unroll
                for (int nj = 0; nj < 4; nj++)
                    asm volatile(
                        "mma.sync.aligned.m16n8k16.row.col.f32.f16.f16.f32 "
                        "{%0,%1,%2,%3}, {%4,%5,%6,%7}, {%8,%9}, {%0,%1,%2,%3};"
                        : "+f"(c[mi][nj][0]), "+f"(c[mi][nj][1]),
                          "+f"(c[mi][nj][2]), "+f"(c[mi][nj][3])
                        : "r"(a[mi][0]), "r"(a[mi][1]), "r"(a[mi][2]), "r"(a[mi][3]),
                          "r"(b[nj][0]), "r"(b[nj][1]));
        }
        s = (s + 1 == 3) ? 0 : s + 1;
    }
#undef LOAD_A_STAGE
#undef LOAD_B_STAGE

    GRID_LAUNCH_DEP();

    const bool single = (gridDim.z == 1);
    const bool addb = (blockIdx.z == 0);
    const bool h16 = (flags & 1);
    #pragma unroll
    for (int mi = 0; mi < 2; mi++) {
        const int row = m0 + wm * 32 + mi * 16 + lrow;
        #pragma unroll
        for (int nj = 0; nj < 4; nj++) {
            const int col = n0 + wn * 32 + nj * 8 + 2 * lcol;
            float b0 = addb ? bias[col] : 0.0f;
            float b1 = addb ? bias[col + 1] : 0.0f;
            if (single) {
                if (h16) {
                    __half* Ch = (__half*)C;
                    *(__half2*)(Ch + (size_t)row * ldc + col) =
                        __floats2half2_rn(c[mi][nj][0] + b0, c[mi][nj][1] + b1);
                    *(__half2*)(Ch + (size_t)(row + 8) * ldc + col) =
                        __floats2half2_rn(c[mi][nj][2] + b0, c[mi][nj][3] + b1);
                } else {
                    *(float2*)&C[(size_t)row * ldc + col] =
                        make_float2(c[mi][nj][0] + b0, c[mi][nj][1] + b1);
                    *(float2*)&C[(size_t)(row + 8) * ldc + col] =
                        make_float2(c[mi][nj][2] + b0, c[mi][nj][3] + b1);
                }
            } else {
                atomicAdd(&C[(size_t)row * ldc + col],           c[mi][nj][0] + b0);
                atomicAdd(&C[(size_t)row * ldc + col + 1],       c[mi][nj][1] + b1);
                atomicAdd(&C[(size_t)(row + 8) * ldc + col],     c[mi][nj][2] + b0);
                atomicAdd(&C[(size_t)(row + 8) * ldc + col + 1], c[mi][nj][3] + b1);
            }
        }
    }
}

// ---------------- transpose fp32 -> fp16 K-major ----------------
__global__ void transpose_into(const float* __restrict__ src, int K, int N,
                               __half* __restrict__ dst, int ldd, int koff)
{
    __shared__ float tile[32][33];
    const int kb = blockIdx.x * 32, nb = blockIdx.y * 32;
    const int tx = threadIdx.x, ty = threadIdx.y;
    #pragma unroll
    for (int i = ty; i < 32; i += 8)
        tile[i][tx] = src[(size_t)(kb + i) * N + nb + tx];
    __syncthreads();
    #pragma unroll
    for (int i = ty; i < 32; i += 8)
        dst[(size_t)(nb + i) * ldd + koff + kb + tx] = __float2half_rn(tile[tx][i]);
}

__global__ void zero_region_h(__half* __restrict__ dst, int ldd, int r0, int c0)
{
    __half z = __float2half(0.0f);
    #pragma unroll
    for (int j = 0; j < 4; j++)
        dst[(size_t)(r0 + blockIdx.x) * ldd + c0 + threadIdx.x * 4 + j] = z;
}

__global__ void cvt_eh(const float* __restrict__ src)
{
    size_t i = (size_t)blockIdx.x * blockDim.x + threadIdx.x;
    float4 v = *(const float4*)(src + i * 4);
    __half2* d = (__half2*)g_ehtf;
    d[2 * i] = __floats2half2_rn(v.x, v.y);
    d[2 * i + 1] = __floats2half2_rn(v.z, v.w);
}

__global__ void gbias_kernel(const float* __restrict__ b_ih1, const float* __restrict__ b_hh1,
                             const float* __restrict__ b_ih2, const float* __restrict__ b_hh2,
                             const float* __restrict__ lt_b)
{
    int i = blockIdx.x * blockDim.x + threadIdx.x;
    if (i < 4 * HDz) {
        g_gb1[i] = b_ih1[i] + b_hh1[i];
        g_gb2c[i] = b_ih2[i] + b_hh2[i];
    }
    if (i < HDz) g_gb2c[4 * HDz + i] = lt_b[i];
}

// ---------------- init state ----------------
__global__ void init_state(const float* __restrict__ h1_0, const float* __restrict__ c1_0,
                           const float* __restrict__ h2_0, const float* __restrict__ c2_0)
{
    int idx = blockIdx.x * blockDim.x + threadIdx.x;
    if (idx >= Bz * HDz) return;
    int b = idx >> 10, j = idx & (HDz - 1);
    g_c1[idx] = c1_0[idx];
    g_c2[idx] = c2_0[idx];
    g_abuf1[(size_t)b * K1z + 1536 + j] = __float2half_rn(h1_0[idx]);
    g_abuf2[(size_t)b * K2z + 1024 + j] = __float2half_rn(h2_0[idx]);
    g_hprev[idx] = __float2half_rn(1.0f / (float)HEz);
    #pragma unroll
    for (int gi = 0; gi < 4; gi++)
        g_gates1[(size_t)b * 4 * HDz + gi * HDz + j] = 0.0f;
    if (idx < Bz * APz) g_q[idx] = 0.0f;
}

// ---------------- fused attention (PDL) ----------------
__global__ __launch_bounds__(512) void attn_fused(
    const int* __restrict__ enc_masks,
    const float* __restrict__ corr_w, const float* __restrict__ corr_b,
    const float* __restrict__ captions, int t)
{
    __shared__ __align__(16) float qv[APz];
    __shared__ __align__(16) float cw[APz];
    __shared__ float al[Lz];
    const int b = blockIdx.x;
    const int tid = threadIdx.x, lane = tid & 31, warp = tid >> 5;

    // independent pre-work: corr_w load + x_t copy (doesn't touch predecessor data)
    if (tid < APz) {
        cw[tid] = corr_w[tid];
        g_abuf1[(size_t)b * K1z + tid] = __float2half_rn(captions[((size_t)t * Bz + b) * Ez + tid]);
    }
    GRID_WAIT();
    if (tid < APz) qv[tid] = g_q[b * APz + tid];
    __syncthreads();

    const float cb = corr_b[0];
    #pragma unroll
    for (int li = 0; li < 8; li++) {
        const int l = warp + li * 16;
        const uint4* ep = (const uint4*)(g_enc_proj + ((size_t)(b * Lz + l)) * APz);
        float acc = 0.0f;
        #pragma unroll
        for (int u = 0; u < 2; u++) {
            uint4 pk = ep[lane * 2 + u];
            const __half2* h2 = (const __half2*)&pk;
            const int ap0 = lane * 16 + u * 8;
            #pragma unroll
            for (int p = 0; p < 4; p++) {
                float2 v = __half22float2(h2[p]);
                acc += fast_tanh(v.x + qv[ap0 + 2 * p]) * cw[ap0 + 2 * p];
                acc += fast_tanh(v.y + qv[ap0 + 2 * p + 1]) * cw[ap0 + 2 * p + 1];
            }
        }
        #pragma unroll
        for (int off = 16; off; off >>= 1) acc += __shfl_xor_sync(0xffffffffu, acc, off);
        if (lane == 0) {
            float v = acc + cb;
            if (enc_masks[b * Lz + l]) v = -INFINITY;
            al[l] = v;
        }
    }
    __syncthreads();

    if (tid < 32) {
        float m = -INFINITY;
        #pragma unroll
        for (int i = 0; i < 4; i++) m = fmaxf(m, al[tid + 32 * i]);
        #pragma unroll
        for (int off = 16; off; off >>= 1) m = fmaxf(m, __shfl_xor_sync(0xffffffffu, m, off));
        float ex[4], s = 0.0f;
        #pragma unroll
        for (int i = 0; i < 4; i++) { ex[i] = __expf(al[tid + 32 * i] - m); s += ex[i]; }
        #pragma unroll
        for (int off = 16; off; off >>= 1) s += __shfl_xor_sync(0xffffffffu, s, off);
        float inv = 1.0f / s;
        #pragma unroll
        for (int i = 0; i < 4; i++) al[tid + 32 * i] = ex[i] * inv;
    }
    __syncthreads();
    GRID_LAUNCH_DEP();   // gates1 GEMM may start prefetching W1t now

    const __half2* eh2 = (const __half2*)(g_ehtf + (size_t)b * Lz * HEz);
    float2 acc2 = make_float2(0.0f, 0.0f);
    #pragma unroll 8
    for (int l = 0; l < Lz; l++) {
        float2 v = __half22float2(eh2[(size_t)l * (HEz / 2) + tid]);
        float a = al[l];
        acc2.x += a * v.x;
        acc2.y += a * v.y;
    }
    *(__half2*)(g_abuf1 + (size_t)b * K1z + Ez + 2 * tid) = __floats2half2_rn(acc2.x, acc2.y);
}

// ---------------- LSTM pointwise (PDL) ----------------
__global__ __launch_bounds__(256) void lstm_point1()
{
    GRID_WAIT();
    int idx = blockIdx.x * blockDim.x + threadIdx.x;
    int b = idx >> 10, j = idx & (HDz - 1);
    const float* g = g_gates1 + (size_t)b * 4 * HDz;
    float ig = sigmoidf_(g[j]);
    float fg = sigmoidf_(g[HDz + j]);
    float gg = tanhf(g[2 * HDz + j]);
    float og = sigmoidf_(g[3 * HDz + j]);
    float cn = fg * g_c1[idx] + ig * gg;
    float hn = og * tanhf(cn);
    GRID_LAUNCH_DEP();   // gates2c GEMM may start prefetching W2c now
    g_c1[idx] = cn;
    __half hn_h = __float2half_rn(hn);
    g_abuf2[(size_t)b * K2z + j] = hn_h;
    g_abuf1[(size_t)b * K1z + 1536 + j] = hn_h;
    #pragma unroll
    for (int gi = 0; gi < 5; gi++)
        g_g2c[(size_t)b * N2z + gi * HDz + j] = 0.0f;
}

__global__ __launch_bounds__(256) void lstm_point2(float* __restrict__ out)
{
    GRID_WAIT();
    int idx = blockIdx.x * blockDim.x + threadIdx.x;
    int b = idx >> 10, j = idx & (HDz - 1);
    const float* g = g_g2c + (size_t)b * N2z;
    float ig = sigmoidf_(g[j]);
    float fg = sigmoidf_(g[HDz + j]);
    float gg = tanhf(g[2 * HDz + j]);
    float og = sigmoidf_(g[3 * HDz + j]);
    float cn = fg * g_c2[idx] + ig * gg;
    float hn = og * tanhf(cn);
    GRID_LAUNCH_DEP();   // next step's q GEMM may start prefetching dhpWt now
    g_c2[idx] = cn;
    __half hn_h = __float2half_rn(hn);
    g_abuf2[(size_t)b * K2z + 1024 + j] = hn_h;
    g_hprev[idx] = hn_h;
    out[idx] = tanhf(g[4 * HDz + j]);
    #pragma unroll
    for (int gi = 0; gi < 4; gi++)
        g_gates1[(size_t)b * 4 * HDz + gi * HDz + j] = 0.0f;
    if (idx < Bz * APz) g_q[idx] = 0.0f;
}

// ---------------- PDL launch helper ----------------
template <class T> struct idt { using type = T; };
template <typename... Args>
static inline void launch_pdl(dim3 grid, dim3 block, size_t shm,
                              void (*kern)(Args...),
                              typename idt<Args>::type... args)
{
    cudaLaunchConfig_t cfg = {};
    cfg.gridDim = grid; cfg.blockDim = block;
    cfg.dynamicSmemBytes = shm; cfg.stream = 0;
    cudaLaunchAttribute at[1];
    at[0].id = cudaLaunchAttributeProgrammaticStreamSerialization;
    at[0].val.programmaticStreamSerializationAllowed = 1;
    cfg.attrs = at; cfg.numAttrs = 1;
    cudaLaunchKernelEx(&cfg, kern, args...);
}

// ---------------- host launcher ----------------
extern "C" void kernel_launch(void* const* d_in, const int* in_sizes, int n_in,
                              void* d_out, int out_size)
{
    const float* enc_hiddens = (const float*)d_in[0];
    const int*   enc_masks   = (const int*)  d_in[1];
    const float* h1_0 = (const float*)d_in[2];
    const float* c1_0 = (const float*)d_in[3];
    const float* h2_0 = (const float*)d_in[4];
    const float* c2_0 = (const float*)d_in[5];
    const float* captions = (const float*)d_in[6];
    const float* att_W = (const float*)d_in[7];
    const float* att_b = (const float*)d_in[8];
    const float* dhp_W = (const float*)d_in[9];
    const float* dhp_b = (const float*)d_in[10];
    const float* corr_w = (const float*)d_in[11];
    const float* corr_b = (const float*)d_in[12];
    const float* lt_W = (const float*)d_in[13];
    const float* lt_b = (const float*)d_in[14];
    const float* W_ih1 = (const float*)d_in[15];
    const float* W_hh1 = (const float*)d_in[16];
    const float* b_ih1 = (const float*)d_in[17];
    const float* b_hh1 = (const float*)d_in[18];
    const float* W_ih2 = (const float*)d_in[19];
    const float* W_hh2 = (const float*)d_in[20];
    const float* b_ih2 = (const float*)d_in[21];
    const float* b_hh2 = (const float*)d_in[22];
    float* out = (float*)d_out;

    static bool inited = false;
    static __half *p_enc_proj, *p_ehtf, *p_a1, *p_a2, *p_hprev;
    static __half *p_W1t, *p_W2c, *p_dhpWt, *p_attWt;
    static float *p_g1, *p_g2c, *p_q, *p_gb1, *p_gb2c;
    if (!inited) {
        cudaGetSymbolAddress((void**)&p_enc_proj, g_enc_proj);
        cudaGetSymbolAddress((void**)&p_ehtf,  g_ehtf);
        cudaGetSymbolAddress((void**)&p_a1,    g_abuf1);
        cudaGetSymbolAddress((void**)&p_a2,    g_abuf2);
        cudaGetSymbolAddress((void**)&p_g1,    g_gates1);
        cudaGetSymbolAddress((void**)&p_g2c,   g_g2c);
        cudaGetSymbolAddress((void**)&p_q,     g_q);
        cudaGetSymbolAddress((void**)&p_hprev, g_hprev);
        cudaGetSymbolAddress((void**)&p_W1t,   g_W1t);
        cudaGetSymbolAddress((void**)&p_W2c,   g_W2c);
        cudaGetSymbolAddress((void**)&p_dhpWt, g_dhpWt);
        cudaGetSymbolAddress((void**)&p_attWt, g_attWt);
        cudaGetSymbolAddress((void**)&p_gb1,   g_gb1);
        cudaGetSymbolAddress((void**)&p_gb2c,  g_gb2c);
        cudaFuncSetAttribute(gemm_mma, cudaFuncAttributeMaxDynamicSharedMemorySize,
                             3 * STGH * 2);
        inited = true;
    }
    const int GSM = 3 * STGH * 2;   // 82944 B
    dim3 tb(32, 8);

    init_state<<<(Bz * HDz + 255) / 256, 256>>>(h1_0, c1_0, h2_0, c2_0);

    transpose_into<<<dim3(HEz / 32, APz / 32), tb>>>(att_W, HEz, APz, p_attWt, HEz, 0);
    transpose_into<<<dim3(HDz / 32, APz / 32), tb>>>(dhp_W, HDz, APz, p_dhpWt, HDz, 0);
    transpose_into<<<dim3(1536 / 32, 4 * HDz / 32), tb>>>(W_ih1, 1536, 4 * HDz, p_W1t, K1z, 0);
    transpose_into<<<dim3(HDz / 32, 4 * HDz / 32), tb>>>(W_hh1, HDz, 4 * HDz, p_W1t, K1z, 1536);
    transpose_into<<<dim3(HDz / 32, 4 * HDz / 32), tb>>>(W_ih2, HDz, 4 * HDz, p_W2c, K2z, 0);
    transpose_into<<<dim3(HDz / 32, 4 * HDz / 32), tb>>>(W_hh2, HDz, 4 * HDz, p_W2c, K2z, 1024);
    transpose_into<<<dim3(HDz / 32, HDz / 32), tb>>>(lt_W, HDz, HDz,
                                                     p_W2c + (size_t)4 * HDz * K2z, K2z, 0);
    zero_region_h<<<HDz, 256>>>(p_W2c, K2z, 4 * HDz, 1024);
    cvt_eh<<<(Bz * Lz * HEz / 4 + 255) / 256, 256>>>(enc_hiddens);
    gbias_kernel<<<(4 * HDz + 255) / 256, 256>>>(b_ih1, b_hh1, b_ih2, b_hh2, lt_b);

    // enc_proj(fp16) = enc_hiddens @ att_W + att_b   (normal launch)
    gemm_mma<<<dim3(APz / BN, Bz * Lz / BMt, 1), 256, GSM>>>(
        p_ehtf, HEz, p_attWt, HEz, (float*)p_enc_proj, APz, HEz, att_b, 1);

    for (int t = 0; t < Tz; t++) {
        // q += hprev @ dhp_W (+dhp_b)   K=1024, z=16
        launch_pdl(dim3(APz / BN, Bz / BMt, 16), dim3(256), (size_t)GSM, gemm_mma,
                   (const __half*)p_hprev, HDz, (const __half*)p_dhpWt, HDz,
                   (float*)p_q, APz, 64, (const float*)dhp_b, 0);

        launch_pdl(dim3(Bz), dim3(512), (size_t)0, attn_fused,
                   enc_masks, corr_w, corr_b, captions, t);

        // gates1 += [x|a|h1] @ W1t^T (+gb1)   K=2560, z=5
        launch_pdl(dim3(4 * HDz / BN, Bz / BMt, 5), dim3(256), (size_t)GSM, gemm_mma,
                   (const __half*)p_a1, K1z, (const __half*)p_W1t, K1z,
                   (float*)p_g1, 4 * HDz, 512, (const float*)p_gb1, 0);

        launch_pdl(dim3(Bz * HDz / 256), dim3(256), (size_t)0, lstm_point1);

        // [gates2 | outsc] += [h1|h2] @ W2c^T (+gb2c)   K=2048, z=4
        launch_pdl(dim3(N2z / BN, Bz / BMt, 4), dim3(256), (size_t)GSM, gemm_mma,
                   (const __half*)p_a2, K2z, (const __half*)p_W2c, K2z,
                   (float*)p_g2c, N2z, 512, (const float*)p_gb2c, 0);

        launch_pdl(dim3(Bz * HDz / 256), dim3(256), (size_t)0, lstm_point2,
                   (float*)(out + (size_t)t * Bz * HDz));
    }
    (void)in_sizes; (void)n_in; (void)out_size;
}

// round 11
// speedup vs baseline: 9.1462x; 1.0409x over previous
#include <cuda_runtime.h>
#include <cuda_fp16.h>
#include <math.h>
#include <cstdint>

#define Bz 128
#define Lz 128
#define HEz 1024
#define HDz 1024
#define Ez 512
#define APz 512
#define Tz 64
#define K1z 2560        // [x_t | a_t | h1_prev]
#define K2z 2048        // [h1 | h2]
#define N2z 5120        // gates2 (4096) + out-proj (1024)

// ---------------- device scratch ----------------
__device__ __align__(128) __half g_enc_proj[Bz * Lz * APz];
__device__ __align__(128) __half g_ehtf[Bz * Lz * HEz];
__device__ __align__(128) float  g_q[Bz * APz];
__device__ __align__(128) __half g_abuf1[Bz * K1z];
__device__ __align__(128) __half g_abuf2[Bz * K2z];
__device__ __align__(128) float  g_gates1[Bz * 4 * HDz];
__device__ __align__(128) float  g_g2c[Bz * N2z];
__device__ __align__(128) float  g_c1[Bz * HDz];
__device__ __align__(128) float  g_c2[Bz * HDz];
__device__ __align__(128) __half g_hprev[Bz * HDz];
__device__ __align__(128) __half g_W1t[4 * HDz * K1z];
__device__ __align__(128) __half g_W2c[N2z * K2z];
__device__ __align__(128) __half g_dhpWt[APz * HDz];
__device__ __align__(128) __half g_attWt[APz * HEz];
__device__ __align__(128) float  g_gb1[4 * HDz];
__device__ __align__(128) float  g_gb2c[N2z];

__device__ __forceinline__ float fast_tanh(float x) {
    float y; asm("tanh.approx.f32 %0, %1;" : "=f"(y) : "f"(x)); return y;
}
__device__ __forceinline__ float sigmoidf_(float x) { return 1.0f / (1.0f + expf(-x)); }
__device__ __forceinline__ uint32_t smem_u32(const void* p) {
    uint32_t a;
    asm("{ .reg .u64 t; cvta.to.shared.u64 t, %1; cvt.u32.u64 %0, t; }" : "=r"(a) : "l"(p));
    return a;
}
#define CP16(dst, src) \
    asm volatile("cp.async.cg.shared.global [%0], [%1], 16;" :: "r"(dst), "l"(src))
#define LDSM4(d0, d1, d2, d3, addr) \
    asm volatile("ldmatrix.sync.aligned.m8n8.x4.shared.b16 {%0,%1,%2,%3}, [%4];" \
                 : "=r"(d0), "=r"(d1), "=r"(d2), "=r"(d3) : "r"(addr))
// PDL
#define GRID_WAIT()       asm volatile("griddepcontrol.wait;" ::: "memory")
#define GRID_LAUNCH_DEP() asm volatile("griddepcontrol.launch_dependents;" ::: "memory")

// ---------------- 3-stage pipelined HMMA fp16 GEMM (m16n8k16 + ldmatrix + PDL) --
#define BMt 64
#define BN 128
#define BKh 64
#define SWH 72
#define STGH ((BMt + BN) * SWH)

__global__ __launch_bounds__(256, 2) void gemm_mma(
    const __half* __restrict__ A, int lda,
    const __half* __restrict__ Bt, int ldb,
    float* __restrict__ C, int ldc,
    int chunk, const float* __restrict__ bias, int flags)
{
    extern __shared__ __half smh[];
    const int tid = threadIdx.x;
    const int wid = tid >> 5, lane = tid & 31;
    const int wm = wid & 1, wn = wid >> 1;
    const int lrow = lane >> 2, lcol = lane & 3;
    const int n0 = blockIdx.x * BN;
    const int m0 = blockIdx.y * BMt;
    const int kbeg = blockIdx.z * chunk;
    const int NC = chunk / BKh;

    float c[2][4][4];
    #pragma unroll
    for (int i = 0; i < 2; i++)
        #pragma unroll
        for (int j = 0; j < 4; j++)
            #pragma unroll
            for (int r = 0; r < 4; r++) c[i][j][r] = 0.0f;

    const uint32_t sbase = smem_u32(smh);
    const __half* Abase = A + (size_t)m0 * lda + kbeg;
    const __half* Bbase = Bt + (size_t)n0 * ldb + kbeg;

    const int ar0 = (tid + 0)   >> 3, ao0 = (tid + 0)   & 7;
    const int ar1 = (tid + 256) >> 3, ao1 = (tid + 256) & 7;

    const uint32_t a_off =
        ((uint32_t)((wm * 32 + (lane & 15)) * SWH + ((lane >> 4) << 3))) * 2;
    const uint32_t b_off =
        ((uint32_t)((BMt + wn * 32 + (lane & 7) + (((lane >> 4) & 1) << 3)) * SWH
                    + (((lane >> 3) & 1) << 3))) * 2;

#define LOAD_A_STAGE(ck, st) do {                                                 \
        uint32_t sb = sbase + (uint32_t)(st) * STGH * 2;                          \
        const __half* Ag = Abase + (size_t)(ck) * BKh;                            \
        CP16(sb + ar0 * 144 + ao0 * 16, Ag + (size_t)ar0 * lda + ao0 * 8);        \
        CP16(sb + ar1 * 144 + ao1 * 16, Ag + (size_t)ar1 * lda + ao1 * 8);        \
    } while (0)
#define LOAD_B_STAGE(ck, st) do {                                                 \
        uint32_t sb = sbase + (uint32_t)(st) * STGH * 2;                          \
        const __half* Bg = Bbase + (size_t)(ck) * BKh;                            \
        _Pragma("unroll")                                                         \
        for (int j = 0; j < 4; j++) {                                             \
            int i = tid + j * 256;                                                \
            int row = i >> 3, off = i & 7;                                        \
            CP16(sb + (BMt + row) * 144 + off * 16,                               \
                 Bg + (size_t)row * ldb + off * 8);                               \
        }                                                                         \
    } while (0)

    // weight prefetch (independent of predecessor) BEFORE the PDL wait
    LOAD_B_STAGE(0, 0);
    if (NC > 1) LOAD_B_STAGE(1, 1);
    GRID_WAIT();
    LOAD_A_STAGE(0, 0);
    asm volatile("cp.async.commit_group;" ::: "memory");
    if (NC > 1) {
        LOAD_A_STAGE(1, 1);
        asm volatile("cp.async.commit_group;" ::: "memory");
    }

    int s = 0;
    for (int cc = 0; cc < NC; cc++) {
        if (cc + 1 < NC) { asm volatile("cp.async.wait_group 1;" ::: "memory"); }
        else             { asm volatile("cp.async.wait_group 0;" ::: "memory"); }
        __syncthreads();
        if (cc + 2 < NC) {
            int st = s + 2 >= 3 ? s - 1 : s + 2;
            LOAD_B_STAGE(cc + 2, st);
            LOAD_A_STAGE(cc + 2, st);
            asm volatile("cp.async.commit_group;" ::: "memory");
        }

        const uint32_t stg = sbase + (uint32_t)s * STGH * 2;
        const uint32_t aad = stg + a_off;
        const uint32_t bad = stg + b_off;

        #pragma unroll
        for (int ks = 0; ks < 4; ks++) {
            uint32_t a[2][4], b[4][2];
            const uint32_t kso = ks * 32;
            LDSM4(a[0][0], a[0][1], a[0][2], a[0][3], aad + kso);
            LDSM4(a[1][0], a[1][1], a[1][2], a[1][3], aad + 16 * SWH * 2 + kso);
            LDSM4(b[0][0], b[0][1], b[1][0], b[1][1], bad + kso);
            LDSM4(b[2][0], b[2][1], b[3][0], b[3][1], bad + 16 * SWH * 2 + kso);
            #pragma unroll
            for (int mi = 0; mi < 2; mi++)
                #pragma unroll
                for (int nj = 0; nj < 4; nj++)
                    asm volatile(
                        "mma.sync.aligned.m16n8k16.row.col.f32.f16.f16.f32 "
                        "{%0,%1,%2,%3}, {%4,%5,%6,%7}, {%8,%9}, {%0,%1,%2,%3};"
                        : "+f"(c[mi][nj][0]), "+f"(c[mi][nj][1]),
                          "+f"(c[mi][nj][2]), "+f"(c[mi][nj][3])
                        : "r"(a[mi][0]), "r"(a[mi][1]), "r"(a[mi][2]), "r"(a[mi][3]),
                          "r"(b[nj][0]), "r"(b[nj][1]));
        }
        s = (s + 1 == 3) ? 0 : s + 1;
    }
#undef LOAD_A_STAGE
#undef LOAD_B_STAGE

    GRID_LAUNCH_DEP();

    const bool single = (gridDim.z == 1);
    const bool addb = (blockIdx.z == 0);
    const bool h16 = (flags & 1);
    #pragma unroll
    for (int mi = 0; mi < 2; mi++) {
        const int row = m0 + wm * 32 + mi * 16 + lrow;
        #pragma unroll
        for (int nj = 0; nj < 4; nj++) {
            const int col = n0 + wn * 32 + nj * 8 + 2 * lcol;
            float b0 = addb ? bias[col] : 0.0f;
            float b1 = addb ? bias[col + 1] : 0.0f;
            if (single) {
                if (h16) {
                    __half* Ch = (__half*)C;
                    *(__half2*)(Ch + (size_t)row * ldc + col) =
                        __floats2half2_rn(c[mi][nj][0] + b0, c[mi][nj][1] + b1);
                    *(__half2*)(Ch + (size_t)(row + 8) * ldc + col) =
                        __floats2half2_rn(c[mi][nj][2] + b0, c[mi][nj][3] + b1);
                } else {
                    *(float2*)&C[(size_t)row * ldc + col] =
                        make_float2(c[mi][nj][0] + b0, c[mi][nj][1] + b1);
                    *(float2*)&C[(size_t)(row + 8) * ldc + col] =
                        make_float2(c[mi][nj][2] + b0, c[mi][nj][3] + b1);
                }
            } else {
                atomicAdd(&C[(size_t)row * ldc + col],           c[mi][nj][0] + b0);
                atomicAdd(&C[(size_t)row * ldc + col + 1],       c[mi][nj][1] + b1);
                atomicAdd(&C[(size_t)(row + 8) * ldc + col],     c[mi][nj][2] + b0);
                atomicAdd(&C[(size_t)(row + 8) * ldc + col + 1], c[mi][nj][3] + b1);
            }
        }
    }
}

// ---------------- merged one-time prep ----------------
// blockIdx.x ranges:
//   [0,512)       att_W  -> g_attWt   (K=1024,N=512, ldd=1024, koff=0)
//   [512,1024)    dhp_W  -> g_dhpWt
//   [1024,7168)   W_ih1  -> g_W1t     (K=1536,N=4096, ldd=K1z, koff=0)
//   [7168,11264)  W_hh1  -> g_W1t     (koff=1536)
//   [11264,15360) W_ih2  -> g_W2c     (ldd=K2z, koff=0)
//   [15360,19456) W_hh2  -> g_W2c     (koff=1024)
//   [19456,20480) lt_W   -> g_W2c + 4*HDz*K2z
//   [20480,21504) zero pad W2c rows 4096.., cols 1024..
//   [21504,21520) gate biases
//   [21520,22032) state init
//   [22032,38416) enc_hiddens fp32->fp16
#define PJ0 512
#define PJ1 1024
#define PJ2 7168
#define PJ3 11264
#define PJ4 15360
#define PJ5 19456
#define PJ6 20480
#define PJ7 21504
#define PJ8 21520
#define PJ9 22032
#define PJTOT 38416

__global__ __launch_bounds__(256) void prep_all(
    const float* __restrict__ att_W, const float* __restrict__ dhp_W,
    const float* __restrict__ W_ih1, const float* __restrict__ W_hh1,
    const float* __restrict__ W_ih2, const float* __restrict__ W_hh2,
    const float* __restrict__ lt_W,
    const float* __restrict__ b_ih1, const float* __restrict__ b_hh1,
    const float* __restrict__ b_ih2, const float* __restrict__ b_hh2,
    const float* __restrict__ lt_b,
    const float* __restrict__ h1_0, const float* __restrict__ c1_0,
    const float* __restrict__ h2_0, const float* __restrict__ c2_0,
    const float* __restrict__ enc_hiddens)
{
    __shared__ float tile[32][33];
    const int bid = blockIdx.x;
    const int tid = threadIdx.x;
    const int tx = tid & 31, ty = tid >> 5;

#define DO_TR(src, K, N, dst, ldd, koff, tIdx) do {                                \
        int nkb = (K) >> 5;                                                        \
        int kb = ((tIdx) % nkb) * 32, nb = ((tIdx) / nkb) * 32;                    \
        _Pragma("unroll")                                                          \
        for (int i = ty; i < 32; i += 8)                                           \
            tile[i][tx] = (src)[(size_t)(kb + i) * (N) + nb + tx];                 \
        __syncthreads();                                                           \
        _Pragma("unroll")                                                          \
        for (int i = ty; i < 32; i += 8)                                           \
            (dst)[(size_t)(nb + i) * (ldd) + (koff) + kb + tx] =                   \
                __float2half_rn(tile[tx][i]);                                      \
    } while (0)

    if (bid < PJ0) {
        DO_TR(att_W, HEz, APz, g_attWt, HEz, 0, bid);
    } else if (bid < PJ1) {
        DO_TR(dhp_W, HDz, APz, g_dhpWt, HDz, 0, bid - PJ0);
    } else if (bid < PJ2) {
        DO_TR(W_ih1, 1536, 4 * HDz, g_W1t, K1z, 0, bid - PJ1);
    } else if (bid < PJ3) {
        DO_TR(W_hh1, HDz, 4 * HDz, g_W1t, K1z, 1536, bid - PJ2);
    } else if (bid < PJ4) {
        DO_TR(W_ih2, HDz, 4 * HDz, g_W2c, K2z, 0, bid - PJ3);
    } else if (bid < PJ5) {
        DO_TR(W_hh2, HDz, 4 * HDz, g_W2c, K2z, 1024, bid - PJ4);
    } else if (bid < PJ6) {
        DO_TR(lt_W, HDz, HDz, g_W2c + (size_t)4 * HDz * K2z, K2z, 0, bid - PJ5);
    } else if (bid < PJ7) {
        // zero W2c rows [4096, 5120) cols [1024, 2048)
        int row = 4 * HDz + (bid - PJ6);
        __half z = __float2half(0.0f);
        #pragma unroll
        for (int j = 0; j < 4; j++)
            g_W2c[(size_t)row * K2z + 1024 + tid * 4 + j] = z;
    } else if (bid < PJ8) {
        int i = (bid - PJ7) * 256 + tid;
        g_gb1[i]  = b_ih1[i] + b_hh1[i];
        g_gb2c[i] = b_ih2[i] + b_hh2[i];
        if (i < HDz) g_gb2c[4 * HDz + i] = lt_b[i];
    } else if (bid < PJ9) {
        int idx = (bid - PJ8) * 256 + tid;
        int b = idx >> 10, j = idx & (HDz - 1);
        g_c1[idx] = c1_0[idx];
        g_c2[idx] = c2_0[idx];
        g_abuf1[(size_t)b * K1z + 1536 + j] = __float2half_rn(h1_0[idx]);
        g_abuf2[(size_t)b * K2z + 1024 + j] = __float2half_rn(h2_0[idx]);
        g_hprev[idx] = __float2half_rn(1.0f / (float)HEz);
        #pragma unroll
        for (int gi = 0; gi < 4; gi++)
            g_gates1[(size_t)b * 4 * HDz + gi * HDz + j] = 0.0f;
        if (idx < Bz * APz) g_q[idx] = 0.0f;
    } else {
        size_t i = (size_t)(bid - PJ9) * 256 + tid;
        float4 v = *(const float4*)(enc_hiddens + i * 4);
        __half2* d = (__half2*)g_ehtf;
        d[2 * i]     = __floats2half2_rn(v.x, v.y);
        d[2 * i + 1] = __floats2half2_rn(v.z, v.w);
    }
#undef DO_TR
}

// ---------------- fused attention (PDL) ----------------
__global__ __launch_bounds__(512) void attn_fused(
    const int* __restrict__ enc_masks,
    const float* __restrict__ corr_w, const float* __restrict__ corr_b,
    const float* __restrict__ captions, int t)
{
    __shared__ __align__(16) float qv[APz];
    __shared__ __align__(16) float cw[APz];
    __shared__ float al[Lz];
    const int b = blockIdx.x;
    const int tid = threadIdx.x, lane = tid & 31, warp = tid >> 5;

    if (tid < APz) {
        cw[tid] = corr_w[tid];
        g_abuf1[(size_t)b * K1z + tid] = __float2half_rn(captions[((size_t)t * Bz + b) * Ez + tid]);
    }
    GRID_WAIT();
    if (tid < APz) qv[tid] = g_q[b * APz + tid];
    __syncthreads();

    const float cb = corr_b[0];
    #pragma unroll
    for (int li = 0; li < 8; li++) {
        const int l = warp + li * 16;
        const uint4* ep = (const uint4*)(g_enc_proj + ((size_t)(b * Lz + l)) * APz);
        float acc = 0.0f;
        #pragma unroll
        for (int u = 0; u < 2; u++) {
            uint4 pk = ep[lane * 2 + u];
            const __half2* h2 = (const __half2*)&pk;
            const int ap0 = lane * 16 + u * 8;
            #pragma unroll
            for (int p = 0; p < 4; p++) {
                float2 v = __half22float2(h2[p]);
                acc += fast_tanh(v.x + qv[ap0 + 2 * p]) * cw[ap0 + 2 * p];
                acc += fast_tanh(v.y + qv[ap0 + 2 * p + 1]) * cw[ap0 + 2 * p + 1];
            }
        }
        #pragma unroll
        for (int off = 16; off; off >>= 1) acc += __shfl_xor_sync(0xffffffffu, acc, off);
        if (lane == 0) {
            float v = acc + cb;
            if (enc_masks[b * Lz + l]) v = -INFINITY;
            al[l] = v;
        }
    }
    __syncthreads();

    if (tid < 32) {
        float m = -INFINITY;
        #pragma unroll
        for (int i = 0; i < 4; i++) m = fmaxf(m, al[tid + 32 * i]);
        #pragma unroll
        for (int off = 16; off; off >>= 1) m = fmaxf(m, __shfl_xor_sync(0xffffffffu, m, off));
        float ex[4], s = 0.0f;
        #pragma unroll
        for (int i = 0; i < 4; i++) { ex[i] = __expf(al[tid + 32 * i] - m); s += ex[i]; }
        #pragma unroll
        for (int off = 16; off; off >>= 1) s += __shfl_xor_sync(0xffffffffu, s, off);
        float inv = 1.0f / s;
        #pragma unroll
        for (int i = 0; i < 4; i++) al[tid + 32 * i] = ex[i] * inv;
    }
    __syncthreads();
    GRID_LAUNCH_DEP();

    const __half2* eh2 = (const __half2*)(g_ehtf + (size_t)b * Lz * HEz);
    float2 acc2 = make_float2(0.0f, 0.0f);
    #pragma unroll 8
    for (int l = 0; l < Lz; l++) {
        float2 v = __half22float2(eh2[(size_t)l * (HEz / 2) + tid]);
        float a = al[l];
        acc2.x += a * v.x;
        acc2.y += a * v.y;
    }
    *(__half2*)(g_abuf1 + (size_t)b * K1z + Ez + 2 * tid) = __floats2half2_rn(acc2.x, acc2.y);
}

// ---------------- LSTM pointwise (PDL) ----------------
__global__ __launch_bounds__(256) void lstm_point1()
{
    GRID_WAIT();
    int idx = blockIdx.x * blockDim.x + threadIdx.x;
    int b = idx >> 10, j = idx & (HDz - 1);
    const float* g = g_gates1 + (size_t)b * 4 * HDz;
    float ig = sigmoidf_(g[j]);
    float fg = sigmoidf_(g[HDz + j]);
    float gg = tanhf(g[2 * HDz + j]);
    float og = sigmoidf_(g[3 * HDz + j]);
    float cn = fg * g_c1[idx] + ig * gg;
    float hn = og * tanhf(cn);
    GRID_LAUNCH_DEP();
    g_c1[idx] = cn;
    __half hn_h = __float2half_rn(hn);
    g_abuf2[(size_t)b * K2z + j] = hn_h;
    g_abuf1[(size_t)b * K1z + 1536 + j] = hn_h;
    #pragma unroll
    for (int gi = 0; gi < 5; gi++)
        g_g2c[(size_t)b * N2z + gi * HDz + j] = 0.0f;
}

__global__ __launch_bounds__(256) void lstm_point2(float* __restrict__ out)
{
    GRID_WAIT();
    int idx = blockIdx.x * blockDim.x + threadIdx.x;
    int b = idx >> 10, j = idx & (HDz - 1);
    const float* g = g_g2c + (size_t)b * N2z;
    float ig = sigmoidf_(g[j]);
    float fg = sigmoidf_(g[HDz + j]);
    float gg = tanhf(g[2 * HDz + j]);
    float og = sigmoidf_(g[3 * HDz + j]);
    float cn = fg * g_c2[idx] + ig * gg;
    float hn = og * tanhf(cn);
    GRID_LAUNCH_DEP();
    g_c2[idx] = cn;
    __half hn_h = __float2half_rn(hn);
    g_abuf2[(size_t)b * K2z + 1024 + j] = hn_h;
    g_hprev[idx] = hn_h;
    out[idx] = tanhf(g[4 * HDz + j]);
    #pragma unroll
    for (int gi = 0; gi < 4; gi++)
        g_gates1[(size_t)b * 4 * HDz + gi * HDz + j] = 0.0f;
    if (idx < Bz * APz) g_q[idx] = 0.0f;
}

// ---------------- PDL launch helper ----------------
template <class T> struct idt { using type = T; };
template <typename... Args>
static inline void launch_pdl(dim3 grid, dim3 block, size_t shm,
                              void (*kern)(Args...),
                              typename idt<Args>::type... args)
{
    cudaLaunchConfig_t cfg = {};
    cfg.gridDim = grid; cfg.blockDim = block;
    cfg.dynamicSmemBytes = shm; cfg.stream = 0;
    cudaLaunchAttribute at[1];
    at[0].id = cudaLaunchAttributeProgrammaticStreamSerialization;
    at[0].val.programmaticStreamSerializationAllowed = 1;
    cfg.attrs = at; cfg.numAttrs = 1;
    cudaLaunchKernelEx(&cfg, kern, args...);
}

// ---------------- host launcher ----------------
extern "C" void kernel_launch(void* const* d_in, const int* in_sizes, int n_in,
                              void* d_out, int out_size)
{
    const float* enc_hiddens = (const float*)d_in[0];
    const int*   enc_masks   = (const int*)  d_in[1];
    const float* h1_0 = (const float*)d_in[2];
    const float* c1_0 = (const float*)d_in[3];
    const float* h2_0 = (const float*)d_in[4];
    const float* c2_0 = (const float*)d_in[5];
    const float* captions = (const float*)d_in[6];
    const float* att_W = (const float*)d_in[7];
    const float* att_b = (const float*)d_in[8];
    const float* dhp_W = (const float*)d_in[9];
    const float* dhp_b = (const float*)d_in[10];
    const float* corr_w = (const float*)d_in[11];
    const float* corr_b = (const float*)d_in[12];
    const float* lt_W = (const float*)d_in[13];
    const float* lt_b = (const float*)d_in[14];
    const float* W_ih1 = (const float*)d_in[15];
    const float* W_hh1 = (const float*)d_in[16];
    const float* b_ih1 = (const float*)d_in[17];
    const float* b_hh1 = (const float*)d_in[18];
    const float* W_ih2 = (const float*)d_in[19];
    const float* W_hh2 = (const float*)d_in[20];
    const float* b_ih2 = (const float*)d_in[21];
    const float* b_hh2 = (const float*)d_in[22];
    float* out = (float*)d_out;

    static bool inited = false;
    static __half *p_enc_proj, *p_ehtf, *p_a1, *p_a2, *p_hprev;
    static __half *p_W1t, *p_W2c, *p_dhpWt, *p_attWt;
    static float *p_g1, *p_g2c, *p_q, *p_gb1, *p_gb2c;
    if (!inited) {
        cudaGetSymbolAddress((void**)&p_enc_proj, g_enc_proj);
        cudaGetSymbolAddress((void**)&p_ehtf,  g_ehtf);
        cudaGetSymbolAddress((void**)&p_a1,    g_abuf1);
        cudaGetSymbolAddress((void**)&p_a2,    g_abuf2);
        cudaGetSymbolAddress((void**)&p_g1,    g_gates1);
        cudaGetSymbolAddress((void**)&p_g2c,   g_g2c);
        cudaGetSymbolAddress((void**)&p_q,     g_q);
        cudaGetSymbolAddress((void**)&p_hprev, g_hprev);
        cudaGetSymbolAddress((void**)&p_W1t,   g_W1t);
        cudaGetSymbolAddress((void**)&p_W2c,   g_W2c);
        cudaGetSymbolAddress((void**)&p_dhpWt, g_dhpWt);
        cudaGetSymbolAddress((void**)&p_attWt, g_attWt);
        cudaGetSymbolAddress((void**)&p_gb1,   g_gb1);
        cudaGetSymbolAddress((void**)&p_gb2c,  g_gb2c);
        cudaFuncSetAttribute(gemm_mma, cudaFuncAttributeMaxDynamicSharedMemorySize,
                             3 * STGH * 2);
        inited = true;
    }
    const int GSM = 3 * STGH * 2;   // 82944 B

    // one merged prep kernel (transposes, biases, state init, enc fp16 cvt)
    prep_all<<<PJTOT, 256>>>(att_W, dhp_W, W_ih1, W_hh1, W_ih2, W_hh2, lt_W,
                             b_ih1, b_hh1, b_ih2, b_hh2, lt_b,
                             h1_0, c1_0, h2_0, c2_0, enc_hiddens);

    // enc_proj(fp16) = enc_hiddens @ att_W + att_b   (normal launch)
    gemm_mma<<<dim3(APz / BN, Bz * Lz / BMt, 1), 256, GSM>>>(
        p_ehtf, HEz, p_attWt, HEz, (float*)p_enc_proj, APz, HEz, att_b, 1);

    for (int t = 0; t < Tz; t++) {
        // q += hprev @ dhp_W (+dhp_b)   K=1024, z=16
        launch_pdl(dim3(APz / BN, Bz / BMt, 16), dim3(256), (size_t)GSM, gemm_mma,
                   (const __half*)p_hprev, HDz, (const __half*)p_dhpWt, HDz,
                   (float*)p_q, APz, 64, (const float*)dhp_b, 0);

        launch_pdl(dim3(Bz), dim3(512), (size_t)0, attn_fused,
                   enc_masks, corr_w, corr_b, captions, t);

        // gates1 += [x|a|h1] @ W1t^T (+gb1)   K=2560, z=4 -> 256 blocks (1 wave)
        launch_pdl(dim3(4 * HDz / BN, Bz / BMt, 4), dim3(256), (size_t)GSM, gemm_mma,
                   (const __half*)p_a1, K1z, (const __half*)p_W1t, K1z,
                   (float*)p_g1, 4 * HDz, 640, (const float*)p_gb1, 0);

        launch_pdl(dim3(Bz * HDz / 256), dim3(256), (size_t)0, lstm_point1);

        // [gates2 | outsc] += [h1|h2] @ W2c^T (+gb2c)   K=2048, z=4
        launch_pdl(dim3(N2z / BN, Bz / BMt, 4), dim3(256), (size_t)GSM, gemm_mma,
                   (const __half*)p_a2, K2z, (const __half*)p_W2c, K2z,
                   (float*)p_g2c, N2z, 512, (const float*)p_gb2c, 0);

        launch_pdl(dim3(Bz * HDz / 256), dim3(256), (size_t)0, lstm_point2,
                   (float*)(out + (size_t)t * Bz * HDz));
    }
    (void)in_sizes; (void)n_in; (void)out_size;
}